// round 2
// baseline (speedup 1.0000x reference)
#include <cuda_runtime.h>
#include <cuda_bf16.h>
#include <math.h>

// ---------------- problem constants ----------------
#define BATCH 4
#define SEQ   1024
#define NTOK  (BATCH*SEQ)      // 4096
#define DMODEL 768
#define NHEAD 12
#define DHEAD 64
#define NOPE  32
#define ROPE  32
#define QP    384
#define KVP   512
#define CKVW  (KVP+ROPE)       // 544
#define UKVW  1152             // D + H*NOPE
#define NEXP  8
#define TOPK  2
#define NSH   2
#define FFDIM 3072

// ---------------- scratch (device globals; no allocations allowed) ----------------
__device__ float g_h1 [NTOK*DMODEL];
__device__ float g_cqp[NTOK*QP];
__device__ float g_cq [NTOK*QP];
__device__ float g_q  [NTOK*DMODEL];
__device__ float g_ckv[NTOK*CKVW];
__device__ float g_kvl[NTOK*KVP];
__device__ float g_kv [NTOK*UKVW];
__device__ float g_kr [NTOK*ROPE];
__device__ float g_o  [NTOK*DMODEL];
__device__ float g_x2 [NTOK*DMODEL];
__device__ float g_h2 [NTOK*DMODEL];
__device__ float g_ff [NTOK*FFDIM];
__device__ float g_ffe[(size_t)NEXP*NTOK*FFDIM];
__device__ float g_routed[2*NTOK*DMODEL];
__device__ int   g_ecnt[NEXP];
__device__ int   g_etok[NEXP*NTOK];
__device__ int   g_escat[NEXP*NTOK];
__device__ float g_ewt [NEXP*NTOK];

// ---------------- generic tiled SGEMM body ----------------
// C[M,N] = op(A[M,K] x B), with optional gather of A rows, scatter of C rows,
// GELU, per-row scale, residual add, accumulate.
#define BM 64
#define BN 64
#define BKK 16

template<bool TRANSB>
__device__ __forceinline__ void gemm_tile_body(
    const float* __restrict__ A, const float* __restrict__ B, float* __restrict__ C,
    int M, int N, int K, int lda, int ldb, int ldc,
    const int* __restrict__ gather, const int* __restrict__ scatter,
    const float* __restrict__ residual, int ldr,
    const float* __restrict__ rowScale,
    int doGelu, int accum, int rt, int ct)
{
    __shared__ float As[BKK][BM+4];
    __shared__ float Bs[BKK][BN+4];
    const int tid = threadIdx.x;
    const int tx = tid & 15, ty = tid >> 4;
    const int row0 = rt * BM, col0 = ct * BN;
    float acc[4][4] = {};

    // A-load indices: each thread loads 4 consecutive k of one row
    const int lr = tid >> 2;        // 0..63  (tile row)
    const int lk = (tid & 3) * 4;   // 0,4,8,12
    const float* Arow = nullptr;
    {
        int grow = row0 + lr;
        if (grow < M) {
            int ar = gather ? gather[grow] : grow;
            Arow = A + (size_t)ar * lda;
        }
    }

    for (int k0 = 0; k0 < K; k0 += BKK) {
        #pragma unroll
        for (int v = 0; v < 4; v++) {
            int kk = lk + v;
            float val = 0.f;
            if (Arow && (k0 + kk) < K) val = Arow[k0 + kk];
            As[kk][lr] = val;
        }
        if (TRANSB) {
            int bn = tid >> 2; int bkq = (tid & 3) * 4;
            #pragma unroll
            for (int v = 0; v < 4; v++) {
                int kk = bkq + v; float val = 0.f;
                if ((col0 + bn) < N && (k0 + kk) < K)
                    val = B[(size_t)(col0 + bn) * ldb + k0 + kk];
                Bs[kk][bn] = val;
            }
        } else {
            int bk = tid >> 4; int bn0 = (tid & 15) * 4;
            #pragma unroll
            for (int v = 0; v < 4; v++) {
                int n = bn0 + v; float val = 0.f;
                if ((k0 + bk) < K && (col0 + n) < N)
                    val = B[(size_t)(k0 + bk) * ldb + col0 + n];
                Bs[bk][n] = val;
            }
        }
        __syncthreads();
        #pragma unroll
        for (int kk = 0; kk < BKK; kk++) {
            float a[4], bv[4];
            #pragma unroll
            for (int i = 0; i < 4; i++) a[i] = As[kk][ty*4 + i];
            #pragma unroll
            for (int j = 0; j < 4; j++) bv[j] = Bs[kk][tx*4 + j];
            #pragma unroll
            for (int i = 0; i < 4; i++)
                #pragma unroll
                for (int j = 0; j < 4; j++)
                    acc[i][j] = fmaf(a[i], bv[j], acc[i][j]);
        }
        __syncthreads();
    }

    #pragma unroll
    for (int i = 0; i < 4; i++) {
        int r = row0 + ty*4 + i;
        if (r >= M) continue;
        int orow = scatter ? scatter[r] : r;
        float sc = rowScale ? rowScale[r] : 1.f;
        #pragma unroll
        for (int j = 0; j < 4; j++) {
            int c = col0 + tx*4 + j;
            if (c >= N) continue;
            float v = acc[i][j];
            if (doGelu) v = 0.5f * v * (1.f + erff(v * 0.70710678118654752f));
            v *= sc;
            if (residual) v += residual[(size_t)r * ldr + c];
            size_t off = (size_t)orow * ldc + c;
            if (accum) C[off] += v; else C[off] = v;
        }
    }
}

template<bool TRANSB>
__global__ void gemm_kernel(
    const float* __restrict__ A, const float* __restrict__ B, float* __restrict__ C,
    int M, int N, int K, int lda, int ldb, int ldc,
    const float* __restrict__ residual, int ldr, int doGelu, int accum)
{
    gemm_tile_body<TRANSB>(A, B, C, M, N, K, lda, ldb, ldc,
                           nullptr, nullptr, residual, ldr, nullptr,
                           doGelu, accum, blockIdx.y, blockIdx.x);
}

// ---------------- expert (ragged) GEMMs ----------------
__global__ void expert_fc_kernel(const float* __restrict__ h2,
                                 const float* __restrict__ e_fc,
                                 float* __restrict__ ffe,
                                 const int* __restrict__ ecnt,
                                 const int* __restrict__ etok)
{
    int e = blockIdx.z;
    int cnt = ecnt[e];
    if ((int)blockIdx.y * BM >= cnt) return;
    gemm_tile_body<true>(h2, e_fc + (size_t)e * FFDIM * DMODEL,
                         ffe + (size_t)e * NTOK * FFDIM,
                         cnt, FFDIM, DMODEL, DMODEL, DMODEL, FFDIM,
                         etok + e * NTOK, nullptr, nullptr, 0, nullptr,
                         1 /*gelu*/, 0, blockIdx.y, blockIdx.x);
}

__global__ void expert_proj_kernel(const float* __restrict__ ffe,
                                   const float* __restrict__ e_proj,
                                   float* __restrict__ routed,
                                   const int* __restrict__ ecnt,
                                   const int* __restrict__ escat,
                                   const float* __restrict__ ewt)
{
    int e = blockIdx.z;
    int cnt = ecnt[e];
    if ((int)blockIdx.y * BM >= cnt) return;
    gemm_tile_body<true>(ffe + (size_t)e * NTOK * FFDIM,
                         e_proj + (size_t)e * DMODEL * FFDIM,
                         routed,
                         cnt, DMODEL, FFDIM, FFDIM, FFDIM, DMODEL,
                         nullptr, escat + e * NTOK, nullptr, 0, ewt + e * NTOK,
                         0, 0, blockIdx.y, blockIdx.x);
}

// ---------------- layernorm ----------------
__global__ void ln_kernel(const float* __restrict__ in, int ldin, int W,
                          const float* __restrict__ w, const float* __restrict__ b,
                          float* __restrict__ out, int ldout)
{
    int t = blockIdx.x;
    int tid = threadIdx.x;
    const float* x = in + (size_t)t * ldin;
    float s = 0.f, sq = 0.f;
    for (int c = tid; c < W; c += blockDim.x) { float v = x[c]; s += v; sq += v*v; }
    __shared__ float rs[32], rq[32];
    #pragma unroll
    for (int o = 16; o; o >>= 1) { s += __shfl_xor_sync(~0u, s, o); sq += __shfl_xor_sync(~0u, sq, o); }
    int warp = tid >> 5, lane = tid & 31;
    if (lane == 0) { rs[warp] = s; rq[warp] = sq; }
    __syncthreads();
    int nw = blockDim.x >> 5;
    if (warp == 0) {
        s  = lane < nw ? rs[lane] : 0.f;
        sq = lane < nw ? rq[lane] : 0.f;
        #pragma unroll
        for (int o = 16; o; o >>= 1) { s += __shfl_xor_sync(~0u, s, o); sq += __shfl_xor_sync(~0u, sq, o); }
        if (lane == 0) { rs[0] = s; rq[0] = sq; }
    }
    __syncthreads();
    float mean = rs[0] / W;
    float var  = rq[0] / W - mean * mean;
    float rstd = rsqrtf(var + 1e-5f);
    float* y = out + (size_t)t * ldout;
    for (int c = tid; c < W; c += blockDim.x) {
        float v = (x[c] - mean) * rstd * w[c];
        if (b) v += b[c];
        y[c] = v;
    }
}

// ---------------- rope (in-place on Q, builds shared roped K) ----------------
__global__ void rope_kernel(float* __restrict__ q, const float* __restrict__ ckv,
                            float* __restrict__ kr)
{
    int t = blockIdx.x;
    int s = t & (SEQ - 1);
    int tid = threadIdx.x;        // 192 threads: h=tid/16, j=tid%16
    int h = tid >> 4, j = tid & 15;
    float freq = powf(10000.f, -(float)j / 32.f);
    float ang = (float)s * freq;
    float c = cosf(ang), si = sinf(ang);
    float* qp = q + (size_t)t * DMODEL + h * DHEAD + NOPE;
    float a = qp[j], bb = qp[j + 16];
    qp[j]      = a * c - bb * si;
    qp[j + 16] = bb * c + a * si;
    if (h == 0) {
        const float* kp = ckv + (size_t)t * CKVW + KVP;
        float a2 = kp[j], b2 = kp[j + 16];
        kr[t * ROPE + j]      = a2 * c - b2 * si;
        kr[t * ROPE + j + 16] = b2 * c + a2 * si;
    }
}

// ---------------- flash attention (causal), 64q x 32k tiles ----------------
__global__ void flash_kernel(const float* __restrict__ Q, const float* __restrict__ KV,
                             const float* __restrict__ KR, float* __restrict__ O)
{
    __shared__ float qs[64][65];
    __shared__ float ks[32][65];
    __shared__ float vs[32][65];
    __shared__ float ps[64][33];
    int qt = blockIdx.x;           // 0..15
    int bh = blockIdx.y;           // 0..47
    int b = bh / NHEAD, h = bh % NHEAD;
    int tid = threadIdx.x;
    int row = tid >> 2, tx = tid & 3;
    int tok0 = b * SEQ + qt * 64;

    for (int i = tid; i < 64 * 64; i += 256) {
        int r = i >> 6, d = i & 63;
        qs[r][d] = Q[(size_t)(tok0 + r) * DMODEL + h * DHEAD + d];
    }

    float m = -1e30f, l = 0.f;
    float acc[16];
    #pragma unroll
    for (int i = 0; i < 16; i++) acc[i] = 0.f;

    int nkt = 2 * qt + 2;
    int qglob = qt * 64 + row;
    for (int kt = 0; kt < nkt; kt++) {
        __syncthreads();
        for (int i = tid; i < 32 * 64; i += 256) {
            int c = i >> 6, d = i & 63;
            int t = b * SEQ + kt * 32 + c;
            vs[c][d] = KV[(size_t)t * UKVW + h * 96 + 32 + d];
            ks[c][d] = (d < 32) ? KV[(size_t)t * UKVW + h * 96 + d]
                                : KR[t * ROPE + (d - 32)];
        }
        __syncthreads();
        float s[8];
        #pragma unroll
        for (int cc = 0; cc < 8; cc++) {
            int c = tx * 8 + cc;
            float dot = 0.f;
            #pragma unroll
            for (int d = 0; d < 64; d++) dot = fmaf(qs[row][d], ks[c][d], dot);
            dot *= 0.125f;
            if (kt * 32 + c > qglob) dot = -1e30f;
            s[cc] = dot;
        }
        float mt = s[0];
        #pragma unroll
        for (int cc = 1; cc < 8; cc++) mt = fmaxf(mt, s[cc]);
        mt = fmaxf(mt, __shfl_xor_sync(0xffffffffu, mt, 1));
        mt = fmaxf(mt, __shfl_xor_sync(0xffffffffu, mt, 2));
        float mnew = fmaxf(m, mt);
        float corr = __expf(m - mnew);
        l *= corr;
        #pragma unroll
        for (int i = 0; i < 16; i++) acc[i] *= corr;
        float psum = 0.f;
        #pragma unroll
        for (int cc = 0; cc < 8; cc++) {
            float p = __expf(s[cc] - mnew);
            ps[row][tx * 8 + cc] = p;
            psum += p;
        }
        psum += __shfl_xor_sync(0xffffffffu, psum, 1);
        psum += __shfl_xor_sync(0xffffffffu, psum, 2);
        l += psum;
        m = mnew;
        __syncwarp();
        #pragma unroll 8
        for (int c = 0; c < 32; c++) {
            float pv = ps[row][c];
            #pragma unroll
            for (int i = 0; i < 16; i++)
                acc[i] = fmaf(pv, vs[c][tx * 16 + i], acc[i]);
        }
    }
    float inv = 1.f / l;
    #pragma unroll
    for (int i = 0; i < 16; i++)
        O[(size_t)(tok0 + row) * DMODEL + h * DHEAD + tx * 16 + i] = acc[i] * inv;
}

// ---------------- routing (sigmoid gates, top-2 of 8) ----------------
__global__ void zero_cnt_kernel(int* __restrict__ ecnt)
{
    if (threadIdx.x < NEXP) ecnt[threadIdx.x] = 0;
}

__global__ void routing_kernel(const float* __restrict__ h2,
                               const float* __restrict__ centroids,
                               const float* __restrict__ rbias,
                               int* __restrict__ ecnt, int* __restrict__ etok,
                               int* __restrict__ escat, float* __restrict__ ewt)
{
    int t = blockIdx.x;
    int tid = threadIdx.x;
    int warp = tid >> 5, lane = tid & 31;
    __shared__ float raw[NEXP];
    const float* hp = h2 + (size_t)t * DMODEL;
    const float* cp = centroids + (size_t)warp * DMODEL;
    float sum = 0.f;
    for (int d = lane; d < DMODEL; d += 32) sum += hp[d] * cp[d];
    #pragma unroll
    for (int o = 16; o; o >>= 1) sum += __shfl_xor_sync(~0u, sum, o);
    if (lane == 0) raw[warp] = sum;
    __syncthreads();
    if (tid == 0) {
        float bb[NEXP];
        #pragma unroll
        for (int e = 0; e < NEXP; e++) bb[e] = raw[e] + rbias[e];
        int i0 = 0;
        #pragma unroll
        for (int e = 1; e < NEXP; e++) if (bb[e] > bb[i0]) i0 = e;
        int i1 = -1;
        #pragma unroll
        for (int e = 0; e < NEXP; e++) {
            if (e == i0) continue;
            if (i1 < 0 || bb[e] > bb[i1]) i1 = e;
        }
        float w0 = 1.f / (1.f + expf(-raw[i0]));
        float w1 = 1.f / (1.f + expf(-raw[i1]));
        float s = w0 + w1 + 1e-9f;
        w0 /= s; w1 /= s;
        int p0 = atomicAdd(&ecnt[i0], 1);
        etok [i0 * NTOK + p0] = t;
        escat[i0 * NTOK + p0] = t;               // slot 0 row
        ewt  [i0 * NTOK + p0] = w0;
        int p1 = atomicAdd(&ecnt[i1], 1);
        etok [i1 * NTOK + p1] = t;
        escat[i1 * NTOK + p1] = NTOK + t;        // slot 1 row
        ewt  [i1 * NTOK + p1] = w1;
    }
}

__global__ void add2_kernel(float* __restrict__ out, const float* __restrict__ a,
                            const float* __restrict__ b, int n)
{
    int i = blockIdx.x * blockDim.x + threadIdx.x;
    if (i < n) out[i] += a[i] + b[i];
}

// ---------------- launcher ----------------
extern "C" void kernel_launch(void* const* d_in, const int* in_sizes, int n_in,
                              void* d_out, int out_size)
{
    const float* x        = (const float*)d_in[0];
    const float* ln1_w    = (const float*)d_in[1];
    const float* ln2_w    = (const float*)d_in[2];
    const float* W_dq     = (const float*)d_in[3];
    const float* W_uq     = (const float*)d_in[4];
    const float* q_ln_w   = (const float*)d_in[5];
    const float* q_ln_b   = (const float*)d_in[6];
    const float* W_dkv    = (const float*)d_in[7];
    const float* W_ukv    = (const float*)d_in[8];
    const float* kv_ln_w  = (const float*)d_in[9];
    const float* kv_ln_b  = (const float*)d_in[10];
    const float* W_o      = (const float*)d_in[11];
    const float* s_fc     = (const float*)d_in[12];
    const float* s_proj   = (const float*)d_in[13];
    const float* e_fc     = (const float*)d_in[14];
    const float* e_proj   = (const float*)d_in[15];
    const float* centroids= (const float*)d_in[16];
    const float* rbias    = (const float*)d_in[17];
    float* out = (float*)d_out;

    float *h1, *cqp, *cq, *q, *ckv, *kvl, *kv, *kr, *o, *x2, *h2, *ff, *ffe, *routed, *ewt;
    int *ecnt, *etok, *escat;
    cudaGetSymbolAddress((void**)&h1,  g_h1);
    cudaGetSymbolAddress((void**)&cqp, g_cqp);
    cudaGetSymbolAddress((void**)&cq,  g_cq);
    cudaGetSymbolAddress((void**)&q,   g_q);
    cudaGetSymbolAddress((void**)&ckv, g_ckv);
    cudaGetSymbolAddress((void**)&kvl, g_kvl);
    cudaGetSymbolAddress((void**)&kv,  g_kv);
    cudaGetSymbolAddress((void**)&kr,  g_kr);
    cudaGetSymbolAddress((void**)&o,   g_o);
    cudaGetSymbolAddress((void**)&x2,  g_x2);
    cudaGetSymbolAddress((void**)&h2,  g_h2);
    cudaGetSymbolAddress((void**)&ff,  g_ff);
    cudaGetSymbolAddress((void**)&ffe, g_ffe);
    cudaGetSymbolAddress((void**)&routed, g_routed);
    cudaGetSymbolAddress((void**)&ecnt, g_ecnt);
    cudaGetSymbolAddress((void**)&etok, g_etok);
    cudaGetSymbolAddress((void**)&escat, g_escat);
    cudaGetSymbolAddress((void**)&ewt, g_ewt);

    const int TB = 256;

    // 1. h1 = LN(x)
    ln_kernel<<<NTOK, TB>>>(x, DMODEL, DMODEL, ln1_w, nullptr, h1, DMODEL);
    // 2. cq_pre = h1 @ W_dq  (768->384)
    gemm_kernel<false><<<dim3(QP/BN, NTOK/BM), TB>>>(h1, W_dq, cqp,
        NTOK, QP, DMODEL, DMODEL, QP, QP, nullptr, 0, 0, 0);
    // 3. cq = LN(cq_pre) with w,b
    ln_kernel<<<NTOK, TB>>>(cqp, QP, QP, q_ln_w, q_ln_b, cq, QP);
    // 4. Q = cq @ W_uq  (384->768)
    gemm_kernel<false><<<dim3(DMODEL/BN, NTOK/BM), TB>>>(cq, W_uq, q,
        NTOK, DMODEL, QP, QP, DMODEL, DMODEL, nullptr, 0, 0, 0);
    // 5. ckv = h1 @ W_dkv  (768->544)
    gemm_kernel<false><<<dim3((CKVW+BN-1)/BN, NTOK/BM), TB>>>(h1, W_dkv, ckv,
        NTOK, CKVW, DMODEL, DMODEL, CKVW, CKVW, nullptr, 0, 0, 0);
    // 6. kvl = LN(ckv[:, :512])
    ln_kernel<<<NTOK, TB>>>(ckv, CKVW, KVP, kv_ln_w, kv_ln_b, kvl, KVP);
    // 7. KV = kvl @ W_ukv  (512->1152)
    gemm_kernel<false><<<dim3(UKVW/BN, NTOK/BM), TB>>>(kvl, W_ukv, kv,
        NTOK, UKVW, KVP, KVP, UKVW, UKVW, nullptr, 0, 0, 0);
    // 8. rope Q in-place, build shared roped K
    rope_kernel<<<NTOK, 192>>>(q, ckv, kr);
    // 9. attention
    flash_kernel<<<dim3(SEQ/64, BATCH*NHEAD), TB>>>(q, kv, kr, o);
    // 10. x2 = o @ W_o^T + x
    gemm_kernel<true><<<dim3(DMODEL/BN, NTOK/BM), TB>>>(o, W_o, x2,
        NTOK, DMODEL, DMODEL, DMODEL, DMODEL, DMODEL, x, DMODEL, 0, 0);
    // 11. h2 = LN(x2)
    ln_kernel<<<NTOK, TB>>>(x2, DMODEL, DMODEL, ln2_w, nullptr, h2, DMODEL);
    // 12. shared expert 0: out = gelu(h2@fc0^T)@proj0^T + x2
    gemm_kernel<true><<<dim3(FFDIM/BN, NTOK/BM), TB>>>(h2, s_fc, ff,
        NTOK, FFDIM, DMODEL, DMODEL, DMODEL, FFDIM, nullptr, 0, 1, 0);
    gemm_kernel<true><<<dim3(DMODEL/BN, NTOK/BM), TB>>>(ff, s_proj, out,
        NTOK, DMODEL, FFDIM, FFDIM, FFDIM, DMODEL, x2, DMODEL, 0, 0);
    // 13. shared expert 1: out += gelu(h2@fc1^T)@proj1^T
    gemm_kernel<true><<<dim3(FFDIM/BN, NTOK/BM), TB>>>(h2, s_fc + (size_t)FFDIM*DMODEL, ff,
        NTOK, FFDIM, DMODEL, DMODEL, DMODEL, FFDIM, nullptr, 0, 1, 0);
    gemm_kernel<true><<<dim3(DMODEL/BN, NTOK/BM), TB>>>(ff, s_proj + (size_t)DMODEL*FFDIM, out,
        NTOK, DMODEL, FFDIM, FFDIM, FFDIM, DMODEL, nullptr, 0, 0, 1);
    // 14. routing
    zero_cnt_kernel<<<1, 32>>>(ecnt);
    routing_kernel<<<NTOK, TB>>>(h2, centroids, rbias, ecnt, etok, escat, ewt);
    // 15. routed experts (ragged GEMMs)
    expert_fc_kernel<<<dim3(FFDIM/BN, NTOK/BM, NEXP), TB>>>(h2, e_fc, ffe, ecnt, etok);
    expert_proj_kernel<<<dim3(DMODEL/BN, NTOK/BM, NEXP), TB>>>(ffe, e_proj, routed, ecnt, escat, ewt);
    // 16. out += routed_slot0 + routed_slot1
    add2_kernel<<<(NTOK*DMODEL + TB - 1)/TB, TB>>>(out, routed, routed + (size_t)NTOK*DMODEL, NTOK*DMODEL);
}

// round 5
// speedup vs baseline: 1.2041x; 1.2041x over previous
#include <cuda_runtime.h>
#include <cuda_bf16.h>
#include <math.h>

// ---------------- problem constants ----------------
#define BATCH 4
#define SEQ   1024
#define NTOK  (BATCH*SEQ)      // 4096
#define DMODEL 768
#define NHEAD 12
#define DHEAD 64
#define NOPE  32
#define ROPE  32
#define QP    384
#define KVP   512
#define CKVW  (KVP+ROPE)       // 544
#define UKVW  1152             // D + H*NOPE
#define NEXP  8
#define TOPK  2
#define FFDIM 3072

// ---------------- scratch (device globals; no allocations allowed) ----------------
__device__ float g_h1 [NTOK*DMODEL];
__device__ float g_cqp[NTOK*QP];
__device__ float g_cq [NTOK*QP];
__device__ float g_q  [NTOK*DMODEL];
__device__ float g_ckv[NTOK*CKVW];
__device__ float g_kvl[NTOK*KVP];
__device__ float g_kv [NTOK*UKVW];
__device__ float g_kr [NTOK*ROPE];
__device__ float g_o  [NTOK*DMODEL];
__device__ float g_x2 [NTOK*DMODEL];
__device__ float g_h2 [NTOK*DMODEL];
__device__ float g_ff [NTOK*FFDIM];
__device__ float g_ffe[(size_t)2*NTOK*FFDIM];      // slot-compact: row = slot*NTOK + token
__device__ float g_routed[2*NTOK*DMODEL];
__device__ int   g_ecnt[NEXP];
__device__ int   g_etok[NEXP*NTOK];
__device__ int   g_escat[NEXP*NTOK];
__device__ float g_ewt [NEXP*NTOK];

// ---------------- high-intensity tiled SGEMM ----------------
// 128x128 tile, K-step 8, 256 threads, 8x8 microtile, double-buffered smem.
// Requires K % 8 == 0 (true for all call sites). M/N boundaries guarded.
#define TM 128
#define TN 128
#define TKS 8
#define SPAD 132

template<bool TRANSB>
__device__ __forceinline__ void gemm_body(
    const float* __restrict__ A, const float* __restrict__ B, float* __restrict__ C,
    int M, int N, int K, int lda, int ldb, int ldc,
    const int* __restrict__ gather, const int* __restrict__ scatter,
    const float* __restrict__ residual, int ldr,
    const float* __restrict__ rowScale,
    int doGelu, int accum, int rt, int ct)
{
    __shared__ float As[2][TKS][SPAD];
    __shared__ float Bs[2][TKS][SPAD];
    const int tid = threadIdx.x;
    const int tx = tid & 15, ty = tid >> 4;
    const int row0 = rt * TM, col0 = ct * TN;

    // A loader: row = tid>>1 (0..127), k-half = (tid&1)*4
    const int alr = tid >> 1;
    const int akk = (tid & 1) * 4;
    const float* Arow = nullptr;
    {
        int gr = row0 + alr;
        if (gr < M) { int ar = gather ? gather[gr] : gr; Arow = A + (size_t)ar * lda; }
    }

    // B loader
    const float* Brow = nullptr;
    int bkk = 0, blr = 0, bc4 = 0, bkr = 0;
    if (TRANSB) {
        blr = tid >> 1; bkk = (tid & 1) * 4;
        int gc = col0 + blr;
        if (gc < N) Brow = B + (size_t)gc * ldb;
    } else {
        bkr = tid >> 5; bc4 = (tid & 31) * 4;
    }

    float4 aReg, bReg;

    auto loadA = [&](int k0) {
        aReg = Arow ? *reinterpret_cast<const float4*>(Arow + k0 + akk)
                    : make_float4(0.f, 0.f, 0.f, 0.f);
    };
    auto loadB = [&](int k0) {
        if (TRANSB) {
            bReg = Brow ? *reinterpret_cast<const float4*>(Brow + k0 + bkk)
                        : make_float4(0.f, 0.f, 0.f, 0.f);
        } else {
            int c = col0 + bc4;
            bReg = (c < N) ? *reinterpret_cast<const float4*>(B + (size_t)(k0 + bkr) * ldb + c)
                           : make_float4(0.f, 0.f, 0.f, 0.f);
        }
    };
    auto storeA = [&](int buf) {
        As[buf][akk + 0][alr] = aReg.x;
        As[buf][akk + 1][alr] = aReg.y;
        As[buf][akk + 2][alr] = aReg.z;
        As[buf][akk + 3][alr] = aReg.w;
    };
    auto storeB = [&](int buf) {
        if (TRANSB) {
            Bs[buf][bkk + 0][blr] = bReg.x;
            Bs[buf][bkk + 1][blr] = bReg.y;
            Bs[buf][bkk + 2][blr] = bReg.z;
            Bs[buf][bkk + 3][blr] = bReg.w;
        } else {
            *reinterpret_cast<float4*>(&Bs[buf][bkr][bc4]) = bReg;
        }
    };

    float acc[8][8] = {};
    loadA(0); loadB(0);
    storeA(0); storeB(0);
    __syncthreads();

    int buf = 0;
    for (int k0 = 0; k0 < K; k0 += TKS) {
        const bool more = (k0 + TKS) < K;
        if (more) { loadA(k0 + TKS); loadB(k0 + TKS); }
        #pragma unroll
        for (int kk = 0; kk < TKS; kk++) {
            float a[8], b[8];
            *(float4*)&a[0] = *(const float4*)&As[buf][kk][ty * 8];
            *(float4*)&a[4] = *(const float4*)&As[buf][kk][ty * 8 + 4];
            *(float4*)&b[0] = *(const float4*)&Bs[buf][kk][tx * 8];
            *(float4*)&b[4] = *(const float4*)&Bs[buf][kk][tx * 8 + 4];
            #pragma unroll
            for (int i = 0; i < 8; i++)
                #pragma unroll
                for (int j = 0; j < 8; j++)
                    acc[i][j] = fmaf(a[i], b[j], acc[i][j]);
        }
        if (more) { storeA(buf ^ 1); storeB(buf ^ 1); }
        __syncthreads();
        buf ^= 1;
    }

    #pragma unroll
    for (int i = 0; i < 8; i++) {
        int r = row0 + ty * 8 + i;
        if (r >= M) continue;
        int orow = scatter ? scatter[r] : r;
        float sc = rowScale ? rowScale[r] : 1.f;
        #pragma unroll
        for (int j = 0; j < 8; j++) {
            int c = col0 + tx * 8 + j;
            if (c >= N) continue;
            float v = acc[i][j];
            if (doGelu) v = 0.5f * v * (1.f + erff(v * 0.70710678118654752f));
            v *= sc;
            if (residual) v += residual[(size_t)r * ldr + c];
            size_t off = (size_t)orow * ldc + c;
            if (accum) C[off] += v; else C[off] = v;
        }
    }
}

template<bool TRANSB>
__global__ void __launch_bounds__(256) gemm_kernel(
    const float* __restrict__ A, const float* __restrict__ B, float* __restrict__ C,
    int M, int N, int K, int lda, int ldb, int ldc,
    const float* __restrict__ residual, int ldr, int doGelu, int accum)
{
    gemm_body<TRANSB>(A, B, C, M, N, K, lda, ldb, ldc,
                      nullptr, nullptr, residual, ldr, nullptr,
                      doGelu, accum, blockIdx.y, blockIdx.x);
}

// ---------------- expert (ragged) GEMMs ----------------
// ffe rows are slot-compact: row index = slot*NTOK + token (from escat).
__global__ void __launch_bounds__(256) expert_fc_kernel(
    const float* __restrict__ h2, const float* __restrict__ e_fc,
    float* __restrict__ ffe, const int* __restrict__ ecnt,
    const int* __restrict__ etok, const int* __restrict__ escat)
{
    int e = blockIdx.z;
    int cnt = ecnt[e];
    if ((int)blockIdx.y * TM >= cnt) return;
    gemm_body<true>(h2, e_fc + (size_t)e * FFDIM * DMODEL,
                    ffe,
                    cnt, FFDIM, DMODEL, DMODEL, DMODEL, FFDIM,
                    etok + e * NTOK, escat + e * NTOK, nullptr, 0, nullptr,
                    1, 0, blockIdx.y, blockIdx.x);
}

__global__ void __launch_bounds__(256) expert_proj_kernel(
    const float* __restrict__ ffe, const float* __restrict__ e_proj,
    float* __restrict__ routed, const int* __restrict__ ecnt,
    const int* __restrict__ escat, const float* __restrict__ ewt)
{
    int e = blockIdx.z;
    int cnt = ecnt[e];
    if ((int)blockIdx.y * TM >= cnt) return;
    gemm_body<true>(ffe,
                    e_proj + (size_t)e * DMODEL * FFDIM,
                    routed,
                    cnt, DMODEL, FFDIM, FFDIM, FFDIM, DMODEL,
                    escat + e * NTOK, escat + e * NTOK, nullptr, 0, ewt + e * NTOK,
                    0, 0, blockIdx.y, blockIdx.x);
}

// ---------------- layernorm ----------------
__global__ void ln_kernel(const float* __restrict__ in, int ldin, int W,
                          const float* __restrict__ w, const float* __restrict__ b,
                          float* __restrict__ out, int ldout)
{
    int t = blockIdx.x;
    int tid = threadIdx.x;
    const float* x = in + (size_t)t * ldin;
    float s = 0.f, sq = 0.f;
    for (int c = tid; c < W; c += blockDim.x) { float v = x[c]; s += v; sq += v*v; }
    __shared__ float rs[32], rq[32];
    #pragma unroll
    for (int o = 16; o; o >>= 1) { s += __shfl_xor_sync(~0u, s, o); sq += __shfl_xor_sync(~0u, sq, o); }
    int warp = tid >> 5, lane = tid & 31;
    if (lane == 0) { rs[warp] = s; rq[warp] = sq; }
    __syncthreads();
    int nw = blockDim.x >> 5;
    if (warp == 0) {
        s  = lane < nw ? rs[lane] : 0.f;
        sq = lane < nw ? rq[lane] : 0.f;
        #pragma unroll
        for (int o = 16; o; o >>= 1) { s += __shfl_xor_sync(~0u, s, o); sq += __shfl_xor_sync(~0u, sq, o); }
        if (lane == 0) { rs[0] = s; rq[0] = sq; }
    }
    __syncthreads();
    float mean = rs[0] / W;
    float var  = rq[0] / W - mean * mean;
    float rstd = rsqrtf(var + 1e-5f);
    float* y = out + (size_t)t * ldout;
    for (int c = tid; c < W; c += blockDim.x) {
        float v = (x[c] - mean) * rstd * w[c];
        if (b) v += b[c];
        y[c] = v;
    }
}

// ---------------- rope ----------------
__global__ void rope_kernel(float* __restrict__ q, const float* __restrict__ ckv,
                            float* __restrict__ kr)
{
    int t = blockIdx.x;
    int s = t & (SEQ - 1);
    int tid = threadIdx.x;        // 192 threads: h=tid/16, j=tid%16
    int h = tid >> 4, j = tid & 15;
    float freq = powf(10000.f, -(float)j / 32.f);
    float ang = (float)s * freq;
    float c = cosf(ang), si = sinf(ang);
    float* qp = q + (size_t)t * DMODEL + h * DHEAD + NOPE;
    float a = qp[j], bb = qp[j + 16];
    qp[j]      = a * c - bb * si;
    qp[j + 16] = bb * c + a * si;
    if (h == 0) {
        const float* kp = ckv + (size_t)t * CKVW + KVP;
        float a2 = kp[j], b2 = kp[j + 16];
        kr[t * ROPE + j]      = a2 * c - b2 * si;
        kr[t * ROPE + j + 16] = b2 * c + a2 * si;
    }
}

// ---------------- flash attention (causal), 64q x 32k tiles ----------------
__global__ void flash_kernel(const float* __restrict__ Q, const float* __restrict__ KV,
                             const float* __restrict__ KR, float* __restrict__ O)
{
    __shared__ float qs[64][65];
    __shared__ float ks[32][65];
    __shared__ float vs[32][65];
    __shared__ float ps[64][33];
    int qt = blockIdx.x;
    int bh = blockIdx.y;
    int b = bh / NHEAD, h = bh % NHEAD;
    int tid = threadIdx.x;
    int row = tid >> 2, tx = tid & 3;
    int tok0 = b * SEQ + qt * 64;

    for (int i = tid; i < 64 * 64; i += 256) {
        int r = i >> 6, d = i & 63;
        qs[r][d] = Q[(size_t)(tok0 + r) * DMODEL + h * DHEAD + d];
    }

    float m = -1e30f, l = 0.f;
    float acc[16];
    #pragma unroll
    for (int i = 0; i < 16; i++) acc[i] = 0.f;

    int nkt = 2 * qt + 2;
    int qglob = qt * 64 + row;
    for (int kt = 0; kt < nkt; kt++) {
        __syncthreads();
        for (int i = tid; i < 32 * 64; i += 256) {
            int c = i >> 6, d = i & 63;
            int t = b * SEQ + kt * 32 + c;
            vs[c][d] = KV[(size_t)t * UKVW + h * 96 + 32 + d];
            ks[c][d] = (d < 32) ? KV[(size_t)t * UKVW + h * 96 + d]
                                : KR[t * ROPE + (d - 32)];
        }
        __syncthreads();
        float s[8];
        #pragma unroll
        for (int cc = 0; cc < 8; cc++) {
            int c = tx * 8 + cc;
            float dot = 0.f;
            #pragma unroll
            for (int d = 0; d < 64; d++) dot = fmaf(qs[row][d], ks[c][d], dot);
            dot *= 0.125f;
            if (kt * 32 + c > qglob) dot = -1e30f;
            s[cc] = dot;
        }
        float mt = s[0];
        #pragma unroll
        for (int cc = 1; cc < 8; cc++) mt = fmaxf(mt, s[cc]);
        mt = fmaxf(mt, __shfl_xor_sync(0xffffffffu, mt, 1));
        mt = fmaxf(mt, __shfl_xor_sync(0xffffffffu, mt, 2));
        float mnew = fmaxf(m, mt);
        float corr = __expf(m - mnew);
        l *= corr;
        #pragma unroll
        for (int i = 0; i < 16; i++) acc[i] *= corr;
        float psum = 0.f;
        #pragma unroll
        for (int cc = 0; cc < 8; cc++) {
            float p = __expf(s[cc] - mnew);
            ps[row][tx * 8 + cc] = p;
            psum += p;
        }
        psum += __shfl_xor_sync(0xffffffffu, psum, 1);
        psum += __shfl_xor_sync(0xffffffffu, psum, 2);
        l += psum;
        m = mnew;
        __syncwarp();
        #pragma unroll 8
        for (int c = 0; c < 32; c++) {
            float pv = ps[row][c];
            #pragma unroll
            for (int i = 0; i < 16; i++)
                acc[i] = fmaf(pv, vs[c][tx * 16 + i], acc[i]);
        }
    }
    float inv = 1.f / l;
    #pragma unroll
    for (int i = 0; i < 16; i++)
        O[(size_t)(tok0 + row) * DMODEL + h * DHEAD + tx * 16 + i] = acc[i] * inv;
}

// ---------------- routing (sigmoid gates, top-2 of 8) ----------------
__global__ void zero_cnt_kernel(int* __restrict__ ecnt)
{
    if (threadIdx.x < NEXP) ecnt[threadIdx.x] = 0;
}

__global__ void routing_kernel(const float* __restrict__ h2,
                               const float* __restrict__ centroids,
                               const float* __restrict__ rbias,
                               int* __restrict__ ecnt, int* __restrict__ etok,
                               int* __restrict__ escat, float* __restrict__ ewt)
{
    int t = blockIdx.x;
    int tid = threadIdx.x;
    int warp = tid >> 5, lane = tid & 31;
    __shared__ float raw[NEXP];
    const float* hp = h2 + (size_t)t * DMODEL;
    const float* cp = centroids + (size_t)warp * DMODEL;
    float sum = 0.f;
    for (int d = lane; d < DMODEL; d += 32) sum += hp[d] * cp[d];
    #pragma unroll
    for (int o = 16; o; o >>= 1) sum += __shfl_xor_sync(~0u, sum, o);
    if (lane == 0) raw[warp] = sum;
    __syncthreads();
    if (tid == 0) {
        float bb[NEXP];
        #pragma unroll
        for (int e = 0; e < NEXP; e++) bb[e] = raw[e] + rbias[e];
        int i0 = 0;
        #pragma unroll
        for (int e = 1; e < NEXP; e++) if (bb[e] > bb[i0]) i0 = e;
        int i1 = -1;
        #pragma unroll
        for (int e = 0; e < NEXP; e++) {
            if (e == i0) continue;
            if (i1 < 0 || bb[e] > bb[i1]) i1 = e;
        }
        float w0 = 1.f / (1.f + expf(-raw[i0]));
        float w1 = 1.f / (1.f + expf(-raw[i1]));
        float s = w0 + w1 + 1e-9f;
        w0 /= s; w1 /= s;
        int p0 = atomicAdd(&ecnt[i0], 1);
        etok [i0 * NTOK + p0] = t;
        escat[i0 * NTOK + p0] = t;
        ewt  [i0 * NTOK + p0] = w0;
        int p1 = atomicAdd(&ecnt[i1], 1);
        etok [i1 * NTOK + p1] = t;
        escat[i1 * NTOK + p1] = NTOK + t;
        ewt  [i1 * NTOK + p1] = w1;
    }
}

__global__ void add2_kernel(float* __restrict__ out, const float* __restrict__ a,
                            const float* __restrict__ b, int n)
{
    int i = blockIdx.x * blockDim.x + threadIdx.x;
    if (i < n) out[i] += a[i] + b[i];
}

// ---------------- launcher ----------------
extern "C" void kernel_launch(void* const* d_in, const int* in_sizes, int n_in,
                              void* d_out, int out_size)
{
    const float* x        = (const float*)d_in[0];
    const float* ln1_w    = (const float*)d_in[1];
    const float* ln2_w    = (const float*)d_in[2];
    const float* W_dq     = (const float*)d_in[3];
    const float* W_uq     = (const float*)d_in[4];
    const float* q_ln_w   = (const float*)d_in[5];
    const float* q_ln_b   = (const float*)d_in[6];
    const float* W_dkv    = (const float*)d_in[7];
    const float* W_ukv    = (const float*)d_in[8];
    const float* kv_ln_w  = (const float*)d_in[9];
    const float* kv_ln_b  = (const float*)d_in[10];
    const float* W_o      = (const float*)d_in[11];
    const float* s_fc     = (const float*)d_in[12];
    const float* s_proj   = (const float*)d_in[13];
    const float* e_fc     = (const float*)d_in[14];
    const float* e_proj   = (const float*)d_in[15];
    const float* centroids= (const float*)d_in[16];
    const float* rbias    = (const float*)d_in[17];
    float* out = (float*)d_out;

    float *h1, *cqp, *cq, *q, *ckv, *kvl, *kv, *kr, *o, *x2, *h2, *ff, *ffe, *routed, *ewt;
    int *ecnt, *etok, *escat;
    cudaGetSymbolAddress((void**)&h1,  g_h1);
    cudaGetSymbolAddress((void**)&cqp, g_cqp);
    cudaGetSymbolAddress((void**)&cq,  g_cq);
    cudaGetSymbolAddress((void**)&q,   g_q);
    cudaGetSymbolAddress((void**)&ckv, g_ckv);
    cudaGetSymbolAddress((void**)&kvl, g_kvl);
    cudaGetSymbolAddress((void**)&kv,  g_kv);
    cudaGetSymbolAddress((void**)&kr,  g_kr);
    cudaGetSymbolAddress((void**)&o,   g_o);
    cudaGetSymbolAddress((void**)&x2,  g_x2);
    cudaGetSymbolAddress((void**)&h2,  g_h2);
    cudaGetSymbolAddress((void**)&ff,  g_ff);
    cudaGetSymbolAddress((void**)&ffe, g_ffe);
    cudaGetSymbolAddress((void**)&routed, g_routed);
    cudaGetSymbolAddress((void**)&ecnt, g_ecnt);
    cudaGetSymbolAddress((void**)&etok, g_etok);
    cudaGetSymbolAddress((void**)&escat, g_escat);
    cudaGetSymbolAddress((void**)&ewt, g_ewt);

    const int TB = 256;
    #define GRID(Mv, Nv) dim3(((Nv)+TN-1)/TN, ((Mv)+TM-1)/TM)

    // 1. h1 = LN(x)
    ln_kernel<<<NTOK, TB>>>(x, DMODEL, DMODEL, ln1_w, nullptr, h1, DMODEL);
    // 2. cq_pre = h1 @ W_dq
    gemm_kernel<false><<<GRID(NTOK, QP), TB>>>(h1, W_dq, cqp,
        NTOK, QP, DMODEL, DMODEL, QP, QP, nullptr, 0, 0, 0);
    // 3. cq = LN(cq_pre)
    ln_kernel<<<NTOK, TB>>>(cqp, QP, QP, q_ln_w, q_ln_b, cq, QP);
    // 4. Q = cq @ W_uq
    gemm_kernel<false><<<GRID(NTOK, DMODEL), TB>>>(cq, W_uq, q,
        NTOK, DMODEL, QP, QP, DMODEL, DMODEL, nullptr, 0, 0, 0);
    // 5. ckv = h1 @ W_dkv
    gemm_kernel<false><<<GRID(NTOK, CKVW), TB>>>(h1, W_dkv, ckv,
        NTOK, CKVW, DMODEL, DMODEL, CKVW, CKVW, nullptr, 0, 0, 0);
    // 6. kvl = LN(ckv[:, :512])
    ln_kernel<<<NTOK, TB>>>(ckv, CKVW, KVP, kv_ln_w, kv_ln_b, kvl, KVP);
    // 7. KV = kvl @ W_ukv
    gemm_kernel<false><<<GRID(NTOK, UKVW), TB>>>(kvl, W_ukv, kv,
        NTOK, UKVW, KVP, KVP, UKVW, UKVW, nullptr, 0, 0, 0);
    // 8. rope
    rope_kernel<<<NTOK, 192>>>(q, ckv, kr);
    // 9. attention
    flash_kernel<<<dim3(SEQ/64, BATCH*NHEAD), TB>>>(q, kv, kr, o);
    // 10. x2 = o @ W_o^T + x
    gemm_kernel<true><<<GRID(NTOK, DMODEL), TB>>>(o, W_o, x2,
        NTOK, DMODEL, DMODEL, DMODEL, DMODEL, DMODEL, x, DMODEL, 0, 0);
    // 11. h2 = LN(x2)
    ln_kernel<<<NTOK, TB>>>(x2, DMODEL, DMODEL, ln2_w, nullptr, h2, DMODEL);
    // 12. shared expert 0
    gemm_kernel<true><<<GRID(NTOK, FFDIM), TB>>>(h2, s_fc, ff,
        NTOK, FFDIM, DMODEL, DMODEL, DMODEL, FFDIM, nullptr, 0, 1, 0);
    gemm_kernel<true><<<GRID(NTOK, DMODEL), TB>>>(ff, s_proj, out,
        NTOK, DMODEL, FFDIM, FFDIM, FFDIM, DMODEL, x2, DMODEL, 0, 0);
    // 13. shared expert 1
    gemm_kernel<true><<<GRID(NTOK, FFDIM), TB>>>(h2, s_fc + (size_t)FFDIM*DMODEL, ff,
        NTOK, FFDIM, DMODEL, DMODEL, DMODEL, FFDIM, nullptr, 0, 1, 0);
    gemm_kernel<true><<<GRID(NTOK, DMODEL), TB>>>(ff, s_proj + (size_t)DMODEL*FFDIM, out,
        NTOK, DMODEL, FFDIM, FFDIM, FFDIM, DMODEL, nullptr, 0, 0, 1);
    // 14. routing
    zero_cnt_kernel<<<1, 32>>>(ecnt);
    routing_kernel<<<NTOK, TB>>>(h2, centroids, rbias, ecnt, etok, escat, ewt);
    // 15. routed experts (ragged GEMMs, slot-compact ffe)
    expert_fc_kernel<<<dim3(FFDIM/TN, NTOK/TM, NEXP), TB>>>(h2, e_fc, ffe, ecnt, etok, escat);
    expert_proj_kernel<<<dim3(DMODEL/TN, NTOK/TM, NEXP), TB>>>(ffe, e_proj, routed, ecnt, escat, ewt);
    // 16. out += routed_slot0 + routed_slot1
    add2_kernel<<<(NTOK*DMODEL + TB - 1)/TB, TB>>>(out, routed, routed + (size_t)NTOK*DMODEL, NTOK*DMODEL);
}

// round 6
// speedup vs baseline: 1.2434x; 1.0326x over previous
#include <cuda_runtime.h>
#include <cuda_bf16.h>
#include <math.h>

// ---------------- problem constants ----------------
#define BATCH 4
#define SEQ   1024
#define NTOK  (BATCH*SEQ)      // 4096
#define DMODEL 768
#define NHEAD 12
#define DHEAD 64
#define NOPE  32
#define ROPE  32
#define QP    384
#define KVP   512
#define CKVW  (KVP+ROPE)       // 544
#define UKVW  1152             // D + H*NOPE
#define NEXP  8
#define TOPK  2
#define FFDIM 3072

// ---------------- scratch (device globals; no allocations allowed) ----------------
__device__ float g_h1 [NTOK*DMODEL];
__device__ float g_cqp[NTOK*QP];
__device__ float g_cq [NTOK*QP];
__device__ float g_q  [NTOK*DMODEL];
__device__ float g_ckv[NTOK*CKVW];
__device__ float g_kvl[NTOK*KVP];
__device__ float g_kv [NTOK*UKVW];
__device__ float g_kr [NTOK*ROPE];
__device__ float g_o  [NTOK*DMODEL];
__device__ float g_x2 [NTOK*DMODEL];
__device__ float g_h2 [NTOK*DMODEL];
__device__ float g_ff [(size_t)2*NTOK*FFDIM];      // shared-expert hidden, slot per expert
__device__ float g_ffe[(size_t)2*NTOK*FFDIM];      // routed hidden, slot-compact
__device__ float g_shp[2*NTOK*DMODEL];             // shared-expert outputs
__device__ float g_routed[2*NTOK*DMODEL];          // routed outputs per slot
__device__ int   g_ecnt[NEXP];
__device__ int   g_etok[NEXP*NTOK];
__device__ int   g_escat[NEXP*NTOK];
__device__ float g_ewt [NEXP*NTOK];

// ---------------- high-intensity tiled SGEMM ----------------
// 128x128 tile, K-step 8, 256 threads, 8x8 microtile, double-buffered smem.
// Requires K % 8 == 0 (true for all call sites). M/N boundaries guarded.
#define TM 128
#define TN 128
#define TKS 8
#define SPAD 132

template<bool TRANSB>
__device__ __forceinline__ void gemm_body(
    const float* __restrict__ A, const float* __restrict__ B, float* __restrict__ C,
    int M, int N, int K, int lda, int ldb, int ldc,
    const int* __restrict__ gather, const int* __restrict__ scatter,
    const float* __restrict__ residual, int ldr,
    const float* __restrict__ rowScale,
    int doGelu, int accum, int rt, int ct)
{
    __shared__ float As[2][TKS][SPAD];
    __shared__ float Bs[2][TKS][SPAD];
    const int tid = threadIdx.x;
    const int tx = tid & 15, ty = tid >> 4;
    const int row0 = rt * TM, col0 = ct * TN;

    const int alr = tid >> 1;
    const int akk = (tid & 1) * 4;
    const float* Arow = nullptr;
    {
        int gr = row0 + alr;
        if (gr < M) { int ar = gather ? gather[gr] : gr; Arow = A + (size_t)ar * lda; }
    }

    const float* Brow = nullptr;
    int bkk = 0, blr = 0, bc4 = 0, bkr = 0;
    if (TRANSB) {
        blr = tid >> 1; bkk = (tid & 1) * 4;
        int gc = col0 + blr;
        if (gc < N) Brow = B + (size_t)gc * ldb;
    } else {
        bkr = tid >> 5; bc4 = (tid & 31) * 4;
    }

    float4 aReg, bReg;

    auto loadA = [&](int k0) {
        aReg = Arow ? *reinterpret_cast<const float4*>(Arow + k0 + akk)
                    : make_float4(0.f, 0.f, 0.f, 0.f);
    };
    auto loadB = [&](int k0) {
        if (TRANSB) {
            bReg = Brow ? *reinterpret_cast<const float4*>(Brow + k0 + bkk)
                        : make_float4(0.f, 0.f, 0.f, 0.f);
        } else {
            int c = col0 + bc4;
            bReg = (c < N) ? *reinterpret_cast<const float4*>(B + (size_t)(k0 + bkr) * ldb + c)
                           : make_float4(0.f, 0.f, 0.f, 0.f);
        }
    };
    auto storeA = [&](int buf) {
        As[buf][akk + 0][alr] = aReg.x;
        As[buf][akk + 1][alr] = aReg.y;
        As[buf][akk + 2][alr] = aReg.z;
        As[buf][akk + 3][alr] = aReg.w;
    };
    auto storeB = [&](int buf) {
        if (TRANSB) {
            Bs[buf][bkk + 0][blr] = bReg.x;
            Bs[buf][bkk + 1][blr] = bReg.y;
            Bs[buf][bkk + 2][blr] = bReg.z;
            Bs[buf][bkk + 3][blr] = bReg.w;
        } else {
            *reinterpret_cast<float4*>(&Bs[buf][bkr][bc4]) = bReg;
        }
    };

    float acc[8][8] = {};
    loadA(0); loadB(0);
    storeA(0); storeB(0);
    __syncthreads();

    int buf = 0;
    for (int k0 = 0; k0 < K; k0 += TKS) {
        const bool more = (k0 + TKS) < K;
        if (more) { loadA(k0 + TKS); loadB(k0 + TKS); }
        #pragma unroll
        for (int kk = 0; kk < TKS; kk++) {
            float a[8], b[8];
            *(float4*)&a[0] = *(const float4*)&As[buf][kk][ty * 8];
            *(float4*)&a[4] = *(const float4*)&As[buf][kk][ty * 8 + 4];
            *(float4*)&b[0] = *(const float4*)&Bs[buf][kk][tx * 8];
            *(float4*)&b[4] = *(const float4*)&Bs[buf][kk][tx * 8 + 4];
            #pragma unroll
            for (int i = 0; i < 8; i++)
                #pragma unroll
                for (int j = 0; j < 8; j++)
                    acc[i][j] = fmaf(a[i], b[j], acc[i][j]);
        }
        if (more) { storeA(buf ^ 1); storeB(buf ^ 1); }
        __syncthreads();
        buf ^= 1;
    }

    #pragma unroll
    for (int i = 0; i < 8; i++) {
        int r = row0 + ty * 8 + i;
        if (r >= M) continue;
        int orow = scatter ? scatter[r] : r;
        float sc = rowScale ? rowScale[r] : 1.f;
        #pragma unroll
        for (int j = 0; j < 8; j++) {
            int c = col0 + tx * 8 + j;
            if (c >= N) continue;
            float v = acc[i][j];
            if (doGelu) v = 0.5f * v * (1.f + erff(v * 0.70710678118654752f));
            v *= sc;
            if (residual) v += residual[(size_t)r * ldr + c];
            size_t off = (size_t)orow * ldc + c;
            if (accum) C[off] += v; else C[off] = v;
        }
    }
}

// descriptor for z-fused launches
struct GDesc {
    const float* A; const float* B; float* C;
    int M, N, K, lda, ldb, ldc;
    const float* residual; int ldr; int gelu;
};

template<bool TRANSB>
__global__ void __launch_bounds__(256, 2) gemm_kernel(
    const float* __restrict__ A, const float* __restrict__ B, float* __restrict__ C,
    int M, int N, int K, int lda, int ldb, int ldc,
    const float* __restrict__ residual, int ldr, int doGelu, int accum)
{
    gemm_body<TRANSB>(A, B, C, M, N, K, lda, ldb, ldc,
                      nullptr, nullptr, residual, ldr, nullptr,
                      doGelu, accum, blockIdx.y, blockIdx.x);
}

template<bool TRANSB>
__global__ void __launch_bounds__(256, 2) gemm2_kernel(GDesc d0, GDesc d1)
{
    const GDesc& d = (blockIdx.z == 0) ? d0 : d1;
    if ((int)blockIdx.x * TN >= d.N) return;
    if ((int)blockIdx.y * TM >= d.M) return;
    gemm_body<TRANSB>(d.A, d.B, d.C, d.M, d.N, d.K, d.lda, d.ldb, d.ldc,
                      nullptr, nullptr, d.residual, d.ldr, nullptr,
                      d.gelu, 0, blockIdx.y, blockIdx.x);
}

// ---------------- expert (ragged) GEMMs ----------------
__global__ void __launch_bounds__(256, 2) expert_fc_kernel(
    const float* __restrict__ h2, const float* __restrict__ e_fc,
    float* __restrict__ ffe, const int* __restrict__ ecnt,
    const int* __restrict__ etok, const int* __restrict__ escat)
{
    int e = blockIdx.z;
    int cnt = ecnt[e];
    if ((int)blockIdx.y * TM >= cnt) return;
    gemm_body<true>(h2, e_fc + (size_t)e * FFDIM * DMODEL,
                    ffe,
                    cnt, FFDIM, DMODEL, DMODEL, DMODEL, FFDIM,
                    etok + e * NTOK, escat + e * NTOK, nullptr, 0, nullptr,
                    1, 0, blockIdx.y, blockIdx.x);
}

__global__ void __launch_bounds__(256, 2) expert_proj_kernel(
    const float* __restrict__ ffe, const float* __restrict__ e_proj,
    float* __restrict__ routed, const int* __restrict__ ecnt,
    const int* __restrict__ escat, const float* __restrict__ ewt)
{
    int e = blockIdx.z;
    int cnt = ecnt[e];
    if ((int)blockIdx.y * TM >= cnt) return;
    gemm_body<true>(ffe,
                    e_proj + (size_t)e * DMODEL * FFDIM,
                    routed,
                    cnt, DMODEL, FFDIM, FFDIM, FFDIM, DMODEL,
                    escat + e * NTOK, escat + e * NTOK, nullptr, 0, ewt + e * NTOK,
                    0, 0, blockIdx.y, blockIdx.x);
}

// ---------------- layernorm ----------------
__global__ void ln_kernel(const float* __restrict__ in, int ldin, int W,
                          const float* __restrict__ w, const float* __restrict__ b,
                          float* __restrict__ out, int ldout)
{
    int t = blockIdx.x;
    int tid = threadIdx.x;
    const float* x = in + (size_t)t * ldin;
    float s = 0.f, sq = 0.f;
    for (int c = tid; c < W; c += blockDim.x) { float v = x[c]; s += v; sq += v*v; }
    __shared__ float rs[32], rq[32];
    #pragma unroll
    for (int o = 16; o; o >>= 1) { s += __shfl_xor_sync(~0u, s, o); sq += __shfl_xor_sync(~0u, sq, o); }
    int warp = tid >> 5, lane = tid & 31;
    if (lane == 0) { rs[warp] = s; rq[warp] = sq; }
    __syncthreads();
    int nw = blockDim.x >> 5;
    if (warp == 0) {
        s  = lane < nw ? rs[lane] : 0.f;
        sq = lane < nw ? rq[lane] : 0.f;
        #pragma unroll
        for (int o = 16; o; o >>= 1) { s += __shfl_xor_sync(~0u, s, o); sq += __shfl_xor_sync(~0u, sq, o); }
        if (lane == 0) { rs[0] = s; rq[0] = sq; }
    }
    __syncthreads();
    float mean = rs[0] / W;
    float var  = rq[0] / W - mean * mean;
    float rstd = rsqrtf(var + 1e-5f);
    float* y = out + (size_t)t * ldout;
    for (int c = tid; c < W; c += blockDim.x) {
        float v = (x[c] - mean) * rstd * w[c];
        if (b) v += b[c];
        y[c] = v;
    }
}

// ---------------- rope ----------------
__global__ void rope_kernel(float* __restrict__ q, const float* __restrict__ ckv,
                            float* __restrict__ kr)
{
    int t = blockIdx.x;
    int s = t & (SEQ - 1);
    int tid = threadIdx.x;        // 192 threads: h=tid/16, j=tid%16
    int h = tid >> 4, j = tid & 15;
    float freq = powf(10000.f, -(float)j / 32.f);
    float ang = (float)s * freq;
    float c = cosf(ang), si = sinf(ang);
    float* qp = q + (size_t)t * DMODEL + h * DHEAD + NOPE;
    float a = qp[j], bb = qp[j + 16];
    qp[j]      = a * c - bb * si;
    qp[j + 16] = bb * c + a * si;
    if (h == 0) {
        const float* kp = ckv + (size_t)t * CKVW + KVP;
        float a2 = kp[j], b2 = kp[j + 16];
        kr[t * ROPE + j]      = a2 * c - b2 * si;
        kr[t * ROPE + j + 16] = b2 * c + a2 * si;
    }
}

// ---------------- flash attention (causal), 64q x 32k tiles ----------------
__global__ void flash_kernel(const float* __restrict__ Q, const float* __restrict__ KV,
                             const float* __restrict__ KR, float* __restrict__ O)
{
    __shared__ float qs[64][65];
    __shared__ float ks[32][65];
    __shared__ float vs[32][65];
    __shared__ float ps[64][33];
    int qt = blockIdx.x;
    int bh = blockIdx.y;
    int b = bh / NHEAD, h = bh % NHEAD;
    int tid = threadIdx.x;
    int row = tid >> 2, tx = tid & 3;
    int tok0 = b * SEQ + qt * 64;

    for (int i = tid; i < 64 * 64; i += 256) {
        int r = i >> 6, d = i & 63;
        qs[r][d] = Q[(size_t)(tok0 + r) * DMODEL + h * DHEAD + d];
    }

    float m = -1e30f, l = 0.f;
    float acc[16];
    #pragma unroll
    for (int i = 0; i < 16; i++) acc[i] = 0.f;

    int nkt = 2 * qt + 2;
    int qglob = qt * 64 + row;
    for (int kt = 0; kt < nkt; kt++) {
        __syncthreads();
        for (int i = tid; i < 32 * 64; i += 256) {
            int c = i >> 6, d = i & 63;
            int t = b * SEQ + kt * 32 + c;
            vs[c][d] = KV[(size_t)t * UKVW + h * 96 + 32 + d];
            ks[c][d] = (d < 32) ? KV[(size_t)t * UKVW + h * 96 + d]
                                : KR[t * ROPE + (d - 32)];
        }
        __syncthreads();
        float s[8];
        #pragma unroll
        for (int cc = 0; cc < 8; cc++) {
            int c = tx * 8 + cc;
            float dot = 0.f;
            #pragma unroll
            for (int d = 0; d < 64; d++) dot = fmaf(qs[row][d], ks[c][d], dot);
            dot *= 0.125f;
            if (kt * 32 + c > qglob) dot = -1e30f;
            s[cc] = dot;
        }
        float mt = s[0];
        #pragma unroll
        for (int cc = 1; cc < 8; cc++) mt = fmaxf(mt, s[cc]);
        mt = fmaxf(mt, __shfl_xor_sync(0xffffffffu, mt, 1));
        mt = fmaxf(mt, __shfl_xor_sync(0xffffffffu, mt, 2));
        float mnew = fmaxf(m, mt);
        float corr = __expf(m - mnew);
        l *= corr;
        #pragma unroll
        for (int i = 0; i < 16; i++) acc[i] *= corr;
        float psum = 0.f;
        #pragma unroll
        for (int cc = 0; cc < 8; cc++) {
            float p = __expf(s[cc] - mnew);
            ps[row][tx * 8 + cc] = p;
            psum += p;
        }
        psum += __shfl_xor_sync(0xffffffffu, psum, 1);
        psum += __shfl_xor_sync(0xffffffffu, psum, 2);
        l += psum;
        m = mnew;
        __syncwarp();
        #pragma unroll 8
        for (int c = 0; c < 32; c++) {
            float pv = ps[row][c];
            #pragma unroll
            for (int i = 0; i < 16; i++)
                acc[i] = fmaf(pv, vs[c][tx * 16 + i], acc[i]);
        }
    }
    float inv = 1.f / l;
    #pragma unroll
    for (int i = 0; i < 16; i++)
        O[(size_t)(tok0 + row) * DMODEL + h * DHEAD + tx * 16 + i] = acc[i] * inv;
}

// ---------------- routing (sigmoid gates, top-2 of 8) ----------------
__global__ void zero_cnt_kernel(int* __restrict__ ecnt)
{
    if (threadIdx.x < NEXP) ecnt[threadIdx.x] = 0;
}

__global__ void routing_kernel(const float* __restrict__ h2,
                               const float* __restrict__ centroids,
                               const float* __restrict__ rbias,
                               int* __restrict__ ecnt, int* __restrict__ etok,
                               int* __restrict__ escat, float* __restrict__ ewt)
{
    int t = blockIdx.x;
    int tid = threadIdx.x;
    int warp = tid >> 5, lane = tid & 31;
    __shared__ float raw[NEXP];
    const float* hp = h2 + (size_t)t * DMODEL;
    const float* cp = centroids + (size_t)warp * DMODEL;
    float sum = 0.f;
    for (int d = lane; d < DMODEL; d += 32) sum += hp[d] * cp[d];
    #pragma unroll
    for (int o = 16; o; o >>= 1) sum += __shfl_xor_sync(~0u, sum, o);
    if (lane == 0) raw[warp] = sum;
    __syncthreads();
    if (tid == 0) {
        float bb[NEXP];
        #pragma unroll
        for (int e = 0; e < NEXP; e++) bb[e] = raw[e] + rbias[e];
        int i0 = 0;
        #pragma unroll
        for (int e = 1; e < NEXP; e++) if (bb[e] > bb[i0]) i0 = e;
        int i1 = -1;
        #pragma unroll
        for (int e = 0; e < NEXP; e++) {
            if (e == i0) continue;
            if (i1 < 0 || bb[e] > bb[i1]) i1 = e;
        }
        float w0 = 1.f / (1.f + expf(-raw[i0]));
        float w1 = 1.f / (1.f + expf(-raw[i1]));
        float s = w0 + w1 + 1e-9f;
        w0 /= s; w1 /= s;
        int p0 = atomicAdd(&ecnt[i0], 1);
        etok [i0 * NTOK + p0] = t;
        escat[i0 * NTOK + p0] = t;
        ewt  [i0 * NTOK + p0] = w0;
        int p1 = atomicAdd(&ecnt[i1], 1);
        etok [i1 * NTOK + p1] = t;
        escat[i1 * NTOK + p1] = NTOK + t;
        ewt  [i1 * NTOK + p1] = w1;
    }
}

__global__ void add5_kernel(float* __restrict__ out, const float* __restrict__ x2,
                            const float* __restrict__ a, const float* __restrict__ b,
                            const float* __restrict__ c, const float* __restrict__ d,
                            int n)
{
    int i = blockIdx.x * blockDim.x + threadIdx.x;
    if (i < n) out[i] = x2[i] + a[i] + b[i] + c[i] + d[i];
}

// ---------------- launcher ----------------
extern "C" void kernel_launch(void* const* d_in, const int* in_sizes, int n_in,
                              void* d_out, int out_size)
{
    const float* x        = (const float*)d_in[0];
    const float* ln1_w    = (const float*)d_in[1];
    const float* ln2_w    = (const float*)d_in[2];
    const float* W_dq     = (const float*)d_in[3];
    const float* W_uq     = (const float*)d_in[4];
    const float* q_ln_w   = (const float*)d_in[5];
    const float* q_ln_b   = (const float*)d_in[6];
    const float* W_dkv    = (const float*)d_in[7];
    const float* W_ukv    = (const float*)d_in[8];
    const float* kv_ln_w  = (const float*)d_in[9];
    const float* kv_ln_b  = (const float*)d_in[10];
    const float* W_o      = (const float*)d_in[11];
    const float* s_fc     = (const float*)d_in[12];
    const float* s_proj   = (const float*)d_in[13];
    const float* e_fc     = (const float*)d_in[14];
    const float* e_proj   = (const float*)d_in[15];
    const float* centroids= (const float*)d_in[16];
    const float* rbias    = (const float*)d_in[17];
    float* out = (float*)d_out;

    float *h1, *cqp, *cq, *q, *ckv, *kvl, *kv, *kr, *o, *x2, *h2, *ff, *ffe, *shp, *routed, *ewt;
    int *ecnt, *etok, *escat;
    cudaGetSymbolAddress((void**)&h1,  g_h1);
    cudaGetSymbolAddress((void**)&cqp, g_cqp);
    cudaGetSymbolAddress((void**)&cq,  g_cq);
    cudaGetSymbolAddress((void**)&q,   g_q);
    cudaGetSymbolAddress((void**)&ckv, g_ckv);
    cudaGetSymbolAddress((void**)&kvl, g_kvl);
    cudaGetSymbolAddress((void**)&kv,  g_kv);
    cudaGetSymbolAddress((void**)&kr,  g_kr);
    cudaGetSymbolAddress((void**)&o,   g_o);
    cudaGetSymbolAddress((void**)&x2,  g_x2);
    cudaGetSymbolAddress((void**)&h2,  g_h2);
    cudaGetSymbolAddress((void**)&ff,  g_ff);
    cudaGetSymbolAddress((void**)&ffe, g_ffe);
    cudaGetSymbolAddress((void**)&shp, g_shp);
    cudaGetSymbolAddress((void**)&routed, g_routed);
    cudaGetSymbolAddress((void**)&ecnt, g_ecnt);
    cudaGetSymbolAddress((void**)&etok, g_etok);
    cudaGetSymbolAddress((void**)&escat, g_escat);
    cudaGetSymbolAddress((void**)&ewt, g_ewt);

    const int TB = 256;
    #define NT(Nv) (((Nv)+TN-1)/TN)

    // 1. h1 = LN(x)
    ln_kernel<<<NTOK, TB>>>(x, DMODEL, DMODEL, ln1_w, nullptr, h1, DMODEL);

    // 2. fused: cq_pre = h1@W_dq  |  ckv = h1@W_dkv
    {
        GDesc d0{h1, W_dq,  cqp, NTOK, QP,   DMODEL, DMODEL, QP,   QP,   nullptr, 0, 0};
        GDesc d1{h1, W_dkv, ckv, NTOK, CKVW, DMODEL, DMODEL, CKVW, CKVW, nullptr, 0, 0};
        gemm2_kernel<false><<<dim3(NT(CKVW), NTOK/TM, 2), TB>>>(d0, d1);
    }
    // 3. LNs on cq_pre and ckv[:, :512]
    ln_kernel<<<NTOK, TB>>>(cqp, QP, QP, q_ln_w, q_ln_b, cq, QP);
    ln_kernel<<<NTOK, TB>>>(ckv, CKVW, KVP, kv_ln_w, kv_ln_b, kvl, KVP);

    // 4. fused: Q = cq@W_uq  |  KV = kvl@W_ukv
    {
        GDesc d0{cq,  W_uq,  q,  NTOK, DMODEL, QP,  QP,  DMODEL, DMODEL, nullptr, 0, 0};
        GDesc d1{kvl, W_ukv, kv, NTOK, UKVW,   KVP, KVP, UKVW,   UKVW,   nullptr, 0, 0};
        gemm2_kernel<false><<<dim3(NT(UKVW), NTOK/TM, 2), TB>>>(d0, d1);
    }
    // 5. rope
    rope_kernel<<<NTOK, 192>>>(q, ckv, kr);
    // 6. attention
    flash_kernel<<<dim3(SEQ/64, BATCH*NHEAD), TB>>>(q, kv, kr, o);
    // 7. x2 = o @ W_o^T + x
    gemm_kernel<true><<<dim3(NT(DMODEL), NTOK/TM), TB>>>(o, W_o, x2,
        NTOK, DMODEL, DMODEL, DMODEL, DMODEL, DMODEL, x, DMODEL, 0, 0);
    // 8. h2 = LN(x2)
    ln_kernel<<<NTOK, TB>>>(x2, DMODEL, DMODEL, ln2_w, nullptr, h2, DMODEL);

    // 9. routing (depends only on h2; run before MLP so expert GEMMs are ready)
    zero_cnt_kernel<<<1, 32>>>(ecnt);
    routing_kernel<<<NTOK, TB>>>(h2, centroids, rbias, ecnt, etok, escat, ewt);

    // 10. fused shared fc (both experts in one launch)
    {
        GDesc d0{h2, s_fc,                          ff,                          NTOK, FFDIM, DMODEL, DMODEL, DMODEL, FFDIM, nullptr, 0, 1};
        GDesc d1{h2, s_fc + (size_t)FFDIM*DMODEL,   ff + (size_t)NTOK*FFDIM,     NTOK, FFDIM, DMODEL, DMODEL, DMODEL, FFDIM, nullptr, 0, 1};
        gemm2_kernel<true><<<dim3(NT(FFDIM), NTOK/TM, 2), TB>>>(d0, d1);
    }
    // 11. fused shared proj (into private slot buffers)
    {
        GDesc d0{ff,                        s_proj,                        shp,                        NTOK, DMODEL, FFDIM, FFDIM, FFDIM, DMODEL, nullptr, 0, 0};
        GDesc d1{ff + (size_t)NTOK*FFDIM,   s_proj + (size_t)DMODEL*FFDIM, shp + (size_t)NTOK*DMODEL,  NTOK, DMODEL, FFDIM, FFDIM, FFDIM, DMODEL, nullptr, 0, 0};
        gemm2_kernel<true><<<dim3(NT(DMODEL), NTOK/TM, 2), TB>>>(d0, d1);
    }
    // 12. routed experts (ragged GEMMs, slot-compact ffe)
    expert_fc_kernel<<<dim3(FFDIM/TN, NTOK/TM, NEXP), TB>>>(h2, e_fc, ffe, ecnt, etok, escat);
    expert_proj_kernel<<<dim3(DMODEL/TN, NTOK/TM, NEXP), TB>>>(ffe, e_proj, routed, ecnt, escat, ewt);
    // 13. out = x2 + shared0 + shared1 + routed0 + routed1
    add5_kernel<<<(NTOK*DMODEL + TB - 1)/TB, TB>>>(out, x2,
        shp, shp + (size_t)NTOK*DMODEL,
        routed, routed + (size_t)NTOK*DMODEL, NTOK*DMODEL);
}

// round 8
// speedup vs baseline: 2.5878x; 2.0813x over previous
#include <cuda_runtime.h>
#include <cuda_bf16.h>
#include <math.h>
#include <stdint.h>

// ---------------- problem constants ----------------
#define BATCH 4
#define SEQ   1024
#define NTOK  (BATCH*SEQ)      // 4096
#define DMODEL 768
#define NHEAD 12
#define DHEAD 64
#define NOPE  32
#define ROPE  32
#define QP    384
#define KVP   512
#define CKVW  (KVP+ROPE)       // 544
#define UKVW  1152             // D + H*NOPE
#define NEXP  8
#define TOPK  2
#define FFDIM 3072

// ---------------- scratch ----------------
__device__ float g_h1 [NTOK*DMODEL];
__device__ float g_cqp[NTOK*QP];
__device__ float g_cq [NTOK*QP];
__device__ float g_q  [NTOK*DMODEL];
__device__ float g_ckv[NTOK*CKVW];
__device__ float g_kvl[NTOK*KVP];
__device__ float g_kv [NTOK*UKVW];
__device__ float g_kr [NTOK*ROPE];
__device__ float g_o  [NTOK*DMODEL];
__device__ float g_x2 [NTOK*DMODEL];
__device__ float g_h2 [NTOK*DMODEL];
__device__ float g_ff [(size_t)2*NTOK*FFDIM];
__device__ float g_ffe[(size_t)2*NTOK*FFDIM];
__device__ float g_shp[2*NTOK*DMODEL];
__device__ float g_routed[2*NTOK*DMODEL];
__device__ int   g_ecnt[NEXP];
__device__ int   g_etok[NEXP*NTOK];
__device__ int   g_escat[NEXP*NTOK];
__device__ float g_ewt [NEXP*NTOK];

// ---------------- tf32 tensor-core GEMM ----------------
// 128x128 tile, K-stage 16, 256 threads (8 warps, 4x2), each warp 32x64.
// mma.sync.m16n8k8 tf32, fp32 accumulate. K % 16 == 0 at all call sites.
#define TM 128
#define TN 128
#define KS 16
#define KPAD 136   // 136 % 32 == 8 -> conflict-free fragment loads

__device__ __forceinline__ float to_tf32(float x) {
    uint32_t u;
    asm("cvt.rna.tf32.f32 %0, %1;" : "=r"(u) : "f"(x));
    return __uint_as_float(u);
}

__device__ __forceinline__ void mma_tf32(float& c0, float& c1, float& c2, float& c3,
                                         float a0, float a1, float a2, float a3,
                                         float b0, float b1)
{
    asm volatile(
        "mma.sync.aligned.m16n8k8.row.col.f32.tf32.tf32.f32 "
        "{%0,%1,%2,%3}, {%4,%5,%6,%7}, {%8,%9}, {%0,%1,%2,%3};\n"
        : "+f"(c0), "+f"(c1), "+f"(c2), "+f"(c3)
        : "r"(__float_as_uint(a0)), "r"(__float_as_uint(a1)),
          "r"(__float_as_uint(a2)), "r"(__float_as_uint(a3)),
          "r"(__float_as_uint(b0)), "r"(__float_as_uint(b1)));
}

template<bool TRANSB>
__device__ __forceinline__ void gemm_body(
    const float* __restrict__ A, const float* __restrict__ B, float* __restrict__ C,
    int M, int N, int K, int lda, int ldb, int ldc,
    const int* __restrict__ gather, const int* __restrict__ scatter,
    const float* __restrict__ residual, int ldr,
    const float* __restrict__ rowScale,
    int doGelu, int accum, int rt, int ct)
{
    __shared__ float As[2][KS][KPAD];   // k-major, tf32 bits
    __shared__ float Bs[2][KS][KPAD];
    const int tid = threadIdx.x;
    const int lane = tid & 31, wid = tid >> 5;
    const int group = lane >> 2, tig = lane & 3;
    const int warp_m = wid & 3;        // 4 warps along M, 32 rows each
    const int warp_n = wid >> 2;       // 2 warps along N, 64 cols each
    const int row0 = rt * TM, col0 = ct * TN;

    // A loader: row = tid>>1 (0..127), k-quad = (tid&1)*4, plus +8
    const int alr = tid >> 1;
    const int akk = (tid & 1) * 4;
    const float* Arow = nullptr;
    {
        int gr = row0 + alr;
        if (gr < M) { int ar = gather ? gather[gr] : gr; Arow = A + (size_t)ar * lda; }
    }

    // B loader
    const float* Brow = nullptr;
    int bkr = 0, bc4 = 0;
    if (TRANSB) {
        int gc = col0 + alr;
        if (gc < N) Brow = B + (size_t)gc * ldb;
    } else {
        bkr = tid >> 5; bc4 = (tid & 31) * 4;
    }

    float4 aR0, aR1, bR0, bR1;
    auto loadG = [&](int k0) {
        aR0 = Arow ? *(const float4*)(Arow + k0 + akk)     : make_float4(0,0,0,0);
        aR1 = Arow ? *(const float4*)(Arow + k0 + akk + 8) : make_float4(0,0,0,0);
        if (TRANSB) {
            bR0 = Brow ? *(const float4*)(Brow + k0 + akk)     : make_float4(0,0,0,0);
            bR1 = Brow ? *(const float4*)(Brow + k0 + akk + 8) : make_float4(0,0,0,0);
        } else {
            int c = col0 + bc4;
            bR0 = (c < N) ? *(const float4*)(B + (size_t)(k0 + bkr) * ldb + c)     : make_float4(0,0,0,0);
            bR1 = (c < N) ? *(const float4*)(B + (size_t)(k0 + bkr + 8) * ldb + c) : make_float4(0,0,0,0);
        }
    };
    auto storeS = [&](int buf) {
        As[buf][akk+0][alr] = to_tf32(aR0.x);
        As[buf][akk+1][alr] = to_tf32(aR0.y);
        As[buf][akk+2][alr] = to_tf32(aR0.z);
        As[buf][akk+3][alr] = to_tf32(aR0.w);
        As[buf][akk+8][alr] = to_tf32(aR1.x);
        As[buf][akk+9][alr] = to_tf32(aR1.y);
        As[buf][akk+10][alr] = to_tf32(aR1.z);
        As[buf][akk+11][alr] = to_tf32(aR1.w);
        if (TRANSB) {
            Bs[buf][akk+0][alr] = to_tf32(bR0.x);
            Bs[buf][akk+1][alr] = to_tf32(bR0.y);
            Bs[buf][akk+2][alr] = to_tf32(bR0.z);
            Bs[buf][akk+3][alr] = to_tf32(bR0.w);
            Bs[buf][akk+8][alr] = to_tf32(bR1.x);
            Bs[buf][akk+9][alr] = to_tf32(bR1.y);
            Bs[buf][akk+10][alr] = to_tf32(bR1.z);
            Bs[buf][akk+11][alr] = to_tf32(bR1.w);
        } else {
            float4 t0 = make_float4(to_tf32(bR0.x), to_tf32(bR0.y), to_tf32(bR0.z), to_tf32(bR0.w));
            float4 t1 = make_float4(to_tf32(bR1.x), to_tf32(bR1.y), to_tf32(bR1.z), to_tf32(bR1.w));
            *(float4*)&Bs[buf][bkr][bc4]     = t0;
            *(float4*)&Bs[buf][bkr + 8][bc4] = t1;
        }
    };

    float acc[2][8][4];
    #pragma unroll
    for (int i = 0; i < 2; i++)
        #pragma unroll
        for (int j = 0; j < 8; j++)
            #pragma unroll
            for (int c = 0; c < 4; c++) acc[i][j][c] = 0.f;

    loadG(0);
    storeS(0);
    __syncthreads();

    const int m0 = warp_m * 32;
    const int n0 = warp_n * 64;
    int buf = 0;
    for (int k0 = 0; k0 < K; k0 += KS) {
        const bool more = (k0 + KS) < K;
        if (more) loadG(k0 + KS);
        #pragma unroll
        for (int half = 0; half < 2; half++) {
            const int kb = half * 8;
            float a[2][4];
            #pragma unroll
            for (int i = 0; i < 2; i++) {
                int mb = m0 + i * 16 + group;
                a[i][0] = As[buf][kb + tig][mb];
                a[i][1] = As[buf][kb + tig][mb + 8];
                a[i][2] = As[buf][kb + tig + 4][mb];
                a[i][3] = As[buf][kb + tig + 4][mb + 8];
            }
            #pragma unroll
            for (int j = 0; j < 8; j++) {
                int nb = n0 + j * 8 + group;
                float b0 = Bs[buf][kb + tig][nb];
                float b1 = Bs[buf][kb + tig + 4][nb];
                #pragma unroll
                for (int i = 0; i < 2; i++)
                    mma_tf32(acc[i][j][0], acc[i][j][1], acc[i][j][2], acc[i][j][3],
                             a[i][0], a[i][1], a[i][2], a[i][3], b0, b1);
            }
        }
        if (more) storeS(buf ^ 1);
        __syncthreads();
        buf ^= 1;
    }

    // epilogue
    auto emit = [&](int r, int c, float v) {
        if (r >= M || c >= N) return;
        if (doGelu) v = 0.5f * v * (1.f + erff(v * 0.70710678118654752f));
        if (rowScale) v *= rowScale[r];
        if (residual) v += residual[(size_t)r * ldr + c];
        int orow = scatter ? scatter[r] : r;
        size_t off = (size_t)orow * ldc + c;
        if (accum) C[off] += v; else C[off] = v;
    };
    #pragma unroll
    for (int i = 0; i < 2; i++) {
        int rA = row0 + m0 + i * 16 + group;
        int rB = rA + 8;
        #pragma unroll
        for (int j = 0; j < 8; j++) {
            int c = col0 + n0 + j * 8 + 2 * tig;
            emit(rA, c,     acc[i][j][0]);
            emit(rA, c + 1, acc[i][j][1]);
            emit(rB, c,     acc[i][j][2]);
            emit(rB, c + 1, acc[i][j][3]);
        }
    }
}

// descriptor for z-fused launches
struct GDesc {
    const float* A; const float* B; float* C;
    int M, N, K, lda, ldb, ldc;
    const float* residual; int ldr; int gelu;
};

template<bool TRANSB>
__global__ void __launch_bounds__(256, 2) gemm_kernel(
    const float* __restrict__ A, const float* __restrict__ B, float* __restrict__ C,
    int M, int N, int K, int lda, int ldb, int ldc,
    const float* __restrict__ residual, int ldr, int doGelu, int accum)
{
    gemm_body<TRANSB>(A, B, C, M, N, K, lda, ldb, ldc,
                      nullptr, nullptr, residual, ldr, nullptr,
                      doGelu, accum, blockIdx.y, blockIdx.x);
}

template<bool TRANSB>
__global__ void __launch_bounds__(256, 2) gemm2_kernel(GDesc d0, GDesc d1)
{
    const GDesc& d = (blockIdx.z == 0) ? d0 : d1;
    if ((int)blockIdx.x * TN >= d.N) return;
    if ((int)blockIdx.y * TM >= d.M) return;
    gemm_body<TRANSB>(d.A, d.B, d.C, d.M, d.N, d.K, d.lda, d.ldb, d.ldc,
                      nullptr, nullptr, d.residual, d.ldr, nullptr,
                      d.gelu, 0, blockIdx.y, blockIdx.x);
}

// ---------------- expert (ragged) GEMMs ----------------
__global__ void __launch_bounds__(256, 2) expert_fc_kernel(
    const float* __restrict__ h2, const float* __restrict__ e_fc,
    float* __restrict__ ffe, const int* __restrict__ ecnt,
    const int* __restrict__ etok, const int* __restrict__ escat)
{
    int e = blockIdx.z;
    int cnt = ecnt[e];
    if ((int)blockIdx.y * TM >= cnt) return;
    gemm_body<true>(h2, e_fc + (size_t)e * FFDIM * DMODEL,
                    ffe,
                    cnt, FFDIM, DMODEL, DMODEL, DMODEL, FFDIM,
                    etok + e * NTOK, escat + e * NTOK, nullptr, 0, nullptr,
                    1, 0, blockIdx.y, blockIdx.x);
}

__global__ void __launch_bounds__(256, 2) expert_proj_kernel(
    const float* __restrict__ ffe, const float* __restrict__ e_proj,
    float* __restrict__ routed, const int* __restrict__ ecnt,
    const int* __restrict__ escat, const float* __restrict__ ewt)
{
    int e = blockIdx.z;
    int cnt = ecnt[e];
    if ((int)blockIdx.y * TM >= cnt) return;
    gemm_body<true>(ffe,
                    e_proj + (size_t)e * DMODEL * FFDIM,
                    routed,
                    cnt, DMODEL, FFDIM, FFDIM, FFDIM, DMODEL,
                    escat + e * NTOK, escat + e * NTOK, nullptr, 0, ewt + e * NTOK,
                    0, 0, blockIdx.y, blockIdx.x);
}

// ---------------- layernorm ----------------
__global__ void ln_kernel(const float* __restrict__ in, int ldin, int W,
                          const float* __restrict__ w, const float* __restrict__ b,
                          float* __restrict__ out, int ldout)
{
    int t = blockIdx.x;
    int tid = threadIdx.x;
    const float* x = in + (size_t)t * ldin;
    float s = 0.f, sq = 0.f;
    for (int c = tid; c < W; c += blockDim.x) { float v = x[c]; s += v; sq += v*v; }
    __shared__ float rs[32], rq[32];
    #pragma unroll
    for (int o = 16; o; o >>= 1) { s += __shfl_xor_sync(~0u, s, o); sq += __shfl_xor_sync(~0u, sq, o); }
    int warp = tid >> 5, lane = tid & 31;
    if (lane == 0) { rs[warp] = s; rq[warp] = sq; }
    __syncthreads();
    int nw = blockDim.x >> 5;
    if (warp == 0) {
        s  = lane < nw ? rs[lane] : 0.f;
        sq = lane < nw ? rq[lane] : 0.f;
        #pragma unroll
        for (int o = 16; o; o >>= 1) { s += __shfl_xor_sync(~0u, s, o); sq += __shfl_xor_sync(~0u, sq, o); }
        if (lane == 0) { rs[0] = s; rq[0] = sq; }
    }
    __syncthreads();
    float mean = rs[0] / W;
    float var  = rq[0] / W - mean * mean;
    float rstd = rsqrtf(var + 1e-5f);
    float* y = out + (size_t)t * ldout;
    for (int c = tid; c < W; c += blockDim.x) {
        float v = (x[c] - mean) * rstd * w[c];
        if (b) v += b[c];
        y[c] = v;
    }
}

// ---------------- rope ----------------
__global__ void rope_kernel(float* __restrict__ q, const float* __restrict__ ckv,
                            float* __restrict__ kr)
{
    int t = blockIdx.x;
    int s = t & (SEQ - 1);
    int tid = threadIdx.x;        // 192 threads: h=tid/16, j=tid%16
    int h = tid >> 4, j = tid & 15;
    float freq = powf(10000.f, -(float)j / 32.f);
    float ang = (float)s * freq;
    float c = cosf(ang), si = sinf(ang);
    float* qp = q + (size_t)t * DMODEL + h * DHEAD + NOPE;
    float a = qp[j], bb = qp[j + 16];
    qp[j]      = a * c - bb * si;
    qp[j + 16] = bb * c + a * si;
    if (h == 0) {
        const float* kp = ckv + (size_t)t * CKVW + KVP;
        float a2 = kp[j], b2 = kp[j + 16];
        kr[t * ROPE + j]      = a2 * c - b2 * si;
        kr[t * ROPE + j + 16] = b2 * c + a2 * si;
    }
}

// ---------------- flash attention (causal), 64q x 32k tiles ----------------
__global__ void flash_kernel(const float* __restrict__ Q, const float* __restrict__ KV,
                             const float* __restrict__ KR, float* __restrict__ O)
{
    __shared__ float qs[64][65];
    __shared__ float ks[32][65];
    __shared__ float vs[32][65];
    __shared__ float ps[64][33];
    int qt = blockIdx.x;
    int bh = blockIdx.y;
    int b = bh / NHEAD, h = bh % NHEAD;
    int tid = threadIdx.x;
    int row = tid >> 2, tx = tid & 3;
    int tok0 = b * SEQ + qt * 64;

    for (int i = tid; i < 64 * 64; i += 256) {
        int r = i >> 6, d = i & 63;
        qs[r][d] = Q[(size_t)(tok0 + r) * DMODEL + h * DHEAD + d];
    }

    float m = -1e30f, l = 0.f;
    float acc[16];
    #pragma unroll
    for (int i = 0; i < 16; i++) acc[i] = 0.f;

    int nkt = 2 * qt + 2;
    int qglob = qt * 64 + row;
    for (int kt = 0; kt < nkt; kt++) {
        __syncthreads();
        for (int i = tid; i < 32 * 64; i += 256) {
            int c = i >> 6, d = i & 63;
            int t = b * SEQ + kt * 32 + c;
            vs[c][d] = KV[(size_t)t * UKVW + h * 96 + 32 + d];
            ks[c][d] = (d < 32) ? KV[(size_t)t * UKVW + h * 96 + d]
                                : KR[t * ROPE + (d - 32)];
        }
        __syncthreads();
        float s[8];
        #pragma unroll
        for (int cc = 0; cc < 8; cc++) {
            int c = tx * 8 + cc;
            float dot = 0.f;
            #pragma unroll
            for (int d = 0; d < 64; d++) dot = fmaf(qs[row][d], ks[c][d], dot);
            dot *= 0.125f;
            if (kt * 32 + c > qglob) dot = -1e30f;
            s[cc] = dot;
        }
        float mt = s[0];
        #pragma unroll
        for (int cc = 1; cc < 8; cc++) mt = fmaxf(mt, s[cc]);
        mt = fmaxf(mt, __shfl_xor_sync(0xffffffffu, mt, 1));
        mt = fmaxf(mt, __shfl_xor_sync(0xffffffffu, mt, 2));
        float mnew = fmaxf(m, mt);
        float corr = __expf(m - mnew);
        l *= corr;
        #pragma unroll
        for (int i = 0; i < 16; i++) acc[i] *= corr;
        float psum = 0.f;
        #pragma unroll
        for (int cc = 0; cc < 8; cc++) {
            float p = __expf(s[cc] - mnew);
            ps[row][tx * 8 + cc] = p;
            psum += p;
        }
        psum += __shfl_xor_sync(0xffffffffu, psum, 1);
        psum += __shfl_xor_sync(0xffffffffu, psum, 2);
        l += psum;
        m = mnew;
        __syncwarp();
        #pragma unroll 8
        for (int c = 0; c < 32; c++) {
            float pv = ps[row][c];
            #pragma unroll
            for (int i = 0; i < 16; i++)
                acc[i] = fmaf(pv, vs[c][tx * 16 + i], acc[i]);
        }
    }
    float inv = 1.f / l;
    #pragma unroll
    for (int i = 0; i < 16; i++)
        O[(size_t)(tok0 + row) * DMODEL + h * DHEAD + tx * 16 + i] = acc[i] * inv;
}

// ---------------- routing (sigmoid gates, top-2 of 8) ----------------
__global__ void zero_cnt_kernel(int* __restrict__ ecnt)
{
    if (threadIdx.x < NEXP) ecnt[threadIdx.x] = 0;
}

__global__ void routing_kernel(const float* __restrict__ h2,
                               const float* __restrict__ centroids,
                               const float* __restrict__ rbias,
                               int* __restrict__ ecnt, int* __restrict__ etok,
                               int* __restrict__ escat, float* __restrict__ ewt)
{
    int t = blockIdx.x;
    int tid = threadIdx.x;
    int warp = tid >> 5, lane = tid & 31;
    __shared__ float raw[NEXP];
    const float* hp = h2 + (size_t)t * DMODEL;
    const float* cp = centroids + (size_t)warp * DMODEL;
    float sum = 0.f;
    for (int d = lane; d < DMODEL; d += 32) sum += hp[d] * cp[d];
    #pragma unroll
    for (int o = 16; o; o >>= 1) sum += __shfl_xor_sync(~0u, sum, o);
    if (lane == 0) raw[warp] = sum;
    __syncthreads();
    if (tid == 0) {
        float bb[NEXP];
        #pragma unroll
        for (int e = 0; e < NEXP; e++) bb[e] = raw[e] + rbias[e];
        int i0 = 0;
        #pragma unroll
        for (int e = 1; e < NEXP; e++) if (bb[e] > bb[i0]) i0 = e;
        int i1 = -1;
        #pragma unroll
        for (int e = 0; e < NEXP; e++) {
            if (e == i0) continue;
            if (i1 < 0 || bb[e] > bb[i1]) i1 = e;
        }
        float w0 = 1.f / (1.f + expf(-raw[i0]));
        float w1 = 1.f / (1.f + expf(-raw[i1]));
        float s = w0 + w1 + 1e-9f;
        w0 /= s; w1 /= s;
        int p0 = atomicAdd(&ecnt[i0], 1);
        etok [i0 * NTOK + p0] = t;
        escat[i0 * NTOK + p0] = t;
        ewt  [i0 * NTOK + p0] = w0;
        int p1 = atomicAdd(&ecnt[i1], 1);
        etok [i1 * NTOK + p1] = t;
        escat[i1 * NTOK + p1] = NTOK + t;
        ewt  [i1 * NTOK + p1] = w1;
    }
}

__global__ void add5_kernel(float* __restrict__ out, const float* __restrict__ x2,
                            const float* __restrict__ a, const float* __restrict__ b,
                            const float* __restrict__ c, const float* __restrict__ d,
                            int n)
{
    int i = blockIdx.x * blockDim.x + threadIdx.x;
    if (i < n) out[i] = x2[i] + a[i] + b[i] + c[i] + d[i];
}

// ---------------- launcher ----------------
extern "C" void kernel_launch(void* const* d_in, const int* in_sizes, int n_in,
                              void* d_out, int out_size)
{
    const float* x        = (const float*)d_in[0];
    const float* ln1_w    = (const float*)d_in[1];
    const float* ln2_w    = (const float*)d_in[2];
    const float* W_dq     = (const float*)d_in[3];
    const float* W_uq     = (const float*)d_in[4];
    const float* q_ln_w   = (const float*)d_in[5];
    const float* q_ln_b   = (const float*)d_in[6];
    const float* W_dkv    = (const float*)d_in[7];
    const float* W_ukv    = (const float*)d_in[8];
    const float* kv_ln_w  = (const float*)d_in[9];
    const float* kv_ln_b  = (const float*)d_in[10];
    const float* W_o      = (const float*)d_in[11];
    const float* s_fc     = (const float*)d_in[12];
    const float* s_proj   = (const float*)d_in[13];
    const float* e_fc     = (const float*)d_in[14];
    const float* e_proj   = (const float*)d_in[15];
    const float* centroids= (const float*)d_in[16];
    const float* rbias    = (const float*)d_in[17];
    float* out = (float*)d_out;

    float *h1, *cqp, *cq, *q, *ckv, *kvl, *kv, *kr, *o, *x2, *h2, *ff, *ffe, *shp, *routed, *ewt;
    int *ecnt, *etok, *escat;
    cudaGetSymbolAddress((void**)&h1,  g_h1);
    cudaGetSymbolAddress((void**)&cqp, g_cqp);
    cudaGetSymbolAddress((void**)&cq,  g_cq);
    cudaGetSymbolAddress((void**)&q,   g_q);
    cudaGetSymbolAddress((void**)&ckv, g_ckv);
    cudaGetSymbolAddress((void**)&kvl, g_kvl);
    cudaGetSymbolAddress((void**)&kv,  g_kv);
    cudaGetSymbolAddress((void**)&kr,  g_kr);
    cudaGetSymbolAddress((void**)&o,   g_o);
    cudaGetSymbolAddress((void**)&x2,  g_x2);
    cudaGetSymbolAddress((void**)&h2,  g_h2);
    cudaGetSymbolAddress((void**)&ff,  g_ff);
    cudaGetSymbolAddress((void**)&ffe, g_ffe);
    cudaGetSymbolAddress((void**)&shp, g_shp);
    cudaGetSymbolAddress((void**)&routed, g_routed);
    cudaGetSymbolAddress((void**)&ecnt, g_ecnt);
    cudaGetSymbolAddress((void**)&etok, g_etok);
    cudaGetSymbolAddress((void**)&escat, g_escat);
    cudaGetSymbolAddress((void**)&ewt, g_ewt);

    const int TB = 256;
    #define NT(Nv) (((Nv)+TN-1)/TN)

    // 1. h1 = LN(x)
    ln_kernel<<<NTOK, TB>>>(x, DMODEL, DMODEL, ln1_w, nullptr, h1, DMODEL);

    // 2. fused: cq_pre = h1@W_dq  |  ckv = h1@W_dkv
    {
        GDesc d0{h1, W_dq,  cqp, NTOK, QP,   DMODEL, DMODEL, QP,   QP,   nullptr, 0, 0};
        GDesc d1{h1, W_dkv, ckv, NTOK, CKVW, DMODEL, DMODEL, CKVW, CKVW, nullptr, 0, 0};
        gemm2_kernel<false><<<dim3(NT(CKVW), NTOK/TM, 2), TB>>>(d0, d1);
    }
    // 3. LNs
    ln_kernel<<<NTOK, TB>>>(cqp, QP, QP, q_ln_w, q_ln_b, cq, QP);
    ln_kernel<<<NTOK, TB>>>(ckv, CKVW, KVP, kv_ln_w, kv_ln_b, kvl, KVP);

    // 4. fused: Q = cq@W_uq  |  KV = kvl@W_ukv
    {
        GDesc d0{cq,  W_uq,  q,  NTOK, DMODEL, QP,  QP,  DMODEL, DMODEL, nullptr, 0, 0};
        GDesc d1{kvl, W_ukv, kv, NTOK, UKVW,   KVP, KVP, UKVW,   UKVW,   nullptr, 0, 0};
        gemm2_kernel<false><<<dim3(NT(UKVW), NTOK/TM, 2), TB>>>(d0, d1);
    }
    // 5. rope
    rope_kernel<<<NTOK, 192>>>(q, ckv, kr);
    // 6. attention
    flash_kernel<<<dim3(SEQ/64, BATCH*NHEAD), TB>>>(q, kv, kr, o);
    // 7. x2 = o @ W_o^T + x
    gemm_kernel<true><<<dim3(NT(DMODEL), NTOK/TM), TB>>>(o, W_o, x2,
        NTOK, DMODEL, DMODEL, DMODEL, DMODEL, DMODEL, x, DMODEL, 0, 0);
    // 8. h2 = LN(x2)
    ln_kernel<<<NTOK, TB>>>(x2, DMODEL, DMODEL, ln2_w, nullptr, h2, DMODEL);

    // 9. routing
    zero_cnt_kernel<<<1, 32>>>(ecnt);
    routing_kernel<<<NTOK, TB>>>(h2, centroids, rbias, ecnt, etok, escat, ewt);

    // 10. fused shared fc (both experts)
    {
        GDesc d0{h2, s_fc,                          ff,                          NTOK, FFDIM, DMODEL, DMODEL, DMODEL, FFDIM, nullptr, 0, 1};
        GDesc d1{h2, s_fc + (size_t)FFDIM*DMODEL,   ff + (size_t)NTOK*FFDIM,     NTOK, FFDIM, DMODEL, DMODEL, DMODEL, FFDIM, nullptr, 0, 1};
        gemm2_kernel<true><<<dim3(NT(FFDIM), NTOK/TM, 2), TB>>>(d0, d1);
    }
    // 11. fused shared proj
    {
        GDesc d0{ff,                        s_proj,                        shp,                        NTOK, DMODEL, FFDIM, FFDIM, FFDIM, DMODEL, nullptr, 0, 0};
        GDesc d1{ff + (size_t)NTOK*FFDIM,   s_proj + (size_t)DMODEL*FFDIM, shp + (size_t)NTOK*DMODEL,  NTOK, DMODEL, FFDIM, FFDIM, FFDIM, DMODEL, nullptr, 0, 0};
        gemm2_kernel<true><<<dim3(NT(DMODEL), NTOK/TM, 2), TB>>>(d0, d1);
    }
    // 12. routed experts
    expert_fc_kernel<<<dim3(FFDIM/TN, NTOK/TM, NEXP), TB>>>(h2, e_fc, ffe, ecnt, etok, escat);
    expert_proj_kernel<<<dim3(DMODEL/TN, NTOK/TM, NEXP), TB>>>(ffe, e_proj, routed, ecnt, escat, ewt);
    // 13. out = x2 + shared0 + shared1 + routed0 + routed1
    add5_kernel<<<(NTOK*DMODEL + TB - 1)/TB, TB>>>(out, x2,
        shp, shp + (size_t)NTOK*DMODEL,
        routed, routed + (size_t)NTOK*DMODEL, NTOK*DMODEL);
}

// round 10
// speedup vs baseline: 3.3576x; 1.2975x over previous
#include <cuda_runtime.h>
#include <cuda_bf16.h>
#include <math.h>
#include <stdint.h>

// ---------------- problem constants ----------------
#define BATCH 4
#define SEQ   1024
#define NTOK  (BATCH*SEQ)      // 4096
#define DMODEL 768
#define NHEAD 12
#define DHEAD 64
#define NOPE  32
#define ROPE  32
#define QP    384
#define KVP   512
#define CKVW  (KVP+ROPE)       // 544
#define UKVW  1152             // D + H*NOPE
#define NEXP  8
#define TOPK  2
#define FFDIM 3072

// ---------------- scratch ----------------
__device__ float g_h1 [NTOK*DMODEL];
__device__ float g_cqp[NTOK*QP];
__device__ float g_cq [NTOK*QP];
__device__ float g_q  [NTOK*DMODEL];
__device__ float g_ckv[NTOK*CKVW];
__device__ float g_kvl[NTOK*KVP];
__device__ float g_kv [NTOK*UKVW];
__device__ float g_kr [NTOK*ROPE];
__device__ float g_o  [NTOK*DMODEL];
__device__ float g_x2 [NTOK*DMODEL];
__device__ float g_h2 [NTOK*DMODEL];
__device__ float g_ff [(size_t)2*NTOK*FFDIM];
__device__ float g_ffe[(size_t)2*NTOK*FFDIM];
__device__ float g_shp[2*NTOK*DMODEL];
__device__ float g_routed[2*NTOK*DMODEL];
__device__ int   g_ecnt[NEXP];
__device__ int   g_etok[NEXP*NTOK];
__device__ int   g_escat[NEXP*NTOK];
__device__ float g_ewt [NEXP*NTOK];

// ---------------- tf32 helpers ----------------
__device__ __forceinline__ float to_tf32(float x) {
    uint32_t u;
    asm("cvt.rna.tf32.f32 %0, %1;" : "=r"(u) : "f"(x));
    return __uint_as_float(u);
}

__device__ __forceinline__ void mma_tf32(float& c0, float& c1, float& c2, float& c3,
                                         float a0, float a1, float a2, float a3,
                                         float b0, float b1)
{
    asm volatile(
        "mma.sync.aligned.m16n8k8.row.col.f32.tf32.tf32.f32 "
        "{%0,%1,%2,%3}, {%4,%5,%6,%7}, {%8,%9}, {%0,%1,%2,%3};\n"
        : "+f"(c0), "+f"(c1), "+f"(c2), "+f"(c3)
        : "r"(__float_as_uint(a0)), "r"(__float_as_uint(a1)),
          "r"(__float_as_uint(a2)), "r"(__float_as_uint(a3)),
          "r"(__float_as_uint(b0)), "r"(__float_as_uint(b1)));
}

// ---------------- tf32 tensor-core GEMM ----------------
#define TM 128
#define TN 128
#define KS 16
#define KPAD 136

template<bool TRANSB>
__device__ __forceinline__ void gemm_body(
    const float* __restrict__ A, const float* __restrict__ B, float* __restrict__ C,
    int M, int N, int K, int lda, int ldb, int ldc,
    const int* __restrict__ gather, const int* __restrict__ scatter,
    const float* __restrict__ residual, int ldr,
    const float* __restrict__ rowScale,
    int doGelu, int accum, int rt, int ct)
{
    __shared__ float As[2][KS][KPAD];
    __shared__ float Bs[2][KS][KPAD];
    const int tid = threadIdx.x;
    const int lane = tid & 31, wid = tid >> 5;
    const int group = lane >> 2, tig = lane & 3;
    const int warp_m = wid & 3;
    const int warp_n = wid >> 2;
    const int row0 = rt * TM, col0 = ct * TN;

    const int alr = tid >> 1;
    const int akk = (tid & 1) * 4;
    const float* Arow = nullptr;
    {
        int gr = row0 + alr;
        if (gr < M) { int ar = gather ? gather[gr] : gr; Arow = A + (size_t)ar * lda; }
    }

    const float* Brow = nullptr;
    int bkr = 0, bc4 = 0;
    if (TRANSB) {
        int gc = col0 + alr;
        if (gc < N) Brow = B + (size_t)gc * ldb;
    } else {
        bkr = tid >> 5; bc4 = (tid & 31) * 4;
    }

    float4 aR0, aR1, bR0, bR1;
    auto loadG = [&](int k0) {
        aR0 = Arow ? *(const float4*)(Arow + k0 + akk)     : make_float4(0,0,0,0);
        aR1 = Arow ? *(const float4*)(Arow + k0 + akk + 8) : make_float4(0,0,0,0);
        if (TRANSB) {
            bR0 = Brow ? *(const float4*)(Brow + k0 + akk)     : make_float4(0,0,0,0);
            bR1 = Brow ? *(const float4*)(Brow + k0 + akk + 8) : make_float4(0,0,0,0);
        } else {
            int c = col0 + bc4;
            bR0 = (c < N) ? *(const float4*)(B + (size_t)(k0 + bkr) * ldb + c)     : make_float4(0,0,0,0);
            bR1 = (c < N) ? *(const float4*)(B + (size_t)(k0 + bkr + 8) * ldb + c) : make_float4(0,0,0,0);
        }
    };
    auto storeS = [&](int buf) {
        As[buf][akk+0][alr] = to_tf32(aR0.x);
        As[buf][akk+1][alr] = to_tf32(aR0.y);
        As[buf][akk+2][alr] = to_tf32(aR0.z);
        As[buf][akk+3][alr] = to_tf32(aR0.w);
        As[buf][akk+8][alr] = to_tf32(aR1.x);
        As[buf][akk+9][alr] = to_tf32(aR1.y);
        As[buf][akk+10][alr] = to_tf32(aR1.z);
        As[buf][akk+11][alr] = to_tf32(aR1.w);
        if (TRANSB) {
            Bs[buf][akk+0][alr] = to_tf32(bR0.x);
            Bs[buf][akk+1][alr] = to_tf32(bR0.y);
            Bs[buf][akk+2][alr] = to_tf32(bR0.z);
            Bs[buf][akk+3][alr] = to_tf32(bR0.w);
            Bs[buf][akk+8][alr] = to_tf32(bR1.x);
            Bs[buf][akk+9][alr] = to_tf32(bR1.y);
            Bs[buf][akk+10][alr] = to_tf32(bR1.z);
            Bs[buf][akk+11][alr] = to_tf32(bR1.w);
        } else {
            float4 t0 = make_float4(to_tf32(bR0.x), to_tf32(bR0.y), to_tf32(bR0.z), to_tf32(bR0.w));
            float4 t1 = make_float4(to_tf32(bR1.x), to_tf32(bR1.y), to_tf32(bR1.z), to_tf32(bR1.w));
            *(float4*)&Bs[buf][bkr][bc4]     = t0;
            *(float4*)&Bs[buf][bkr + 8][bc4] = t1;
        }
    };

    float acc[2][8][4];
    #pragma unroll
    for (int i = 0; i < 2; i++)
        #pragma unroll
        for (int j = 0; j < 8; j++)
            #pragma unroll
            for (int c = 0; c < 4; c++) acc[i][j][c] = 0.f;

    loadG(0);
    storeS(0);
    __syncthreads();

    const int m0 = warp_m * 32;
    const int n0 = warp_n * 64;
    int buf = 0;
    for (int k0 = 0; k0 < K; k0 += KS) {
        const bool more = (k0 + KS) < K;
        if (more) loadG(k0 + KS);
        #pragma unroll
        for (int half = 0; half < 2; half++) {
            const int kb = half * 8;
            float a[2][4];
            #pragma unroll
            for (int i = 0; i < 2; i++) {
                int mb = m0 + i * 16 + group;
                a[i][0] = As[buf][kb + tig][mb];
                a[i][1] = As[buf][kb + tig][mb + 8];
                a[i][2] = As[buf][kb + tig + 4][mb];
                a[i][3] = As[buf][kb + tig + 4][mb + 8];
            }
            #pragma unroll
            for (int j = 0; j < 8; j++) {
                int nb = n0 + j * 8 + group;
                float b0 = Bs[buf][kb + tig][nb];
                float b1 = Bs[buf][kb + tig + 4][nb];
                #pragma unroll
                for (int i = 0; i < 2; i++)
                    mma_tf32(acc[i][j][0], acc[i][j][1], acc[i][j][2], acc[i][j][3],
                             a[i][0], a[i][1], a[i][2], a[i][3], b0, b1);
            }
        }
        if (more) storeS(buf ^ 1);
        __syncthreads();
        buf ^= 1;
    }

    auto emit = [&](int r, int c, float v) {
        if (r >= M || c >= N) return;
        if (doGelu) v = 0.5f * v * (1.f + erff(v * 0.70710678118654752f));
        if (rowScale) v *= rowScale[r];
        if (residual) v += residual[(size_t)r * ldr + c];
        int orow = scatter ? scatter[r] : r;
        size_t off = (size_t)orow * ldc + c;
        if (accum) C[off] += v; else C[off] = v;
    };
    #pragma unroll
    for (int i = 0; i < 2; i++) {
        int rA = row0 + m0 + i * 16 + group;
        int rB = rA + 8;
        #pragma unroll
        for (int j = 0; j < 8; j++) {
            int c = col0 + n0 + j * 8 + 2 * tig;
            emit(rA, c,     acc[i][j][0]);
            emit(rA, c + 1, acc[i][j][1]);
            emit(rB, c,     acc[i][j][2]);
            emit(rB, c + 1, acc[i][j][3]);
        }
    }
}

struct GDesc {
    const float* A; const float* B; float* C;
    int M, N, K, lda, ldb, ldc;
    const float* residual; int ldr; int gelu;
};

template<bool TRANSB>
__global__ void __launch_bounds__(256, 2) gemm_kernel(
    const float* __restrict__ A, const float* __restrict__ B, float* __restrict__ C,
    int M, int N, int K, int lda, int ldb, int ldc,
    const float* __restrict__ residual, int ldr, int doGelu, int accum)
{
    gemm_body<TRANSB>(A, B, C, M, N, K, lda, ldb, ldc,
                      nullptr, nullptr, residual, ldr, nullptr,
                      doGelu, accum, blockIdx.y, blockIdx.x);
}

template<bool TRANSB>
__global__ void __launch_bounds__(256, 2) gemm2_kernel(GDesc d0, GDesc d1)
{
    const GDesc& d = (blockIdx.z == 0) ? d0 : d1;
    if ((int)blockIdx.x * TN >= d.N) return;
    if ((int)blockIdx.y * TM >= d.M) return;
    gemm_body<TRANSB>(d.A, d.B, d.C, d.M, d.N, d.K, d.lda, d.ldb, d.ldc,
                      nullptr, nullptr, d.residual, d.ldr, nullptr,
                      d.gelu, 0, blockIdx.y, blockIdx.x);
}

// ---------------- expert (ragged) GEMMs ----------------
__global__ void __launch_bounds__(256, 2) expert_fc_kernel(
    const float* __restrict__ h2, const float* __restrict__ e_fc,
    float* __restrict__ ffe, const int* __restrict__ ecnt,
    const int* __restrict__ etok, const int* __restrict__ escat)
{
    int e = blockIdx.z;
    int cnt = ecnt[e];
    if ((int)blockIdx.y * TM >= cnt) return;
    gemm_body<true>(h2, e_fc + (size_t)e * FFDIM * DMODEL,
                    ffe,
                    cnt, FFDIM, DMODEL, DMODEL, DMODEL, FFDIM,
                    etok + e * NTOK, escat + e * NTOK, nullptr, 0, nullptr,
                    1, 0, blockIdx.y, blockIdx.x);
}

__global__ void __launch_bounds__(256, 2) expert_proj_kernel(
    const float* __restrict__ ffe, const float* __restrict__ e_proj,
    float* __restrict__ routed, const int* __restrict__ ecnt,
    const int* __restrict__ escat, const float* __restrict__ ewt)
{
    int e = blockIdx.z;
    int cnt = ecnt[e];
    if ((int)blockIdx.y * TM >= cnt) return;
    gemm_body<true>(ffe,
                    e_proj + (size_t)e * DMODEL * FFDIM,
                    routed,
                    cnt, DMODEL, FFDIM, FFDIM, FFDIM, DMODEL,
                    escat + e * NTOK, escat + e * NTOK, nullptr, 0, ewt + e * NTOK,
                    0, 0, blockIdx.y, blockIdx.x);
}

// ---------------- layernorm ----------------
__global__ void ln_kernel(const float* __restrict__ in, int ldin, int W,
                          const float* __restrict__ w, const float* __restrict__ b,
                          float* __restrict__ out, int ldout)
{
    int t = blockIdx.x;
    int tid = threadIdx.x;
    const float* x = in + (size_t)t * ldin;
    float s = 0.f, sq = 0.f;
    for (int c = tid; c < W; c += blockDim.x) { float v = x[c]; s += v; sq += v*v; }
    __shared__ float rs[32], rq[32];
    #pragma unroll
    for (int o = 16; o; o >>= 1) { s += __shfl_xor_sync(~0u, s, o); sq += __shfl_xor_sync(~0u, sq, o); }
    int warp = tid >> 5, lane = tid & 31;
    if (lane == 0) { rs[warp] = s; rq[warp] = sq; }
    __syncthreads();
    int nw = blockDim.x >> 5;
    if (warp == 0) {
        s  = lane < nw ? rs[lane] : 0.f;
        sq = lane < nw ? rq[lane] : 0.f;
        #pragma unroll
        for (int o = 16; o; o >>= 1) { s += __shfl_xor_sync(~0u, s, o); sq += __shfl_xor_sync(~0u, sq, o); }
        if (lane == 0) { rs[0] = s; rq[0] = sq; }
    }
    __syncthreads();
    float mean = rs[0] / W;
    float var  = rq[0] / W - mean * mean;
    float rstd = rsqrtf(var + 1e-5f);
    float* y = out + (size_t)t * ldout;
    for (int c = tid; c < W; c += blockDim.x) {
        float v = (x[c] - mean) * rstd * w[c];
        if (b) v += b[c];
        y[c] = v;
    }
}

// ---------------- rope ----------------
__global__ void rope_kernel(float* __restrict__ q, const float* __restrict__ ckv,
                            float* __restrict__ kr)
{
    int t = blockIdx.x;
    int s = t & (SEQ - 1);
    int tid = threadIdx.x;
    int h = tid >> 4, j = tid & 15;
    float freq = powf(10000.f, -(float)j / 32.f);
    float ang = (float)s * freq;
    float c = cosf(ang), si = sinf(ang);
    float* qp = q + (size_t)t * DMODEL + h * DHEAD + NOPE;
    float a = qp[j], bb = qp[j + 16];
    qp[j]      = a * c - bb * si;
    qp[j + 16] = bb * c + a * si;
    if (h == 0) {
        const float* kp = ckv + (size_t)t * CKVW + KVP;
        float a2 = kp[j], b2 = kp[j + 16];
        kr[t * ROPE + j]      = a2 * c - b2 * si;
        kr[t * ROPE + j + 16] = b2 * c + a2 * si;
    }
}

// ---------------- tensor-core flash attention ----------------
// q-tile 128, k-tile 32, 256 threads (8 warps, each 16 q-rows x all keys).
// S = Q K^T and O += P V via mma.m16n8k8.tf32. Warp-local online softmax.
#define KSP 40    // ks pad: [dim][key], conflict-free B reads
#define VSP 72    // vs pad: [key][dim]
#define PSP 132   // ps/qs pad: [k][m]

__global__ void __launch_bounds__(256, 2) flash_mma_kernel(
    const float* __restrict__ Q, const float* __restrict__ KV,
    const float* __restrict__ KR, float* __restrict__ O)
{
    __shared__ float sbuf[64*KSP + 32*VSP + 32*PSP];  // 9088 floats; qs aliases front
    float* qs = sbuf;                      // [64][PSP] transient (8448 floats)
    float* ks = sbuf;                      // [64][KSP]
    float* vs = sbuf + 64*KSP;             // [32][VSP]
    float* ps = sbuf + 64*KSP + 32*VSP;    // [32][PSP]

    const int qt = (int)(gridDim.x - 1 - blockIdx.x);   // long blocks first
    const int bh = blockIdx.y;
    const int b = bh / NHEAD, h = bh % NHEAD;
    const int tid = threadIdx.x;
    const int lane = tid & 31, wid = tid >> 5;
    const int group = lane >> 2, tig = lane & 3;
    const int m0 = wid * 16;
    const int tok0 = b * SEQ + qt * 128;

    // ---- load Q (transposed, tf32) and hoist fragments ----
    for (int i = tid; i < 128 * 64; i += 256) {
        int r = i >> 6, d = i & 63;
        qs[d * PSP + r] = to_tf32(Q[(size_t)(tok0 + r) * DMODEL + h * DHEAD + d]);
    }
    __syncthreads();
    float qa[8][4];
    #pragma unroll
    for (int k8 = 0; k8 < 8; k8++) {
        int kb = k8 * 8;
        qa[k8][0] = qs[(kb + tig) * PSP + m0 + group];
        qa[k8][1] = qs[(kb + tig) * PSP + m0 + group + 8];
        qa[k8][2] = qs[(kb + tig + 4) * PSP + m0 + group];
        qa[k8][3] = qs[(kb + tig + 4) * PSP + m0 + group + 8];
    }
    __syncthreads();   // before overwriting qs region with ks

    float oacc[8][4];
    #pragma unroll
    for (int j = 0; j < 8; j++)
        #pragma unroll
        for (int c = 0; c < 4; c++) oacc[j][c] = 0.f;
    float mrow[2] = {-1e30f, -1e30f};
    float lrow[2] = {0.f, 0.f};

    const int qgA = qt * 128 + m0 + group;      // seq-local q index, row A
    const int qgB = qgA + 8;
    const int nkt = 4 * qt + 4;

    for (int kt = 0; kt < nkt; kt++) {
        const int key0 = kt * 32;
        __syncthreads();
        // load K tile [dim 64][key 32] (tf32) — nope part + shared rope part
        for (int i = tid; i < 32 * 64; i += 256) {
            int d = i & 63, c = i >> 6;
            int t = b * SEQ + key0 + c;
            float v = (d < 32) ? KV[(size_t)t * UKVW + h * 96 + d]
                               : KR[t * ROPE + (d - 32)];
            ks[d * KSP + c] = to_tf32(v);
        }
        // load V tile [key 32][dim 64] (tf32)
        for (int i = tid; i < 32 * 16; i += 256) {
            int c = i >> 4, d4 = (i & 15) * 4;
            int t = b * SEQ + key0 + c;
            float4 v = *(const float4*)(KV + (size_t)t * UKVW + h * 96 + 32 + d4);
            vs[c * VSP + d4 + 0] = to_tf32(v.x);
            vs[c * VSP + d4 + 1] = to_tf32(v.y);
            vs[c * VSP + d4 + 2] = to_tf32(v.z);
            vs[c * VSP + d4 + 3] = to_tf32(v.w);
        }
        __syncthreads();

        // ---- S = Q K^T (128x32 per block; warp: 16x32 = 4 n-tiles) ----
        float sacc[4][4];
        #pragma unroll
        for (int j = 0; j < 4; j++)
            #pragma unroll
            for (int c = 0; c < 4; c++) sacc[j][c] = 0.f;
        #pragma unroll
        for (int k8 = 0; k8 < 8; k8++) {
            int kb = k8 * 8;
            #pragma unroll
            for (int j = 0; j < 4; j++) {
                int nb = j * 8 + group;
                float b0 = ks[(kb + tig) * KSP + nb];
                float b1 = ks[(kb + tig + 4) * KSP + nb];
                mma_tf32(sacc[j][0], sacc[j][1], sacc[j][2], sacc[j][3],
                         qa[k8][0], qa[k8][1], qa[k8][2], qa[k8][3], b0, b1);
            }
        }

        // ---- scale + causal mask ----
        const bool fullTile = (key0 + 31 <= qgA);   // all warp rows >= qgA
        #pragma unroll
        for (int j = 0; j < 4; j++) {
            int c0 = key0 + j * 8 + 2 * tig;
            #pragma unroll
            for (int cc = 0; cc < 4; cc++) sacc[j][cc] *= 0.125f;
            if (!fullTile) {
                if (c0     > qgA) sacc[j][0] = -1e30f;
                if (c0 + 1 > qgA) sacc[j][1] = -1e30f;
                if (c0     > qgB) sacc[j][2] = -1e30f;
                if (c0 + 1 > qgB) sacc[j][3] = -1e30f;
            }
        }

        // ---- online softmax (rows A: c0,c1 ; rows B: c2,c3) ----
        float mtA = -1e30f, mtB = -1e30f;
        #pragma unroll
        for (int j = 0; j < 4; j++) {
            mtA = fmaxf(mtA, fmaxf(sacc[j][0], sacc[j][1]));
            mtB = fmaxf(mtB, fmaxf(sacc[j][2], sacc[j][3]));
        }
        mtA = fmaxf(mtA, __shfl_xor_sync(~0u, mtA, 1));
        mtA = fmaxf(mtA, __shfl_xor_sync(~0u, mtA, 2));
        mtB = fmaxf(mtB, __shfl_xor_sync(~0u, mtB, 1));
        mtB = fmaxf(mtB, __shfl_xor_sync(~0u, mtB, 2));
        float mnA = fmaxf(mrow[0], mtA), mnB = fmaxf(mrow[1], mtB);
        float crA = __expf(mrow[0] - mnA), crB = __expf(mrow[1] - mnB);
        #pragma unroll
        for (int j = 0; j < 8; j++) {
            oacc[j][0] *= crA; oacc[j][1] *= crA;
            oacc[j][2] *= crB; oacc[j][3] *= crB;
        }
        float psA = 0.f, psB = 0.f;
        #pragma unroll
        for (int j = 0; j < 4; j++) {
            float p0 = __expf(sacc[j][0] - mnA);
            float p1 = __expf(sacc[j][1] - mnA);
            float p2 = __expf(sacc[j][2] - mnB);
            float p3 = __expf(sacc[j][3] - mnB);
            psA += p0 + p1; psB += p2 + p3;
            int col = j * 8 + 2 * tig;
            ps[col * PSP + m0 + group]           = to_tf32(p0);
            ps[(col + 1) * PSP + m0 + group]     = to_tf32(p1);
            ps[col * PSP + m0 + group + 8]       = to_tf32(p2);
            ps[(col + 1) * PSP + m0 + group + 8] = to_tf32(p3);
        }
        psA += __shfl_xor_sync(~0u, psA, 1);
        psA += __shfl_xor_sync(~0u, psA, 2);
        psB += __shfl_xor_sync(~0u, psB, 1);
        psB += __shfl_xor_sync(~0u, psB, 2);
        lrow[0] = lrow[0] * crA + psA;
        lrow[1] = lrow[1] * crB + psB;
        mrow[0] = mnA; mrow[1] = mnB;
        __syncwarp();   // ps region is warp-private: warp sync suffices

        // ---- O += P V  (warp: 16 rows x 64 dims = 8 n-tiles, k = 32 keys) ----
        #pragma unroll
        for (int kq = 0; kq < 4; kq++) {
            int kb = kq * 8;
            float a0 = ps[(kb + tig) * PSP + m0 + group];
            float a1 = ps[(kb + tig) * PSP + m0 + group + 8];
            float a2 = ps[(kb + tig + 4) * PSP + m0 + group];
            float a3 = ps[(kb + tig + 4) * PSP + m0 + group + 8];
            #pragma unroll
            for (int j = 0; j < 8; j++) {
                int nb = j * 8 + group;
                float b0 = vs[(kb + tig) * VSP + nb];
                float b1 = vs[(kb + tig + 4) * VSP + nb];
                mma_tf32(oacc[j][0], oacc[j][1], oacc[j][2], oacc[j][3],
                         a0, a1, a2, a3, b0, b1);
            }
        }
    }

    // ---- write O ----
    float invA = 1.f / lrow[0], invB = 1.f / lrow[1];
    int rowA = tok0 + m0 + group, rowB = rowA + 8;
    #pragma unroll
    for (int j = 0; j < 8; j++) {
        int c = j * 8 + 2 * tig;
        size_t offA = (size_t)rowA * DMODEL + h * DHEAD + c;
        size_t offB = (size_t)rowB * DMODEL + h * DHEAD + c;
        O[offA]     = oacc[j][0] * invA;
        O[offA + 1] = oacc[j][1] * invA;
        O[offB]     = oacc[j][2] * invB;
        O[offB + 1] = oacc[j][3] * invB;
    }
}

// ---------------- routing (sigmoid gates, top-2 of 8) ----------------
__global__ void zero_cnt_kernel(int* __restrict__ ecnt)
{
    if (threadIdx.x < NEXP) ecnt[threadIdx.x] = 0;
}

__global__ void routing_kernel(const float* __restrict__ h2,
                               const float* __restrict__ centroids,
                               const float* __restrict__ rbias,
                               int* __restrict__ ecnt, int* __restrict__ etok,
                               int* __restrict__ escat, float* __restrict__ ewt)
{
    int t = blockIdx.x;
    int tid = threadIdx.x;
    int warp = tid >> 5, lane = tid & 31;
    __shared__ float raw[NEXP];
    const float* hp = h2 + (size_t)t * DMODEL;
    const float* cp = centroids + (size_t)warp * DMODEL;
    float sum = 0.f;
    for (int d = lane; d < DMODEL; d += 32) sum += hp[d] * cp[d];
    #pragma unroll
    for (int o = 16; o; o >>= 1) sum += __shfl_xor_sync(~0u, sum, o);
    if (lane == 0) raw[warp] = sum;
    __syncthreads();
    if (tid == 0) {
        float bb[NEXP];
        #pragma unroll
        for (int e = 0; e < NEXP; e++) bb[e] = raw[e] + rbias[e];
        int i0 = 0;
        #pragma unroll
        for (int e = 1; e < NEXP; e++) if (bb[e] > bb[i0]) i0 = e;
        int i1 = -1;
        #pragma unroll
        for (int e = 0; e < NEXP; e++) {
            if (e == i0) continue;
            if (i1 < 0 || bb[e] > bb[i1]) i1 = e;
        }
        float w0 = 1.f / (1.f + expf(-raw[i0]));
        float w1 = 1.f / (1.f + expf(-raw[i1]));
        float s = w0 + w1 + 1e-9f;
        w0 /= s; w1 /= s;
        int p0 = atomicAdd(&ecnt[i0], 1);
        etok [i0 * NTOK + p0] = t;
        escat[i0 * NTOK + p0] = t;
        ewt  [i0 * NTOK + p0] = w0;
        int p1 = atomicAdd(&ecnt[i1], 1);
        etok [i1 * NTOK + p1] = t;
        escat[i1 * NTOK + p1] = NTOK + t;
        ewt  [i1 * NTOK + p1] = w1;
    }
}

__global__ void add5_kernel(float* __restrict__ out, const float* __restrict__ x2,
                            const float* __restrict__ a, const float* __restrict__ b,
                            const float* __restrict__ c, const float* __restrict__ d,
                            int n)
{
    int i = blockIdx.x * blockDim.x + threadIdx.x;
    if (i < n) out[i] = x2[i] + a[i] + b[i] + c[i] + d[i];
}

// ---------------- launcher ----------------
extern "C" void kernel_launch(void* const* d_in, const int* in_sizes, int n_in,
                              void* d_out, int out_size)
{
    const float* x        = (const float*)d_in[0];
    const float* ln1_w    = (const float*)d_in[1];
    const float* ln2_w    = (const float*)d_in[2];
    const float* W_dq     = (const float*)d_in[3];
    const float* W_uq     = (const float*)d_in[4];
    const float* q_ln_w   = (const float*)d_in[5];
    const float* q_ln_b   = (const float*)d_in[6];
    const float* W_dkv    = (const float*)d_in[7];
    const float* W_ukv    = (const float*)d_in[8];
    const float* kv_ln_w  = (const float*)d_in[9];
    const float* kv_ln_b  = (const float*)d_in[10];
    const float* W_o      = (const float*)d_in[11];
    const float* s_fc     = (const float*)d_in[12];
    const float* s_proj   = (const float*)d_in[13];
    const float* e_fc     = (const float*)d_in[14];
    const float* e_proj   = (const float*)d_in[15];
    const float* centroids= (const float*)d_in[16];
    const float* rbias    = (const float*)d_in[17];
    float* out = (float*)d_out;

    float *h1, *cqp, *cq, *q, *ckv, *kvl, *kv, *kr, *o, *x2, *h2, *ff, *ffe, *shp, *routed, *ewt;
    int *ecnt, *etok, *escat;
    cudaGetSymbolAddress((void**)&h1,  g_h1);
    cudaGetSymbolAddress((void**)&cqp, g_cqp);
    cudaGetSymbolAddress((void**)&cq,  g_cq);
    cudaGetSymbolAddress((void**)&q,   g_q);
    cudaGetSymbolAddress((void**)&ckv, g_ckv);
    cudaGetSymbolAddress((void**)&kvl, g_kvl);
    cudaGetSymbolAddress((void**)&kv,  g_kv);
    cudaGetSymbolAddress((void**)&kr,  g_kr);
    cudaGetSymbolAddress((void**)&o,   g_o);
    cudaGetSymbolAddress((void**)&x2,  g_x2);
    cudaGetSymbolAddress((void**)&h2,  g_h2);
    cudaGetSymbolAddress((void**)&ff,  g_ff);
    cudaGetSymbolAddress((void**)&ffe, g_ffe);
    cudaGetSymbolAddress((void**)&shp, g_shp);
    cudaGetSymbolAddress((void**)&routed, g_routed);
    cudaGetSymbolAddress((void**)&ecnt, g_ecnt);
    cudaGetSymbolAddress((void**)&etok, g_etok);
    cudaGetSymbolAddress((void**)&escat, g_escat);
    cudaGetSymbolAddress((void**)&ewt, g_ewt);

    const int TB = 256;
    #define NT(Nv) (((Nv)+TN-1)/TN)

    // 1. h1 = LN(x)
    ln_kernel<<<NTOK, TB>>>(x, DMODEL, DMODEL, ln1_w, nullptr, h1, DMODEL);

    // 2. fused: cq_pre = h1@W_dq  |  ckv = h1@W_dkv
    {
        GDesc d0{h1, W_dq,  cqp, NTOK, QP,   DMODEL, DMODEL, QP,   QP,   nullptr, 0, 0};
        GDesc d1{h1, W_dkv, ckv, NTOK, CKVW, DMODEL, DMODEL, CKVW, CKVW, nullptr, 0, 0};
        gemm2_kernel<false><<<dim3(NT(CKVW), NTOK/TM, 2), TB>>>(d0, d1);
    }
    // 3. LNs
    ln_kernel<<<NTOK, TB>>>(cqp, QP, QP, q_ln_w, q_ln_b, cq, QP);
    ln_kernel<<<NTOK, TB>>>(ckv, CKVW, KVP, kv_ln_w, kv_ln_b, kvl, KVP);

    // 4. fused: Q = cq@W_uq  |  KV = kvl@W_ukv
    {
        GDesc d0{cq,  W_uq,  q,  NTOK, DMODEL, QP,  QP,  DMODEL, DMODEL, nullptr, 0, 0};
        GDesc d1{kvl, W_ukv, kv, NTOK, UKVW,   KVP, KVP, UKVW,   UKVW,   nullptr, 0, 0};
        gemm2_kernel<false><<<dim3(NT(UKVW), NTOK/TM, 2), TB>>>(d0, d1);
    }
    // 5. rope
    rope_kernel<<<NTOK, 192>>>(q, ckv, kr);
    // 6. tensor-core flash attention
    flash_mma_kernel<<<dim3(SEQ/128, BATCH*NHEAD), TB>>>(q, kv, kr, o);
    // 7. x2 = o @ W_o^T + x
    gemm_kernel<true><<<dim3(NT(DMODEL), NTOK/TM), TB>>>(o, W_o, x2,
        NTOK, DMODEL, DMODEL, DMODEL, DMODEL, DMODEL, x, DMODEL, 0, 0);
    // 8. h2 = LN(x2)
    ln_kernel<<<NTOK, TB>>>(x2, DMODEL, DMODEL, ln2_w, nullptr, h2, DMODEL);

    // 9. routing
    zero_cnt_kernel<<<1, 32>>>(ecnt);
    routing_kernel<<<NTOK, TB>>>(h2, centroids, rbias, ecnt, etok, escat, ewt);

    // 10. fused shared fc (both experts)
    {
        GDesc d0{h2, s_fc,                          ff,                          NTOK, FFDIM, DMODEL, DMODEL, DMODEL, FFDIM, nullptr, 0, 1};
        GDesc d1{h2, s_fc + (size_t)FFDIM*DMODEL,   ff + (size_t)NTOK*FFDIM,     NTOK, FFDIM, DMODEL, DMODEL, DMODEL, FFDIM, nullptr, 0, 1};
        gemm2_kernel<true><<<dim3(NT(FFDIM), NTOK/TM, 2), TB>>>(d0, d1);
    }
    // 11. fused shared proj
    {
        GDesc d0{ff,                        s_proj,                        shp,                        NTOK, DMODEL, FFDIM, FFDIM, FFDIM, DMODEL, nullptr, 0, 0};
        GDesc d1{ff + (size_t)NTOK*FFDIM,   s_proj + (size_t)DMODEL*FFDIM, shp + (size_t)NTOK*DMODEL,  NTOK, DMODEL, FFDIM, FFDIM, FFDIM, DMODEL, nullptr, 0, 0};
        gemm2_kernel<true><<<dim3(NT(DMODEL), NTOK/TM, 2), TB>>>(d0, d1);
    }
    // 12. routed experts
    expert_fc_kernel<<<dim3(FFDIM/TN, NTOK/TM, NEXP), TB>>>(h2, e_fc, ffe, ecnt, etok, escat);
    expert_proj_kernel<<<dim3(DMODEL/TN, NTOK/TM, NEXP), TB>>>(ffe, e_proj, routed, ecnt, escat, ewt);
    // 13. out = x2 + shared0 + shared1 + routed0 + routed1
    add5_kernel<<<(NTOK*DMODEL + TB - 1)/TB, TB>>>(out, x2,
        shp, shp + (size_t)NTOK*DMODEL,
        routed, routed + (size_t)NTOK*DMODEL, NTOK*DMODEL);
}

// round 11
// speedup vs baseline: 4.2949x; 1.2792x over previous
#include <cuda_runtime.h>
#include <cuda_bf16.h>
#include <math.h>
#include <stdint.h>

// ---------------- problem constants ----------------
#define BATCH 4
#define SEQ   1024
#define NTOK  (BATCH*SEQ)      // 4096
#define DMODEL 768
#define NHEAD 12
#define DHEAD 64
#define NOPE  32
#define ROPE  32
#define QP    384
#define KVP   512
#define CKVW  (KVP+ROPE)       // 544
#define UKVW  1152             // D + H*NOPE
#define NEXP  8
#define TOPK  2
#define FFDIM 3072

// ---------------- scratch ----------------
__device__ float g_h1 [NTOK*DMODEL];
__device__ float g_cqp[NTOK*QP];
__device__ float g_cq [NTOK*QP];
__device__ float g_q  [NTOK*DMODEL];
__device__ float g_ckv[NTOK*CKVW];
__device__ float g_kvl[NTOK*KVP];
__device__ float g_kv [NTOK*UKVW];
__device__ float g_kr [NTOK*ROPE];
__device__ float g_o  [NTOK*DMODEL];
__device__ float g_x2 [NTOK*DMODEL];
__device__ float g_h2 [NTOK*DMODEL];
__device__ float g_ff [(size_t)2*NTOK*FFDIM];
__device__ float g_ffe[(size_t)2*NTOK*FFDIM];
__device__ float g_shp[2*NTOK*DMODEL];
__device__ float g_routed[2*NTOK*DMODEL];
__device__ int   g_ecnt[NEXP];
__device__ int   g_etok[NEXP*NTOK];
__device__ int   g_escat[NEXP*NTOK];
__device__ float g_ewt [NEXP*NTOK];

// ---------------- mma helper (raw fp32 regs; HMMA uses tf32 field) ----------------
__device__ __forceinline__ void mma_tf32(float& c0, float& c1, float& c2, float& c3,
                                         float a0, float a1, float a2, float a3,
                                         float b0, float b1)
{
    asm volatile(
        "mma.sync.aligned.m16n8k8.row.col.f32.tf32.tf32.f32 "
        "{%0,%1,%2,%3}, {%4,%5,%6,%7}, {%8,%9}, {%0,%1,%2,%3};\n"
        : "+f"(c0), "+f"(c1), "+f"(c2), "+f"(c3)
        : "r"(__float_as_uint(a0)), "r"(__float_as_uint(a1)),
          "r"(__float_as_uint(a2)), "r"(__float_as_uint(a3)),
          "r"(__float_as_uint(b0)), "r"(__float_as_uint(b1)));
}

__device__ __forceinline__ void cp16(uint32_t dst, const void* src, bool pred)
{
    asm volatile("cp.async.ca.shared.global [%0], [%1], 16, %2;\n"
                 :: "r"(dst), "l"(src), "r"(pred ? 16 : 0));
}
__device__ __forceinline__ void cp_commit() {
    asm volatile("cp.async.commit_group;\n" ::: "memory");
}
__device__ __forceinline__ void cp_wait1() {
    asm volatile("cp.async.wait_group 1;\n" ::: "memory");
}
__device__ __forceinline__ void cp_wait0() {
    asm volatile("cp.async.wait_group 0;\n" ::: "memory");
}

// ---------------- tf32 tensor-core GEMM (cp.async pipelined) ----------------
#define TM 128
#define TN 128
#define KS 16
#define APAD 20     // [row][APAD] row-major; group*20+tig is a bank permutation
#define BPADN 136   // non-trans [k][BPADN]

template<bool TRANSB>
__device__ __forceinline__ void gemm_body(
    const float* __restrict__ A, const float* __restrict__ B, float* __restrict__ C,
    int M, int N, int K, int lda, int ldb, int ldc,
    const int* __restrict__ gather, const int* __restrict__ scatter,
    const float* __restrict__ residual, int ldr,
    const float* __restrict__ rowScale,
    int doGelu, int accum, int rt, int ct)
{
    __shared__ float As[2][TM][APAD];
    __shared__ float Bs[2][TRANSB ? TN : KS][TRANSB ? APAD : BPADN];

    const int tid = threadIdx.x;
    const int lane = tid & 31, wid = tid >> 5;
    const int group = lane >> 2, tig = lane & 3;
    const int warp_m = wid & 3;
    const int warp_n = wid >> 2;
    const int row0 = rt * TM, col0 = ct * TN;

    const uint32_t sA = (uint32_t)__cvta_generic_to_shared(&As[0][0][0]);
    const uint32_t sB = (uint32_t)__cvta_generic_to_shared(&Bs[0][0][0]);
    constexpr uint32_t ASTAGE = TM * APAD * 4;
    constexpr uint32_t BSTAGE = (TRANSB ? TN * APAD : KS * BPADN) * 4;

    // ---- A loader: rows ar0, ar0+64; k-chunk akc ----
    const int ar0 = tid >> 2;
    const int akc = (tid & 3) * 4;
    const float *Aptr0, *Aptr1; bool av0, av1;
    {
        int gr0 = row0 + ar0, gr1 = gr0 + 64;
        av0 = gr0 < M; av1 = gr1 < M;
        int i0 = av0 ? (gather ? gather[gr0] : gr0) : 0;
        int i1 = av1 ? (gather ? gather[gr1] : gr1) : 0;
        Aptr0 = A + (size_t)i0 * lda + akc;
        Aptr1 = A + (size_t)i1 * lda + akc;
    }
    const uint32_t adst0 = sA + (uint32_t)((ar0 * APAD + akc) * 4);
    const uint32_t adst1 = sA + (uint32_t)(((ar0 + 64) * APAD + akc) * 4);

    // ---- B loader ----
    const float *Bptr0, *Bptr1; bool bvld;
    uint32_t bdst0, bdst1;
    if (TRANSB) {
        int gn0 = col0 + ar0, gn1 = gn0 + 64;
        bool v0 = gn0 < N, v1 = gn1 < N;
        Bptr0 = B + (size_t)(v0 ? gn0 : 0) * ldb + akc;
        Bptr1 = B + (size_t)(v1 ? gn1 : 0) * ldb + akc;
        bdst0 = sB + (uint32_t)((ar0 * APAD + akc) * 4);
        bdst1 = sB + (uint32_t)(((ar0 + 64) * APAD + akc) * 4);
        bvld = v0;   // v1 handled via separate flag below
        // store both validities in one trick: reuse av-style
        // (we pass per-copy preds directly at issue time)
        (void)bvld;
    } else {
        int kr0 = tid >> 5;                    // 0..7
        int nc = (tid & 31) * 4;               // 0..124
        int gc = col0 + nc;
        bool v = gc < N;                       // N multiple of 32 -> chunk aligned
        Bptr0 = B + (size_t)kr0 * ldb + (v ? gc : 0);
        Bptr1 = B + (size_t)(kr0 + 8) * ldb + (v ? gc : 0);
        bdst0 = sB + (uint32_t)((kr0 * BPADN + nc) * 4);
        bdst1 = sB + (uint32_t)(((kr0 + 8) * BPADN + nc) * 4);
        bvld = v;
    }
    bool btv0 = true, btv1 = true;
    if (TRANSB) { btv0 = (col0 + ar0) < N; btv1 = (col0 + ar0 + 64) < N; }

    auto issue = [&](int stage, int k0) {
        uint32_t ao = stage ? ASTAGE : 0;
        uint32_t bo = stage ? BSTAGE : 0;
        cp16(adst0 + ao, Aptr0 + k0, av0);
        cp16(adst1 + ao, Aptr1 + k0, av1);
        if (TRANSB) {
            cp16(bdst0 + bo, Bptr0 + k0, btv0);
            cp16(bdst1 + bo, Bptr1 + k0, btv1);
        } else {
            cp16(bdst0 + bo, Bptr0 + (size_t)k0 * ldb, bvld);
            cp16(bdst1 + bo, Bptr1 + (size_t)k0 * ldb, bvld);
        }
        cp_commit();
    };

    float acc[2][8][4];
    #pragma unroll
    for (int i = 0; i < 2; i++)
        #pragma unroll
        for (int j = 0; j < 8; j++)
            #pragma unroll
            for (int c = 0; c < 4; c++) acc[i][j][c] = 0.f;

    issue(0, 0);

    const int m0 = warp_m * 32;
    const int n0 = warp_n * 64;
    int buf = 0;
    for (int k0 = 0; k0 < K; k0 += KS) {
        const bool more = (k0 + KS) < K;
        if (more) issue(buf ^ 1, k0 + KS);
        if (more) cp_wait1(); else cp_wait0();
        __syncthreads();

        #pragma unroll
        for (int half = 0; half < 2; half++) {
            const int kb = half * 8;
            float a[2][4];
            #pragma unroll
            for (int i = 0; i < 2; i++) {
                int mb = m0 + i * 16 + group;
                a[i][0] = As[buf][mb][kb + tig];
                a[i][1] = As[buf][mb + 8][kb + tig];
                a[i][2] = As[buf][mb][kb + tig + 4];
                a[i][3] = As[buf][mb + 8][kb + tig + 4];
            }
            #pragma unroll
            for (int j = 0; j < 8; j++) {
                int nb = n0 + j * 8 + group;
                float b0, b1;
                if (TRANSB) {
                    b0 = Bs[buf][nb][kb + tig];
                    b1 = Bs[buf][nb][kb + tig + 4];
                } else {
                    b0 = Bs[buf][kb + tig][nb];
                    b1 = Bs[buf][kb + tig + 4][nb];
                }
                #pragma unroll
                for (int i = 0; i < 2; i++)
                    mma_tf32(acc[i][j][0], acc[i][j][1], acc[i][j][2], acc[i][j][3],
                             a[i][0], a[i][1], a[i][2], a[i][3], b0, b1);
            }
        }
        __syncthreads();
        buf ^= 1;
    }

    auto emit = [&](int r, int c, float v) {
        if (r >= M || c >= N) return;
        if (doGelu) v = 0.5f * v * (1.f + erff(v * 0.70710678118654752f));
        if (rowScale) v *= rowScale[r];
        if (residual) v += residual[(size_t)r * ldr + c];
        int orow = scatter ? scatter[r] : r;
        size_t off = (size_t)orow * ldc + c;
        if (accum) C[off] += v; else C[off] = v;
    };
    #pragma unroll
    for (int i = 0; i < 2; i++) {
        int rA = row0 + m0 + i * 16 + group;
        int rB = rA + 8;
        #pragma unroll
        for (int j = 0; j < 8; j++) {
            int c = col0 + n0 + j * 8 + 2 * tig;
            emit(rA, c,     acc[i][j][0]);
            emit(rA, c + 1, acc[i][j][1]);
            emit(rB, c,     acc[i][j][2]);
            emit(rB, c + 1, acc[i][j][3]);
        }
    }
}

struct GDesc {
    const float* A; const float* B; float* C;
    int M, N, K, lda, ldb, ldc;
    const float* residual; int ldr; int gelu;
};

template<bool TRANSB>
__global__ void __launch_bounds__(256, 2) gemm_kernel(
    const float* __restrict__ A, const float* __restrict__ B, float* __restrict__ C,
    int M, int N, int K, int lda, int ldb, int ldc,
    const float* __restrict__ residual, int ldr, int doGelu, int accum)
{
    gemm_body<TRANSB>(A, B, C, M, N, K, lda, ldb, ldc,
                      nullptr, nullptr, residual, ldr, nullptr,
                      doGelu, accum, blockIdx.y, blockIdx.x);
}

template<bool TRANSB>
__global__ void __launch_bounds__(256, 2) gemm2_kernel(GDesc d0, GDesc d1)
{
    const GDesc& d = (blockIdx.z == 0) ? d0 : d1;
    if ((int)blockIdx.x * TN >= d.N) return;
    if ((int)blockIdx.y * TM >= d.M) return;
    gemm_body<TRANSB>(d.A, d.B, d.C, d.M, d.N, d.K, d.lda, d.ldb, d.ldc,
                      nullptr, nullptr, d.residual, d.ldr, nullptr,
                      d.gelu, 0, blockIdx.y, blockIdx.x);
}

// ---------------- expert (ragged) GEMMs ----------------
__global__ void __launch_bounds__(256, 2) expert_fc_kernel(
    const float* __restrict__ h2, const float* __restrict__ e_fc,
    float* __restrict__ ffe, const int* __restrict__ ecnt,
    const int* __restrict__ etok, const int* __restrict__ escat)
{
    int e = blockIdx.z;
    int cnt = ecnt[e];
    if ((int)blockIdx.y * TM >= cnt) return;
    gemm_body<true>(h2, e_fc + (size_t)e * FFDIM * DMODEL,
                    ffe,
                    cnt, FFDIM, DMODEL, DMODEL, DMODEL, FFDIM,
                    etok + e * NTOK, escat + e * NTOK, nullptr, 0, nullptr,
                    1, 0, blockIdx.y, blockIdx.x);
}

__global__ void __launch_bounds__(256, 2) expert_proj_kernel(
    const float* __restrict__ ffe, const float* __restrict__ e_proj,
    float* __restrict__ routed, const int* __restrict__ ecnt,
    const int* __restrict__ escat, const float* __restrict__ ewt)
{
    int e = blockIdx.z;
    int cnt = ecnt[e];
    if ((int)blockIdx.y * TM >= cnt) return;
    gemm_body<true>(ffe,
                    e_proj + (size_t)e * DMODEL * FFDIM,
                    routed,
                    cnt, DMODEL, FFDIM, FFDIM, FFDIM, DMODEL,
                    escat + e * NTOK, escat + e * NTOK, nullptr, 0, ewt + e * NTOK,
                    0, 0, blockIdx.y, blockIdx.x);
}

// ---------------- layernorm ----------------
__global__ void ln_kernel(const float* __restrict__ in, int ldin, int W,
                          const float* __restrict__ w, const float* __restrict__ b,
                          float* __restrict__ out, int ldout)
{
    int t = blockIdx.x;
    int tid = threadIdx.x;
    const float* x = in + (size_t)t * ldin;
    float s = 0.f, sq = 0.f;
    for (int c = tid; c < W; c += blockDim.x) { float v = x[c]; s += v; sq += v*v; }
    __shared__ float rs[32], rq[32];
    #pragma unroll
    for (int o = 16; o; o >>= 1) { s += __shfl_xor_sync(~0u, s, o); sq += __shfl_xor_sync(~0u, sq, o); }
    int warp = tid >> 5, lane = tid & 31;
    if (lane == 0) { rs[warp] = s; rq[warp] = sq; }
    __syncthreads();
    int nw = blockDim.x >> 5;
    if (warp == 0) {
        s  = lane < nw ? rs[lane] : 0.f;
        sq = lane < nw ? rq[lane] : 0.f;
        #pragma unroll
        for (int o = 16; o; o >>= 1) { s += __shfl_xor_sync(~0u, s, o); sq += __shfl_xor_sync(~0u, sq, o); }
        if (lane == 0) { rs[0] = s; rq[0] = sq; }
    }
    __syncthreads();
    float mean = rs[0] / W;
    float var  = rq[0] / W - mean * mean;
    float rstd = rsqrtf(var + 1e-5f);
    float* y = out + (size_t)t * ldout;
    for (int c = tid; c < W; c += blockDim.x) {
        float v = (x[c] - mean) * rstd * w[c];
        if (b) v += b[c];
        y[c] = v;
    }
}

// ---------------- rope ----------------
__global__ void rope_kernel(float* __restrict__ q, const float* __restrict__ ckv,
                            float* __restrict__ kr)
{
    int t = blockIdx.x;
    int s = t & (SEQ - 1);
    int tid = threadIdx.x;
    int h = tid >> 4, j = tid & 15;
    float freq = powf(10000.f, -(float)j / 32.f);
    float ang = (float)s * freq;
    float c = cosf(ang), si = sinf(ang);
    float* qp = q + (size_t)t * DMODEL + h * DHEAD + NOPE;
    float a = qp[j], bb = qp[j + 16];
    qp[j]      = a * c - bb * si;
    qp[j + 16] = bb * c + a * si;
    if (h == 0) {
        const float* kp = ckv + (size_t)t * CKVW + KVP;
        float a2 = kp[j], b2 = kp[j + 16];
        kr[t * ROPE + j]      = a2 * c - b2 * si;
        kr[t * ROPE + j + 16] = b2 * c + a2 * si;
    }
}

// ---------------- tensor-core flash attention ----------------
#define KSP 40
#define VSP 72
#define PSP 132

__global__ void __launch_bounds__(256, 2) flash_mma_kernel(
    const float* __restrict__ Q, const float* __restrict__ KV,
    const float* __restrict__ KR, float* __restrict__ O)
{
    __shared__ float sbuf[64*KSP + 32*VSP + 32*PSP];
    float* qs = sbuf;
    float* ks = sbuf;
    float* vs = sbuf + 64*KSP;
    float* ps = sbuf + 64*KSP + 32*VSP;

    const int qt = (int)(gridDim.x - 1 - blockIdx.x);
    const int bh = blockIdx.y;
    const int b = bh / NHEAD, h = bh % NHEAD;
    const int tid = threadIdx.x;
    const int lane = tid & 31, wid = tid >> 5;
    const int group = lane >> 2, tig = lane & 3;
    const int m0 = wid * 16;
    const int tok0 = b * SEQ + qt * 128;

    for (int i = tid; i < 128 * 64; i += 256) {
        int r = i >> 6, d = i & 63;
        qs[d * PSP + r] = Q[(size_t)(tok0 + r) * DMODEL + h * DHEAD + d];
    }
    __syncthreads();
    float qa[8][4];
    #pragma unroll
    for (int k8 = 0; k8 < 8; k8++) {
        int kb = k8 * 8;
        qa[k8][0] = qs[(kb + tig) * PSP + m0 + group];
        qa[k8][1] = qs[(kb + tig) * PSP + m0 + group + 8];
        qa[k8][2] = qs[(kb + tig + 4) * PSP + m0 + group];
        qa[k8][3] = qs[(kb + tig + 4) * PSP + m0 + group + 8];
    }
    __syncthreads();

    float oacc[8][4];
    #pragma unroll
    for (int j = 0; j < 8; j++)
        #pragma unroll
        for (int c = 0; c < 4; c++) oacc[j][c] = 0.f;
    float mrow[2] = {-1e30f, -1e30f};
    float lrow[2] = {0.f, 0.f};

    const int qgA = qt * 128 + m0 + group;
    const int qgB = qgA + 8;
    const int nkt = 4 * qt + 4;

    for (int kt = 0; kt < nkt; kt++) {
        const int key0 = kt * 32;
        __syncthreads();
        for (int i = tid; i < 32 * 64; i += 256) {
            int d = i & 63, c = i >> 6;
            int t = b * SEQ + key0 + c;
            float v = (d < 32) ? KV[(size_t)t * UKVW + h * 96 + d]
                               : KR[t * ROPE + (d - 32)];
            ks[d * KSP + c] = v;
        }
        for (int i = tid; i < 32 * 16; i += 256) {
            int c = i >> 4, d4 = (i & 15) * 4;
            int t = b * SEQ + key0 + c;
            float4 v = *(const float4*)(KV + (size_t)t * UKVW + h * 96 + 32 + d4);
            vs[c * VSP + d4 + 0] = v.x;
            vs[c * VSP + d4 + 1] = v.y;
            vs[c * VSP + d4 + 2] = v.z;
            vs[c * VSP + d4 + 3] = v.w;
        }
        __syncthreads();

        float sacc[4][4];
        #pragma unroll
        for (int j = 0; j < 4; j++)
            #pragma unroll
            for (int c = 0; c < 4; c++) sacc[j][c] = 0.f;
        #pragma unroll
        for (int k8 = 0; k8 < 8; k8++) {
            int kb = k8 * 8;
            #pragma unroll
            for (int j = 0; j < 4; j++) {
                int nb = j * 8 + group;
                float b0 = ks[(kb + tig) * KSP + nb];
                float b1 = ks[(kb + tig + 4) * KSP + nb];
                mma_tf32(sacc[j][0], sacc[j][1], sacc[j][2], sacc[j][3],
                         qa[k8][0], qa[k8][1], qa[k8][2], qa[k8][3], b0, b1);
            }
        }

        const bool fullTile = (key0 + 31 <= qgA);
        #pragma unroll
        for (int j = 0; j < 4; j++) {
            int c0 = key0 + j * 8 + 2 * tig;
            #pragma unroll
            for (int cc = 0; cc < 4; cc++) sacc[j][cc] *= 0.125f;
            if (!fullTile) {
                if (c0     > qgA) sacc[j][0] = -1e30f;
                if (c0 + 1 > qgA) sacc[j][1] = -1e30f;
                if (c0     > qgB) sacc[j][2] = -1e30f;
                if (c0 + 1 > qgB) sacc[j][3] = -1e30f;
            }
        }

        float mtA = -1e30f, mtB = -1e30f;
        #pragma unroll
        for (int j = 0; j < 4; j++) {
            mtA = fmaxf(mtA, fmaxf(sacc[j][0], sacc[j][1]));
            mtB = fmaxf(mtB, fmaxf(sacc[j][2], sacc[j][3]));
        }
        mtA = fmaxf(mtA, __shfl_xor_sync(~0u, mtA, 1));
        mtA = fmaxf(mtA, __shfl_xor_sync(~0u, mtA, 2));
        mtB = fmaxf(mtB, __shfl_xor_sync(~0u, mtB, 1));
        mtB = fmaxf(mtB, __shfl_xor_sync(~0u, mtB, 2));
        float mnA = fmaxf(mrow[0], mtA), mnB = fmaxf(mrow[1], mtB);
        float crA = __expf(mrow[0] - mnA), crB = __expf(mrow[1] - mnB);
        #pragma unroll
        for (int j = 0; j < 8; j++) {
            oacc[j][0] *= crA; oacc[j][1] *= crA;
            oacc[j][2] *= crB; oacc[j][3] *= crB;
        }
        float psA = 0.f, psB = 0.f;
        #pragma unroll
        for (int j = 0; j < 4; j++) {
            float p0 = __expf(sacc[j][0] - mnA);
            float p1 = __expf(sacc[j][1] - mnA);
            float p2 = __expf(sacc[j][2] - mnB);
            float p3 = __expf(sacc[j][3] - mnB);
            psA += p0 + p1; psB += p2 + p3;
            int col = j * 8 + 2 * tig;
            ps[col * PSP + m0 + group]           = p0;
            ps[(col + 1) * PSP + m0 + group]     = p1;
            ps[col * PSP + m0 + group + 8]       = p2;
            ps[(col + 1) * PSP + m0 + group + 8] = p3;
        }
        psA += __shfl_xor_sync(~0u, psA, 1);
        psA += __shfl_xor_sync(~0u, psA, 2);
        psB += __shfl_xor_sync(~0u, psB, 1);
        psB += __shfl_xor_sync(~0u, psB, 2);
        lrow[0] = lrow[0] * crA + psA;
        lrow[1] = lrow[1] * crB + psB;
        mrow[0] = mnA; mrow[1] = mnB;
        __syncwarp();

        #pragma unroll
        for (int kq = 0; kq < 4; kq++) {
            int kb = kq * 8;
            float a0 = ps[(kb + tig) * PSP + m0 + group];
            float a1 = ps[(kb + tig) * PSP + m0 + group + 8];
            float a2 = ps[(kb + tig + 4) * PSP + m0 + group];
            float a3 = ps[(kb + tig + 4) * PSP + m0 + group + 8];
            #pragma unroll
            for (int j = 0; j < 8; j++) {
                int nb = j * 8 + group;
                float b0 = vs[(kb + tig) * VSP + nb];
                float b1 = vs[(kb + tig + 4) * VSP + nb];
                mma_tf32(oacc[j][0], oacc[j][1], oacc[j][2], oacc[j][3],
                         a0, a1, a2, a3, b0, b1);
            }
        }
    }

    float invA = 1.f / lrow[0], invB = 1.f / lrow[1];
    int rowA = tok0 + m0 + group, rowB = rowA + 8;
    #pragma unroll
    for (int j = 0; j < 8; j++) {
        int c = j * 8 + 2 * tig;
        size_t offA = (size_t)rowA * DMODEL + h * DHEAD + c;
        size_t offB = (size_t)rowB * DMODEL + h * DHEAD + c;
        O[offA]     = oacc[j][0] * invA;
        O[offA + 1] = oacc[j][1] * invA;
        O[offB]     = oacc[j][2] * invB;
        O[offB + 1] = oacc[j][3] * invB;
    }
}

// ---------------- routing ----------------
__global__ void zero_cnt_kernel(int* __restrict__ ecnt)
{
    if (threadIdx.x < NEXP) ecnt[threadIdx.x] = 0;
}

__global__ void routing_kernel(const float* __restrict__ h2,
                               const float* __restrict__ centroids,
                               const float* __restrict__ rbias,
                               int* __restrict__ ecnt, int* __restrict__ etok,
                               int* __restrict__ escat, float* __restrict__ ewt)
{
    int t = blockIdx.x;
    int tid = threadIdx.x;
    int warp = tid >> 5, lane = tid & 31;
    __shared__ float raw[NEXP];
    const float* hp = h2 + (size_t)t * DMODEL;
    const float* cp = centroids + (size_t)warp * DMODEL;
    float sum = 0.f;
    for (int d = lane; d < DMODEL; d += 32) sum += hp[d] * cp[d];
    #pragma unroll
    for (int o = 16; o; o >>= 1) sum += __shfl_xor_sync(~0u, sum, o);
    if (lane == 0) raw[warp] = sum;
    __syncthreads();
    if (tid == 0) {
        float bb[NEXP];
        #pragma unroll
        for (int e = 0; e < NEXP; e++) bb[e] = raw[e] + rbias[e];
        int i0 = 0;
        #pragma unroll
        for (int e = 1; e < NEXP; e++) if (bb[e] > bb[i0]) i0 = e;
        int i1 = -1;
        #pragma unroll
        for (int e = 0; e < NEXP; e++) {
            if (e == i0) continue;
            if (i1 < 0 || bb[e] > bb[i1]) i1 = e;
        }
        float w0 = 1.f / (1.f + expf(-raw[i0]));
        float w1 = 1.f / (1.f + expf(-raw[i1]));
        float s = w0 + w1 + 1e-9f;
        w0 /= s; w1 /= s;
        int p0 = atomicAdd(&ecnt[i0], 1);
        etok [i0 * NTOK + p0] = t;
        escat[i0 * NTOK + p0] = t;
        ewt  [i0 * NTOK + p0] = w0;
        int p1 = atomicAdd(&ecnt[i1], 1);
        etok [i1 * NTOK + p1] = t;
        escat[i1 * NTOK + p1] = NTOK + t;
        ewt  [i1 * NTOK + p1] = w1;
    }
}

__global__ void add5_kernel(float* __restrict__ out, const float* __restrict__ x2,
                            const float* __restrict__ a, const float* __restrict__ b,
                            const float* __restrict__ c, const float* __restrict__ d,
                            int n)
{
    int i = blockIdx.x * blockDim.x + threadIdx.x;
    if (i < n) out[i] = x2[i] + a[i] + b[i] + c[i] + d[i];
}

// ---------------- launcher ----------------
extern "C" void kernel_launch(void* const* d_in, const int* in_sizes, int n_in,
                              void* d_out, int out_size)
{
    const float* x        = (const float*)d_in[0];
    const float* ln1_w    = (const float*)d_in[1];
    const float* ln2_w    = (const float*)d_in[2];
    const float* W_dq     = (const float*)d_in[3];
    const float* W_uq     = (const float*)d_in[4];
    const float* q_ln_w   = (const float*)d_in[5];
    const float* q_ln_b   = (const float*)d_in[6];
    const float* W_dkv    = (const float*)d_in[7];
    const float* W_ukv    = (const float*)d_in[8];
    const float* kv_ln_w  = (const float*)d_in[9];
    const float* kv_ln_b  = (const float*)d_in[10];
    const float* W_o      = (const float*)d_in[11];
    const float* s_fc     = (const float*)d_in[12];
    const float* s_proj   = (const float*)d_in[13];
    const float* e_fc     = (const float*)d_in[14];
    const float* e_proj   = (const float*)d_in[15];
    const float* centroids= (const float*)d_in[16];
    const float* rbias    = (const float*)d_in[17];
    float* out = (float*)d_out;

    float *h1, *cqp, *cq, *q, *ckv, *kvl, *kv, *kr, *o, *x2, *h2, *ff, *ffe, *shp, *routed, *ewt;
    int *ecnt, *etok, *escat;
    cudaGetSymbolAddress((void**)&h1,  g_h1);
    cudaGetSymbolAddress((void**)&cqp, g_cqp);
    cudaGetSymbolAddress((void**)&cq,  g_cq);
    cudaGetSymbolAddress((void**)&q,   g_q);
    cudaGetSymbolAddress((void**)&ckv, g_ckv);
    cudaGetSymbolAddress((void**)&kvl, g_kvl);
    cudaGetSymbolAddress((void**)&kv,  g_kv);
    cudaGetSymbolAddress((void**)&kr,  g_kr);
    cudaGetSymbolAddress((void**)&o,   g_o);
    cudaGetSymbolAddress((void**)&x2,  g_x2);
    cudaGetSymbolAddress((void**)&h2,  g_h2);
    cudaGetSymbolAddress((void**)&ff,  g_ff);
    cudaGetSymbolAddress((void**)&ffe, g_ffe);
    cudaGetSymbolAddress((void**)&shp, g_shp);
    cudaGetSymbolAddress((void**)&routed, g_routed);
    cudaGetSymbolAddress((void**)&ecnt, g_ecnt);
    cudaGetSymbolAddress((void**)&etok, g_etok);
    cudaGetSymbolAddress((void**)&escat, g_escat);
    cudaGetSymbolAddress((void**)&ewt, g_ewt);

    const int TB = 256;
    #define NT(Nv) (((Nv)+TN-1)/TN)

    // 1. h1 = LN(x)
    ln_kernel<<<NTOK, TB>>>(x, DMODEL, DMODEL, ln1_w, nullptr, h1, DMODEL);

    // 2. fused: cq_pre = h1@W_dq  |  ckv = h1@W_dkv
    {
        GDesc d0{h1, W_dq,  cqp, NTOK, QP,   DMODEL, DMODEL, QP,   QP,   nullptr, 0, 0};
        GDesc d1{h1, W_dkv, ckv, NTOK, CKVW, DMODEL, DMODEL, CKVW, CKVW, nullptr, 0, 0};
        gemm2_kernel<false><<<dim3(NT(CKVW), NTOK/TM, 2), TB>>>(d0, d1);
    }
    // 3. LNs
    ln_kernel<<<NTOK, TB>>>(cqp, QP, QP, q_ln_w, q_ln_b, cq, QP);
    ln_kernel<<<NTOK, TB>>>(ckv, CKVW, KVP, kv_ln_w, kv_ln_b, kvl, KVP);

    // 4. fused: Q = cq@W_uq  |  KV = kvl@W_ukv
    {
        GDesc d0{cq,  W_uq,  q,  NTOK, DMODEL, QP,  QP,  DMODEL, DMODEL, nullptr, 0, 0};
        GDesc d1{kvl, W_ukv, kv, NTOK, UKVW,   KVP, KVP, UKVW,   UKVW,   nullptr, 0, 0};
        gemm2_kernel<false><<<dim3(NT(UKVW), NTOK/TM, 2), TB>>>(d0, d1);
    }
    // 5. rope
    rope_kernel<<<NTOK, 192>>>(q, ckv, kr);
    // 6. tensor-core flash attention
    flash_mma_kernel<<<dim3(SEQ/128, BATCH*NHEAD), TB>>>(q, kv, kr, o);
    // 7. x2 = o @ W_o^T + x
    gemm_kernel<true><<<dim3(NT(DMODEL), NTOK/TM), TB>>>(o, W_o, x2,
        NTOK, DMODEL, DMODEL, DMODEL, DMODEL, DMODEL, x, DMODEL, 0, 0);
    // 8. h2 = LN(x2)
    ln_kernel<<<NTOK, TB>>>(x2, DMODEL, DMODEL, ln2_w, nullptr, h2, DMODEL);

    // 9. routing
    zero_cnt_kernel<<<1, 32>>>(ecnt);
    routing_kernel<<<NTOK, TB>>>(h2, centroids, rbias, ecnt, etok, escat, ewt);

    // 10. fused shared fc (both experts)
    {
        GDesc d0{h2, s_fc,                          ff,                          NTOK, FFDIM, DMODEL, DMODEL, DMODEL, FFDIM, nullptr, 0, 1};
        GDesc d1{h2, s_fc + (size_t)FFDIM*DMODEL,   ff + (size_t)NTOK*FFDIM,     NTOK, FFDIM, DMODEL, DMODEL, DMODEL, FFDIM, nullptr, 0, 1};
        gemm2_kernel<true><<<dim3(NT(FFDIM), NTOK/TM, 2), TB>>>(d0, d1);
    }
    // 11. fused shared proj
    {
        GDesc d0{ff,                        s_proj,                        shp,                        NTOK, DMODEL, FFDIM, FFDIM, FFDIM, DMODEL, nullptr, 0, 0};
        GDesc d1{ff + (size_t)NTOK*FFDIM,   s_proj + (size_t)DMODEL*FFDIM, shp + (size_t)NTOK*DMODEL,  NTOK, DMODEL, FFDIM, FFDIM, FFDIM, DMODEL, nullptr, 0, 0};
        gemm2_kernel<true><<<dim3(NT(DMODEL), NTOK/TM, 2), TB>>>(d0, d1);
    }
    // 12. routed experts
    expert_fc_kernel<<<dim3(FFDIM/TN, NTOK/TM, NEXP), TB>>>(h2, e_fc, ffe, ecnt, etok, escat);
    expert_proj_kernel<<<dim3(DMODEL/TN, NTOK/TM, NEXP), TB>>>(ffe, e_proj, routed, ecnt, escat, ewt);
    // 13. out = x2 + shared0 + shared1 + routed0 + routed1
    add5_kernel<<<(NTOK*DMODEL + TB - 1)/TB, TB>>>(out, x2,
        shp, shp + (size_t)NTOK*DMODEL,
        routed, routed + (size_t)NTOK*DMODEL, NTOK*DMODEL);
}

// round 14
// speedup vs baseline: 4.8622x; 1.1321x over previous
#include <cuda_runtime.h>
#include <cuda_bf16.h>
#include <math.h>
#include <stdint.h>

// ---------------- problem constants ----------------
#define BATCH 4
#define SEQ   1024
#define NTOK  (BATCH*SEQ)      // 4096
#define DMODEL 768
#define NHEAD 12
#define DHEAD 64
#define NOPE  32
#define ROPE  32
#define QP    384
#define KVP   512
#define CKVW  (KVP+ROPE)       // 544
#define UKVW  1152             // D + H*NOPE
#define NEXP  8
#define TOPK  2
#define FFDIM 3072

// ---------------- scratch ----------------
__device__ float g_h1 [NTOK*DMODEL];
__device__ float g_cqp[NTOK*QP];
__device__ float g_cq [NTOK*QP];
__device__ float g_q  [NTOK*DMODEL];
__device__ float g_ckv[NTOK*CKVW];
__device__ float g_kvl[NTOK*KVP];
__device__ float g_kv [NTOK*UKVW];
__device__ float g_kr [NTOK*ROPE];
__device__ float g_o  [NTOK*DMODEL];
__device__ float g_x2 [NTOK*DMODEL];
__device__ float g_h2 [NTOK*DMODEL];
__device__ float g_h2r[NTOK*DMODEL];
__device__ float g_ff [(size_t)2*NTOK*FFDIM];
__device__ float g_ffe[(size_t)2*NTOK*FFDIM];
__device__ float g_shp[2*NTOK*DMODEL];
__device__ float g_routed[2*NTOK*DMODEL];
__device__ int   g_ecnt[NEXP];
__device__ int   g_etok[NEXP*NTOK];
__device__ int   g_escat[NEXP*NTOK];
__device__ float g_ewt [NEXP*NTOK];

// ---------------- helpers ----------------
__device__ __forceinline__ float to_tf32(float x) {
    uint32_t u;
    asm("cvt.rna.tf32.f32 %0, %1;" : "=r"(u) : "f"(x));
    return __uint_as_float(u);
}

__device__ __forceinline__ void mma_tf32(float& c0, float& c1, float& c2, float& c3,
                                         float a0, float a1, float a2, float a3,
                                         float b0, float b1)
{
    asm volatile(
        "mma.sync.aligned.m16n8k8.row.col.f32.tf32.tf32.f32 "
        "{%0,%1,%2,%3}, {%4,%5,%6,%7}, {%8,%9}, {%0,%1,%2,%3};\n"
        : "+f"(c0), "+f"(c1), "+f"(c2), "+f"(c3)
        : "r"(__float_as_uint(a0)), "r"(__float_as_uint(a1)),
          "r"(__float_as_uint(a2)), "r"(__float_as_uint(a3)),
          "r"(__float_as_uint(b0)), "r"(__float_as_uint(b1)));
}

__device__ __forceinline__ void mma_u(float* c, const uint32_t* a, uint32_t b0, uint32_t b1)
{
    asm volatile(
        "mma.sync.aligned.m16n8k8.row.col.f32.tf32.tf32.f32 "
        "{%0,%1,%2,%3}, {%4,%5,%6,%7}, {%8,%9}, {%0,%1,%2,%3};\n"
        : "+f"(c[0]), "+f"(c[1]), "+f"(c[2]), "+f"(c[3])
        : "r"(a[0]), "r"(a[1]), "r"(a[2]), "r"(a[3]), "r"(b0), "r"(b1));
}

__device__ __forceinline__ void ldsm_x4(uint32_t& r0, uint32_t& r1, uint32_t& r2, uint32_t& r3, uint32_t a)
{
    asm volatile("ldmatrix.sync.aligned.m8n8.x4.shared.b16 {%0,%1,%2,%3}, [%4];\n"
                 : "=r"(r0), "=r"(r1), "=r"(r2), "=r"(r3) : "r"(a));
}
__device__ __forceinline__ void ldsm_x2(uint32_t& r0, uint32_t& r1, uint32_t a)
{
    asm volatile("ldmatrix.sync.aligned.m8n8.x2.shared.b16 {%0,%1}, [%2];\n"
                 : "=r"(r0), "=r"(r1) : "r"(a));
}

__device__ __forceinline__ void cp16(uint32_t dst, const void* src, bool pred)
{
    asm volatile("cp.async.ca.shared.global [%0], [%1], 16, %2;\n"
                 :: "r"(dst), "l"(src), "r"(pred ? 16 : 0));
}
__device__ __forceinline__ void cp_commit() {
    asm volatile("cp.async.commit_group;\n" ::: "memory");
}
__device__ __forceinline__ void cp_wait1() {
    asm volatile("cp.async.wait_group 1;\n" ::: "memory");
}
__device__ __forceinline__ void cp_wait0() {
    asm volatile("cp.async.wait_group 0;\n" ::: "memory");
}

// ---------------- tf32 tensor-core GEMM (cp.async + ldmatrix) ----------------
#define TM 128
#define TN 128
#define KS 16
#define APAD 20     // rows 16B-aligned (80 bytes), bank-permuted fragments
#define BPADN 136   // non-trans [k][BPADN]

template<bool TRANSB>
__device__ __forceinline__ void gemm_body(
    const float* __restrict__ A, const float* __restrict__ B, float* __restrict__ C,
    int M, int N, int K, int lda, int ldb, int ldc,
    const int* __restrict__ gather, const int* __restrict__ scatter,
    const float* __restrict__ residual, int ldr,
    const float* __restrict__ rowScale,
    int doGelu, int accum, int roundC, int rt, int ct)
{
    __shared__ __align__(16) float As[2][TM][APAD];
    __shared__ __align__(16) float Bs[2][TRANSB ? TN : KS][TRANSB ? APAD : BPADN];

    const int tid = threadIdx.x;
    const int lane = tid & 31, wid = tid >> 5;
    const int group = lane >> 2, tig = lane & 3;
    const int warp_m = wid & 3;
    const int warp_n = wid >> 2;
    const int row0 = rt * TM, col0 = ct * TN;

    const uint32_t sA = (uint32_t)__cvta_generic_to_shared(&As[0][0][0]);
    const uint32_t sB = (uint32_t)__cvta_generic_to_shared(&Bs[0][0][0]);
    constexpr uint32_t ASTAGE = TM * APAD * 4;
    constexpr uint32_t BSTAGE = (TRANSB ? TN * APAD : KS * BPADN) * 4;

    // ---- A loader ----
    const int ar0 = tid >> 2;
    const int akc = (tid & 3) * 4;
    const float *Aptr0, *Aptr1; bool av0, av1;
    {
        int gr0 = row0 + ar0, gr1 = gr0 + 64;
        av0 = gr0 < M; av1 = gr1 < M;
        int i0 = av0 ? (gather ? gather[gr0] : gr0) : 0;
        int i1 = av1 ? (gather ? gather[gr1] : gr1) : 0;
        Aptr0 = A + (size_t)i0 * lda + akc;
        Aptr1 = A + (size_t)i1 * lda + akc;
    }
    const uint32_t adst0 = sA + (uint32_t)((ar0 * APAD + akc) * 4);
    const uint32_t adst1 = sA + (uint32_t)(((ar0 + 64) * APAD + akc) * 4);

    // ---- B loader ----
    const float *Bptr0, *Bptr1; bool bvld;
    uint32_t bdst0, bdst1;
    bool btv0 = true, btv1 = true;
    if (TRANSB) {
        int gn0 = col0 + ar0, gn1 = gn0 + 64;
        btv0 = gn0 < N; btv1 = gn1 < N;
        Bptr0 = B + (size_t)(btv0 ? gn0 : 0) * ldb + akc;
        Bptr1 = B + (size_t)(btv1 ? gn1 : 0) * ldb + akc;
        bdst0 = sB + (uint32_t)((ar0 * APAD + akc) * 4);
        bdst1 = sB + (uint32_t)(((ar0 + 64) * APAD + akc) * 4);
        bvld = true;
    } else {
        int kr0 = tid >> 5;
        int nc = (tid & 31) * 4;
        int gc = col0 + nc;
        bool v = gc < N;
        Bptr0 = B + (size_t)kr0 * ldb + (v ? gc : 0);
        Bptr1 = B + (size_t)(kr0 + 8) * ldb + (v ? gc : 0);
        bdst0 = sB + (uint32_t)((kr0 * BPADN + nc) * 4);
        bdst1 = sB + (uint32_t)(((kr0 + 8) * BPADN + nc) * 4);
        bvld = v;
    }

    auto issue = [&](int stage, int k0) {
        uint32_t ao = stage ? ASTAGE : 0;
        uint32_t bo = stage ? BSTAGE : 0;
        cp16(adst0 + ao, Aptr0 + k0, av0);
        cp16(adst1 + ao, Aptr1 + k0, av1);
        if (TRANSB) {
            cp16(bdst0 + bo, Bptr0 + k0, btv0);
            cp16(bdst1 + bo, Bptr1 + k0, btv1);
        } else {
            cp16(bdst0 + bo, Bptr0 + (size_t)k0 * ldb, bvld);
            cp16(bdst1 + bo, Bptr1 + (size_t)k0 * ldb, bvld);
        }
        cp_commit();
    };

    // ---- fragment addresses (ldmatrix) ----
    const int m0 = warp_m * 32;
    const int n0 = warp_n * 64;
    const int lrow8 = lane & 7;
    const int quad = lane >> 3;
    const int aColOff = (quad & 2) ? 4 : 0;
    const int aRowBase = m0 + ((quad & 1) ? 8 : 0) + lrow8;
    const uint32_t aAddr0 = sA + (uint32_t)((aRowBase * APAD + aColOff) * 4);
    const uint32_t aAddr1 = sA + (uint32_t)(((aRowBase + 16) * APAD + aColOff) * 4);
    uint32_t bAddr = 0;
    if (TRANSB)
        bAddr = sB + (uint32_t)(((n0 + (lane & 7)) * APAD + ((lane >> 3) & 1) * 4) * 4);

    float acc[2][8][4];
    #pragma unroll
    for (int i = 0; i < 2; i++)
        #pragma unroll
        for (int j = 0; j < 8; j++)
            #pragma unroll
            for (int c = 0; c < 4; c++) acc[i][j][c] = 0.f;

    issue(0, 0);

    int buf = 0;
    for (int k0 = 0; k0 < K; k0 += KS) {
        const bool more = (k0 + KS) < K;
        if (more) issue(buf ^ 1, k0 + KS);
        if (more) cp_wait1(); else cp_wait0();
        __syncthreads();

        const uint32_t ao = buf ? ASTAGE : 0;
        const uint32_t bo = buf ? BSTAGE : 0;
        #pragma unroll
        for (int half = 0; half < 2; half++) {
            const int kb = half * 8;
            uint32_t a0[4], a1[4];
            ldsm_x4(a0[0], a0[1], a0[2], a0[3], aAddr0 + ao + kb * 4);
            ldsm_x4(a1[0], a1[1], a1[2], a1[3], aAddr1 + ao + kb * 4);
            #pragma unroll
            for (int j = 0; j < 8; j++) {
                uint32_t b0, b1;
                if (TRANSB) {
                    ldsm_x2(b0, b1, bAddr + bo + (uint32_t)((j * 8 * APAD + kb) * 4));
                } else {
                    int nb = n0 + j * 8 + group;
                    b0 = __float_as_uint(Bs[buf][kb + tig][nb]);
                    b1 = __float_as_uint(Bs[buf][kb + tig + 4][nb]);
                }
                mma_u(acc[0][j], a0, b0, b1);
                mma_u(acc[1][j], a1, b0, b1);
            }
        }
        __syncthreads();
        buf ^= 1;
    }

    auto emit = [&](int r, int c, float v) {
        if (r >= M || c >= N) return;
        if (doGelu) v = 0.5f * v * (1.f + erff(v * 0.70710678118654752f));
        if (rowScale) v *= rowScale[r];
        if (residual) v += residual[(size_t)r * ldr + c];
        if (roundC) v = to_tf32(v);
        int orow = scatter ? scatter[r] : r;
        size_t off = (size_t)orow * ldc + c;
        if (accum) C[off] += v; else C[off] = v;
    };
    #pragma unroll
    for (int i = 0; i < 2; i++) {
        int rA = row0 + m0 + i * 16 + group;
        int rB = rA + 8;
        #pragma unroll
        for (int j = 0; j < 8; j++) {
            int c = col0 + n0 + j * 8 + 2 * tig;
            emit(rA, c,     acc[i][j][0]);
            emit(rA, c + 1, acc[i][j][1]);
            emit(rB, c,     acc[i][j][2]);
            emit(rB, c + 1, acc[i][j][3]);
        }
    }
}

struct GDesc {
    const float* A; const float* B; float* C;
    int M, N, K, lda, ldb, ldc;
    const float* residual; int ldr; int gelu; int roundC;
};

template<bool TRANSB>
__global__ void __launch_bounds__(256, 2) gemm_kernel(
    const float* __restrict__ A, const float* __restrict__ B, float* __restrict__ C,
    int M, int N, int K, int lda, int ldb, int ldc,
    const float* __restrict__ residual, int ldr, int doGelu, int accum, int roundC)
{
    gemm_body<TRANSB>(A, B, C, M, N, K, lda, ldb, ldc,
                      nullptr, nullptr, residual, ldr, nullptr,
                      doGelu, accum, roundC, blockIdx.y, blockIdx.x);
}

template<bool TRANSB>
__global__ void __launch_bounds__(256, 2) gemm2_kernel(GDesc d0, GDesc d1)
{
    const GDesc& d = (blockIdx.z == 0) ? d0 : d1;
    if ((int)blockIdx.x * TN >= d.N) return;
    if ((int)blockIdx.y * TM >= d.M) return;
    gemm_body<TRANSB>(d.A, d.B, d.C, d.M, d.N, d.K, d.lda, d.ldb, d.ldc,
                      nullptr, nullptr, d.residual, d.ldr, nullptr,
                      d.gelu, 0, d.roundC, blockIdx.y, blockIdx.x);
}

// ---------------- expert (ragged) GEMMs ----------------
__global__ void __launch_bounds__(256, 2) expert_fc_kernel(
    const float* __restrict__ h2, const float* __restrict__ e_fc,
    float* __restrict__ ffe, const int* __restrict__ ecnt,
    const int* __restrict__ etok, const int* __restrict__ escat)
{
    int e = blockIdx.z;
    int cnt = ecnt[e];
    if ((int)blockIdx.y * TM >= cnt) return;
    gemm_body<true>(h2, e_fc + (size_t)e * FFDIM * DMODEL,
                    ffe,
                    cnt, FFDIM, DMODEL, DMODEL, DMODEL, FFDIM,
                    etok + e * NTOK, escat + e * NTOK, nullptr, 0, nullptr,
                    1, 0, 1, blockIdx.y, blockIdx.x);
}

__global__ void __launch_bounds__(256, 2) expert_proj_kernel(
    const float* __restrict__ ffe, const float* __restrict__ e_proj,
    float* __restrict__ routed, const int* __restrict__ ecnt,
    const int* __restrict__ escat, const float* __restrict__ ewt)
{
    int e = blockIdx.z;
    int cnt = ecnt[e];
    if ((int)blockIdx.y * TM >= cnt) return;
    gemm_body<true>(ffe,
                    e_proj + (size_t)e * DMODEL * FFDIM,
                    routed,
                    cnt, DMODEL, FFDIM, FFDIM, FFDIM, DMODEL,
                    escat + e * NTOK, escat + e * NTOK, nullptr, 0, ewt + e * NTOK,
                    0, 0, 0, blockIdx.y, blockIdx.x);
}

// ---------------- layernorm ----------------
__global__ void ln_kernel(const float* __restrict__ in, int ldin, int W,
                          const float* __restrict__ w, const float* __restrict__ b,
                          float* __restrict__ out, int ldout,
                          int roundMain, float* __restrict__ outCopy)
{
    int t = blockIdx.x;
    int tid = threadIdx.x;
    const float* x = in + (size_t)t * ldin;
    float s = 0.f, sq = 0.f;
    for (int c = tid; c < W; c += blockDim.x) { float v = x[c]; s += v; sq += v*v; }
    __shared__ float rs[32], rq[32];
    #pragma unroll
    for (int o = 16; o; o >>= 1) { s += __shfl_xor_sync(~0u, s, o); sq += __shfl_xor_sync(~0u, sq, o); }
    int warp = tid >> 5, lane = tid & 31;
    if (lane == 0) { rs[warp] = s; rq[warp] = sq; }
    __syncthreads();
    int nw = blockDim.x >> 5;
    if (warp == 0) {
        s  = lane < nw ? rs[lane] : 0.f;
        sq = lane < nw ? rq[lane] : 0.f;
        #pragma unroll
        for (int o = 16; o; o >>= 1) { s += __shfl_xor_sync(~0u, s, o); sq += __shfl_xor_sync(~0u, sq, o); }
        if (lane == 0) { rs[0] = s; rq[0] = sq; }
    }
    __syncthreads();
    float mean = rs[0] / W;
    float var  = rq[0] / W - mean * mean;
    float rstd = rsqrtf(var + 1e-5f);
    float* y = out + (size_t)t * ldout;
    float* y2 = outCopy ? outCopy + (size_t)t * ldout : nullptr;
    for (int c = tid; c < W; c += blockDim.x) {
        float v = (x[c] - mean) * rstd * w[c];
        if (b) v += b[c];
        y[c] = roundMain ? to_tf32(v) : v;
        if (y2) y2[c] = to_tf32(v);
    }
}

// ---------------- rope ----------------
__global__ void rope_kernel(float* __restrict__ q, const float* __restrict__ ckv,
                            float* __restrict__ kr)
{
    int t = blockIdx.x;
    int s = t & (SEQ - 1);
    int tid = threadIdx.x;
    int h = tid >> 4, j = tid & 15;
    float freq = powf(10000.f, -(float)j / 32.f);
    float ang = (float)s * freq;
    float c = cosf(ang), si = sinf(ang);
    float* qp = q + (size_t)t * DMODEL + h * DHEAD + NOPE;
    float a = qp[j], bb = qp[j + 16];
    qp[j]      = to_tf32(a * c - bb * si);
    qp[j + 16] = to_tf32(bb * c + a * si);
    if (h == 0) {
        const float* kp = ckv + (size_t)t * CKVW + KVP;
        float a2 = kp[j], b2 = kp[j + 16];
        kr[t * ROPE + j]      = to_tf32(a2 * c - b2 * si);
        kr[t * ROPE + j + 16] = to_tf32(b2 * c + a2 * si);
    }
}

// ---------------- tensor-core flash attention ----------------
#define KSP 40
#define VSP 72
#define PSP 132

__global__ void __launch_bounds__(256, 2) flash_mma_kernel(
    const float* __restrict__ Q, const float* __restrict__ KV,
    const float* __restrict__ KR, float* __restrict__ O)
{
    __shared__ __align__(16) float sbuf[64*KSP + 32*VSP + 32*PSP];
    float* qs = sbuf;
    float* ks = sbuf;
    float* vs = sbuf + 64*KSP;
    float* ps = sbuf + 64*KSP + 32*VSP;

    const int qt = (int)(gridDim.x - 1 - blockIdx.x);
    const int bh = blockIdx.y;
    const int b = bh / NHEAD, h = bh % NHEAD;
    const int tid = threadIdx.x;
    const int lane = tid & 31, wid = tid >> 5;
    const int group = lane >> 2, tig = lane & 3;
    const int m0 = wid * 16;
    const int tok0 = b * SEQ + qt * 128;

    for (int i = tid; i < 128 * 64; i += 256) {
        int r = i >> 6, d = i & 63;
        qs[d * PSP + r] = Q[(size_t)(tok0 + r) * DMODEL + h * DHEAD + d];
    }
    __syncthreads();
    float qa[8][4];
    #pragma unroll
    for (int k8 = 0; k8 < 8; k8++) {
        int kb = k8 * 8;
        qa[k8][0] = qs[(kb + tig) * PSP + m0 + group];
        qa[k8][1] = qs[(kb + tig) * PSP + m0 + group + 8];
        qa[k8][2] = qs[(kb + tig + 4) * PSP + m0 + group];
        qa[k8][3] = qs[(kb + tig + 4) * PSP + m0 + group + 8];
    }
    __syncthreads();

    float oacc[8][4];
    #pragma unroll
    for (int j = 0; j < 8; j++)
        #pragma unroll
        for (int c = 0; c < 4; c++) oacc[j][c] = 0.f;
    float mrow[2] = {-1e30f, -1e30f};
    float lrow[2] = {0.f, 0.f};

    const int qgA = qt * 128 + m0 + group;
    const int qgB = qgA + 8;
    const int nkt = 4 * qt + 4;

    for (int kt = 0; kt < nkt; kt++) {
        const int key0 = kt * 32;
        __syncthreads();
        for (int i = tid; i < 32 * 64; i += 256) {
            int d = i & 63, c = i >> 6;
            int t = b * SEQ + key0 + c;
            float v = (d < 32) ? KV[(size_t)t * UKVW + h * 96 + d]
                               : KR[t * ROPE + (d - 32)];
            ks[d * KSP + c] = v;
        }
        for (int i = tid; i < 32 * 16; i += 256) {
            int c = i >> 4, d4 = (i & 15) * 4;
            int t = b * SEQ + key0 + c;
            float4 v = *(const float4*)(KV + (size_t)t * UKVW + h * 96 + 32 + d4);
            vs[c * VSP + d4 + 0] = v.x;
            vs[c * VSP + d4 + 1] = v.y;
            vs[c * VSP + d4 + 2] = v.z;
            vs[c * VSP + d4 + 3] = v.w;
        }
        __syncthreads();

        float sacc[4][4];
        #pragma unroll
        for (int j = 0; j < 4; j++)
            #pragma unroll
            for (int c = 0; c < 4; c++) sacc[j][c] = 0.f;
        #pragma unroll
        for (int k8 = 0; k8 < 8; k8++) {
            int kb = k8 * 8;
            #pragma unroll
            for (int j = 0; j < 4; j++) {
                int nb = j * 8 + group;
                float b0 = ks[(kb + tig) * KSP + nb];
                float b1 = ks[(kb + tig + 4) * KSP + nb];
                mma_tf32(sacc[j][0], sacc[j][1], sacc[j][2], sacc[j][3],
                         qa[k8][0], qa[k8][1], qa[k8][2], qa[k8][3], b0, b1);
            }
        }

        const bool fullTile = (key0 + 31 <= qgA);
        #pragma unroll
        for (int j = 0; j < 4; j++) {
            int c0 = key0 + j * 8 + 2 * tig;
            #pragma unroll
            for (int cc = 0; cc < 4; cc++) sacc[j][cc] *= 0.125f;
            if (!fullTile) {
                if (c0     > qgA) sacc[j][0] = -1e30f;
                if (c0 + 1 > qgA) sacc[j][1] = -1e30f;
                if (c0     > qgB) sacc[j][2] = -1e30f;
                if (c0 + 1 > qgB) sacc[j][3] = -1e30f;
            }
        }

        float mtA = -1e30f, mtB = -1e30f;
        #pragma unroll
        for (int j = 0; j < 4; j++) {
            mtA = fmaxf(mtA, fmaxf(sacc[j][0], sacc[j][1]));
            mtB = fmaxf(mtB, fmaxf(sacc[j][2], sacc[j][3]));
        }
        mtA = fmaxf(mtA, __shfl_xor_sync(~0u, mtA, 1));
        mtA = fmaxf(mtA, __shfl_xor_sync(~0u, mtA, 2));
        mtB = fmaxf(mtB, __shfl_xor_sync(~0u, mtB, 1));
        mtB = fmaxf(mtB, __shfl_xor_sync(~0u, mtB, 2));
        float mnA = fmaxf(mrow[0], mtA), mnB = fmaxf(mrow[1], mtB);
        float crA = __expf(mrow[0] - mnA), crB = __expf(mrow[1] - mnB);
        #pragma unroll
        for (int j = 0; j < 8; j++) {
            oacc[j][0] *= crA; oacc[j][1] *= crA;
            oacc[j][2] *= crB; oacc[j][3] *= crB;
        }
        float psA = 0.f, psB = 0.f;
        #pragma unroll
        for (int j = 0; j < 4; j++) {
            float p0 = __expf(sacc[j][0] - mnA);
            float p1 = __expf(sacc[j][1] - mnA);
            float p2 = __expf(sacc[j][2] - mnB);
            float p3 = __expf(sacc[j][3] - mnB);
            psA += p0 + p1; psB += p2 + p3;
            int col = j * 8 + 2 * tig;
            ps[col * PSP + m0 + group]           = p0;
            ps[(col + 1) * PSP + m0 + group]     = p1;
            ps[col * PSP + m0 + group + 8]       = p2;
            ps[(col + 1) * PSP + m0 + group + 8] = p3;
        }
        psA += __shfl_xor_sync(~0u, psA, 1);
        psA += __shfl_xor_sync(~0u, psA, 2);
        psB += __shfl_xor_sync(~0u, psB, 1);
        psB += __shfl_xor_sync(~0u, psB, 2);
        lrow[0] = lrow[0] * crA + psA;
        lrow[1] = lrow[1] * crB + psB;
        mrow[0] = mnA; mrow[1] = mnB;
        __syncwarp();

        #pragma unroll
        for (int kq = 0; kq < 4; kq++) {
            int kb = kq * 8;
            float a0 = ps[(kb + tig) * PSP + m0 + group];
            float a1 = ps[(kb + tig) * PSP + m0 + group + 8];
            float a2 = ps[(kb + tig + 4) * PSP + m0 + group];
            float a3 = ps[(kb + tig + 4) * PSP + m0 + group + 8];
            #pragma unroll
            for (int j = 0; j < 8; j++) {
                int nb = j * 8 + group;
                float b0 = vs[(kb + tig) * VSP + nb];
                float b1 = vs[(kb + tig + 4) * VSP + nb];
                mma_tf32(oacc[j][0], oacc[j][1], oacc[j][2], oacc[j][3],
                         a0, a1, a2, a3, b0, b1);
            }
        }
    }

    float invA = 1.f / lrow[0], invB = 1.f / lrow[1];
    int rowA = tok0 + m0 + group, rowB = rowA + 8;
    #pragma unroll
    for (int j = 0; j < 8; j++) {
        int c = j * 8 + 2 * tig;
        size_t offA = (size_t)rowA * DMODEL + h * DHEAD + c;
        size_t offB = (size_t)rowB * DMODEL + h * DHEAD + c;
        O[offA]     = to_tf32(oacc[j][0] * invA);
        O[offA + 1] = to_tf32(oacc[j][1] * invA);
        O[offB]     = to_tf32(oacc[j][2] * invB);
        O[offB + 1] = to_tf32(oacc[j][3] * invB);
    }
}

// ---------------- routing ----------------
__global__ void zero_cnt_kernel(int* __restrict__ ecnt)
{
    if (threadIdx.x < NEXP) ecnt[threadIdx.x] = 0;
}

__global__ void routing_kernel(const float* __restrict__ h2,
                               const float* __restrict__ centroids,
                               const float* __restrict__ rbias,
                               int* __restrict__ ecnt, int* __restrict__ etok,
                               int* __restrict__ escat, float* __restrict__ ewt)
{
    int t = blockIdx.x;
    int tid = threadIdx.x;
    int warp = tid >> 5, lane = tid & 31;
    __shared__ float raw[NEXP];
    const float* hp = h2 + (size_t)t * DMODEL;
    const float* cp = centroids + (size_t)warp * DMODEL;
    float sum = 0.f;
    for (int d = lane; d < DMODEL; d += 32) sum += hp[d] * cp[d];
    #pragma unroll
    for (int o = 16; o; o >>= 1) sum += __shfl_xor_sync(~0u, sum, o);
    if (lane == 0) raw[warp] = sum;
    __syncthreads();
    if (tid == 0) {
        float bb[NEXP];
        #pragma unroll
        for (int e = 0; e < NEXP; e++) bb[e] = raw[e] + rbias[e];
        int i0 = 0;
        #pragma unroll
        for (int e = 1; e < NEXP; e++) if (bb[e] > bb[i0]) i0 = e;
        int i1 = -1;
        #pragma unroll
        for (int e = 0; e < NEXP; e++) {
            if (e == i0) continue;
            if (i1 < 0 || bb[e] > bb[i1]) i1 = e;
        }
        float w0 = 1.f / (1.f + expf(-raw[i0]));
        float w1 = 1.f / (1.f + expf(-raw[i1]));
        float s = w0 + w1 + 1e-9f;
        w0 /= s; w1 /= s;
        int p0 = atomicAdd(&ecnt[i0], 1);
        etok [i0 * NTOK + p0] = t;
        escat[i0 * NTOK + p0] = t;
        ewt  [i0 * NTOK + p0] = w0;
        int p1 = atomicAdd(&ecnt[i1], 1);
        etok [i1 * NTOK + p1] = t;
        escat[i1 * NTOK + p1] = NTOK + t;
        ewt  [i1 * NTOK + p1] = w1;
    }
}

__global__ void add5_kernel(float* __restrict__ out, const float* __restrict__ x2,
                            const float* __restrict__ a, const float* __restrict__ b,
                            const float* __restrict__ c, const float* __restrict__ d,
                            int n)
{
    int i = blockIdx.x * blockDim.x + threadIdx.x;
    if (i < n) out[i] = x2[i] + a[i] + b[i] + c[i] + d[i];
}

// ---------------- launcher ----------------
extern "C" void kernel_launch(void* const* d_in, const int* in_sizes, int n_in,
                              void* d_out, int out_size)
{
    const float* x        = (const float*)d_in[0];
    const float* ln1_w    = (const float*)d_in[1];
    const float* ln2_w    = (const float*)d_in[2];
    const float* W_dq     = (const float*)d_in[3];
    const float* W_uq     = (const float*)d_in[4];
    const float* q_ln_w   = (const float*)d_in[5];
    const float* q_ln_b   = (const float*)d_in[6];
    const float* W_dkv    = (const float*)d_in[7];
    const float* W_ukv    = (const float*)d_in[8];
    const float* kv_ln_w  = (const float*)d_in[9];
    const float* kv_ln_b  = (const float*)d_in[10];
    const float* W_o      = (const float*)d_in[11];
    const float* s_fc     = (const float*)d_in[12];
    const float* s_proj   = (const float*)d_in[13];
    const float* e_fc     = (const float*)d_in[14];
    const float* e_proj   = (const float*)d_in[15];
    const float* centroids= (const float*)d_in[16];
    const float* rbias    = (const float*)d_in[17];
    float* out = (float*)d_out;

    float *h1, *cqp, *cq, *q, *ckv, *kvl, *kv, *kr, *o, *x2, *h2, *h2r, *ff, *ffe, *shp, *routed, *ewt;
    int *ecnt, *etok, *escat;
    cudaGetSymbolAddress((void**)&h1,  g_h1);
    cudaGetSymbolAddress((void**)&cqp, g_cqp);
    cudaGetSymbolAddress((void**)&cq,  g_cq);
    cudaGetSymbolAddress((void**)&q,   g_q);
    cudaGetSymbolAddress((void**)&ckv, g_ckv);
    cudaGetSymbolAddress((void**)&kvl, g_kvl);
    cudaGetSymbolAddress((void**)&kv,  g_kv);
    cudaGetSymbolAddress((void**)&kr,  g_kr);
    cudaGetSymbolAddress((void**)&o,   g_o);
    cudaGetSymbolAddress((void**)&x2,  g_x2);
    cudaGetSymbolAddress((void**)&h2,  g_h2);
    cudaGetSymbolAddress((void**)&h2r, g_h2r);
    cudaGetSymbolAddress((void**)&ff,  g_ff);
    cudaGetSymbolAddress((void**)&ffe, g_ffe);
    cudaGetSymbolAddress((void**)&shp, g_shp);
    cudaGetSymbolAddress((void**)&routed, g_routed);
    cudaGetSymbolAddress((void**)&ecnt, g_ecnt);
    cudaGetSymbolAddress((void**)&etok, g_etok);
    cudaGetSymbolAddress((void**)&escat, g_escat);
    cudaGetSymbolAddress((void**)&ewt, g_ewt);

    const int TB = 256;
    #define NT(Nv) (((Nv)+TN-1)/TN)

    // 1. h1 = round(LN(x))
    ln_kernel<<<NTOK, TB>>>(x, DMODEL, DMODEL, ln1_w, nullptr, h1, DMODEL, 1, nullptr);

    // 2. fused: cq_pre = h1@W_dq  |  ckv = h1@W_dkv   (feed LNs -> no rounding)
    {
        GDesc d0{h1, W_dq,  cqp, NTOK, QP,   DMODEL, DMODEL, QP,   QP,   nullptr, 0, 0, 0};
        GDesc d1{h1, W_dkv, ckv, NTOK, CKVW, DMODEL, DMODEL, CKVW, CKVW, nullptr, 0, 0, 0};
        gemm2_kernel<false><<<dim3(NT(CKVW), NTOK/TM, 2), TB>>>(d0, d1);
    }
    // 3. LNs (rounded outputs; both feed MMAs)
    ln_kernel<<<NTOK, TB>>>(cqp, QP, QP, q_ln_w, q_ln_b, cq, QP, 1, nullptr);
    ln_kernel<<<NTOK, TB>>>(ckv, CKVW, KVP, kv_ln_w, kv_ln_b, kvl, KVP, 1, nullptr);

    // 4. fused: Q | KV   (feed flash MMA -> round)
    {
        GDesc d0{cq,  W_uq,  q,  NTOK, DMODEL, QP,  QP,  DMODEL, DMODEL, nullptr, 0, 0, 1};
        GDesc d1{kvl, W_ukv, kv, NTOK, UKVW,   KVP, KVP, UKVW,   UKVW,   nullptr, 0, 0, 1};
        gemm2_kernel<false><<<dim3(NT(UKVW), NTOK/TM, 2), TB>>>(d0, d1);
    }
    // 5. rope (rounds outputs)
    rope_kernel<<<NTOK, 192>>>(q, ckv, kr);
    // 6. tensor-core flash attention (rounds O)
    flash_mma_kernel<<<dim3(SEQ/128, BATCH*NHEAD), TB>>>(q, kv, kr, o);
    // 7. x2 = o @ W_o^T + x   (feeds LN/residual -> no rounding)
    gemm_kernel<true><<<dim3(NT(DMODEL), NTOK/TM), TB>>>(o, W_o, x2,
        NTOK, DMODEL, DMODEL, DMODEL, DMODEL, DMODEL, x, DMODEL, 0, 0, 0);
    // 8. h2 = LN(x2): exact for routing, rounded copy h2r for GEMMs
    ln_kernel<<<NTOK, TB>>>(x2, DMODEL, DMODEL, ln2_w, nullptr, h2, DMODEL, 0, h2r);

    // 9. routing (exact h2)
    zero_cnt_kernel<<<1, 32>>>(ecnt);
    routing_kernel<<<NTOK, TB>>>(h2, centroids, rbias, ecnt, etok, escat, ewt);

    // 10. fused shared fc (round outputs: feed proj MMA)
    {
        GDesc d0{h2r, s_fc,                        ff,                      NTOK, FFDIM, DMODEL, DMODEL, DMODEL, FFDIM, nullptr, 0, 1, 1};
        GDesc d1{h2r, s_fc + (size_t)FFDIM*DMODEL, ff + (size_t)NTOK*FFDIM, NTOK, FFDIM, DMODEL, DMODEL, DMODEL, FFDIM, nullptr, 0, 1, 1};
        gemm2_kernel<true><<<dim3(NT(FFDIM), NTOK/TM, 2), TB>>>(d0, d1);
    }
    // 11. fused shared proj
    {
        GDesc d0{ff,                      s_proj,                        shp,                       NTOK, DMODEL, FFDIM, FFDIM, FFDIM, DMODEL, nullptr, 0, 0, 0};
        GDesc d1{ff + (size_t)NTOK*FFDIM, s_proj + (size_t)DMODEL*FFDIM, shp + (size_t)NTOK*DMODEL, NTOK, DMODEL, FFDIM, FFDIM, FFDIM, DMODEL, nullptr, 0, 0, 0};
        gemm2_kernel<true><<<dim3(NT(DMODEL), NTOK/TM, 2), TB>>>(d0, d1);
    }
    // 12. routed experts
    expert_fc_kernel<<<dim3(FFDIM/TN, NTOK/TM, NEXP), TB>>>(h2r, e_fc, ffe, ecnt, etok, escat);
    expert_proj_kernel<<<dim3(DMODEL/TN, NTOK/TM, NEXP), TB>>>(ffe, e_proj, routed, ecnt, escat, ewt);
    // 13. out = x2 + shared0 + shared1 + routed0 + routed1
    add5_kernel<<<(NTOK*DMODEL + TB - 1)/TB, TB>>>(out, x2,
        shp, shp + (size_t)NTOK*DMODEL,
        routed, routed + (size_t)NTOK*DMODEL, NTOK*DMODEL);
}